// round 1
// baseline (speedup 1.0000x reference)
#include <cuda_runtime.h>
#include <math_constants.h>

#define B_    8
#define L_    4096
#define DM_   512
#define H_    8
#define DK_   64
#define DV_   64
#define U_    41
#define BH_   (B_*H_)
#define NCH_  8
#define CHUNK_ (L_/NCH_)      // 512
#define EPS_  1e-5f

// ---------------- scratch (static device globals; no allocations) ----------
__device__ float g_Q[B_*L_*DM_];          // 64 MB
__device__ float g_K[B_*L_*DM_];          // 64 MB
__device__ float g_V[B_*L_*DM_];          // 64 MB
__device__ float g_ctx[B_*L_*DM_];        // 64 MB
__device__ float g_M[BH_*L_];             // 1 MB
__device__ int   g_idx[BH_*U_];
__device__ float g_vals[BH_*U_*DV_];
__device__ float g_vmean[BH_*DV_];
__device__ float g_part[BH_*NCH_*U_*66];  // per-chunk {m, s, acc[64]}

// ---------------- fp32 SGEMM: C[M,N] = A[M,K] @ B[K,N] (+ Res) -------------
// 128x128 tile, BK=16, 256 threads, 8x8 micro, double-buffered smem.
__global__ __launch_bounds__(256) void sgemm128(
    const float* __restrict__ A, const float* __restrict__ Bm,
    const float* __restrict__ Res, float* __restrict__ C,
    int M, int N, int K)
{
    __shared__ float As[2][16][128];
    __shared__ float Bs[2][16][128];
    const int tid  = threadIdx.x;
    const int row0 = blockIdx.y * 128, col0 = blockIdx.x * 128;
    const int tm   = tid >> 4, tn = tid & 15;
    const int K4   = K >> 2, N4 = N >> 2;
    const int nkt  = K >> 4;

    float acc[8][8];
#pragma unroll
    for (int i = 0; i < 8; i++)
#pragma unroll
        for (int j = 0; j < 8; j++) acc[i][j] = 0.f;

    // prologue: tile kt=0 -> buf 0
#pragma unroll
    for (int i = 0; i < 2; i++) {
        int idx = tid * 2 + i;
        int ar = idx >> 2, kq = idx & 3;
        float4 v = __ldg((const float4*)A + (size_t)(row0 + ar) * K4 + kq);
        As[0][kq*4+0][ar] = v.x; As[0][kq*4+1][ar] = v.y;
        As[0][kq*4+2][ar] = v.z; As[0][kq*4+3][ar] = v.w;
        int br = idx >> 5, bc = (idx & 31) << 2;
        float4 w2 = __ldg((const float4*)Bm + (size_t)br * N4 + ((col0 + bc) >> 2));
        *(float4*)&Bs[0][br][bc] = w2;
    }
    __syncthreads();

    for (int kt = 0; kt < nkt; kt++) {
        const int cur = kt & 1, nxt = cur ^ 1;
        float4 ra[2], rb[2];
        const bool pf = (kt + 1) < nkt;
        if (pf) {
#pragma unroll
            for (int i = 0; i < 2; i++) {
                int idx = tid * 2 + i;
                int ar = idx >> 2, kq = idx & 3;
                ra[i] = __ldg((const float4*)A + (size_t)(row0 + ar) * K4 + (kt + 1) * 4 + kq);
                int br = idx >> 5, bc = (idx & 31) << 2;
                rb[i] = __ldg((const float4*)Bm + (size_t)((kt + 1) * 16 + br) * N4 + ((col0 + bc) >> 2));
            }
        }
#pragma unroll
        for (int kk = 0; kk < 16; kk++) {
            float a[8], b[8];
            *(float4*)&a[0] = *(const float4*)&As[cur][kk][tm * 8];
            *(float4*)&a[4] = *(const float4*)&As[cur][kk][tm * 8 + 4];
            *(float4*)&b[0] = *(const float4*)&Bs[cur][kk][tn * 8];
            *(float4*)&b[4] = *(const float4*)&Bs[cur][kk][tn * 8 + 4];
#pragma unroll
            for (int i = 0; i < 8; i++)
#pragma unroll
                for (int j = 0; j < 8; j++)
                    acc[i][j] = fmaf(a[i], b[j], acc[i][j]);
        }
        if (pf) {
#pragma unroll
            for (int i = 0; i < 2; i++) {
                int idx = tid * 2 + i;
                int ar = idx >> 2, kq = idx & 3;
                As[nxt][kq*4+0][ar] = ra[i].x; As[nxt][kq*4+1][ar] = ra[i].y;
                As[nxt][kq*4+2][ar] = ra[i].z; As[nxt][kq*4+3][ar] = ra[i].w;
                int br = idx >> 5, bc = (idx & 31) << 2;
                *(float4*)&Bs[nxt][br][bc] = rb[i];
            }
        }
        __syncthreads();
    }

#pragma unroll
    for (int i = 0; i < 8; i++) {
        size_t r = (size_t)(row0 + tm * 8 + i);
#pragma unroll
        for (int j4 = 0; j4 < 2; j4++) {
            size_t off = r * N + col0 + tn * 8 + j4 * 4;
            float4 v;
            v.x = acc[i][j4*4+0]; v.y = acc[i][j4*4+1];
            v.z = acc[i][j4*4+2]; v.w = acc[i][j4*4+3];
            if (Res) {
                float4 rr = *(const float4*)(Res + off);
                v.x += rr.x; v.y += rr.y; v.z += rr.z; v.w += rr.w;
            }
            *(float4*)(C + off) = v;
        }
    }
}

// ---------------- QK_samp -> M (sparsity measure) ---------------------------
// One warp per (b,h,l). Lane holds 2 dims (float2). 41 gathered dots of 64.
__global__ __launch_bounds__(256) void qkm_kernel(const int* __restrict__ isamp)
{
    int gw   = (blockIdx.x * blockDim.x + threadIdx.x) >> 5;  // = bh*L + l
    int lane = threadIdx.x & 31;
    int l  = gw & (L_ - 1);
    int bh = gw >> 12;                  // L_ = 2^12
    int b  = bh >> 3, h = bh & 7;

    const float* qrow = g_Q + ((size_t)(b * L_ + l)) * DM_ + h * DK_;
    float2 q = *(const float2*)(qrow + 2 * lane);

    float smax = -CUDART_INF_F, ssum = 0.f;
#pragma unroll 1
    for (int u = 0; u < U_; u++) {
        int j = __ldg(&isamp[l * U_ + u]);
        const float* krow = g_K + ((size_t)(b * L_ + j)) * DM_ + h * DK_;
        float2 k = *(const float2*)(krow + 2 * lane);
        float s = q.x * k.x + q.y * k.y;
        s += __shfl_xor_sync(0xffffffffu, s, 16);
        s += __shfl_xor_sync(0xffffffffu, s, 8);
        s += __shfl_xor_sync(0xffffffffu, s, 4);
        s += __shfl_xor_sync(0xffffffffu, s, 2);
        s += __shfl_xor_sync(0xffffffffu, s, 1);
        smax = fmaxf(smax, s);
        ssum += s;
    }
    if (lane == 0) g_M[gw] = smax - ssum * (1.0f / U_);
}

// ---------------- top-k (U=41) per (b,h), iterative argmax ------------------
__global__ __launch_bounds__(256) void topk_kernel()
{
    int bh = blockIdx.x;
    __shared__ float sv[L_];
    __shared__ float rv[256];
    __shared__ int   ri[256];
    int tid = threadIdx.x;
    for (int i = tid; i < L_; i += 256) sv[i] = g_M[bh * L_ + i];
    __syncthreads();
    for (int it = 0; it < U_; it++) {
        float best = -CUDART_INF_F; int bi = L_;
        for (int i = tid; i < L_; i += 256) {
            float v = sv[i];
            if (v > best) { best = v; bi = i; }
        }
        rv[tid] = best; ri[tid] = bi;
        __syncthreads();
        for (int s = 128; s > 0; s >>= 1) {
            if (tid < s) {
                float v2 = rv[tid + s]; int i2 = ri[tid + s];
                if (v2 > rv[tid] || (v2 == rv[tid] && i2 < ri[tid])) { rv[tid] = v2; ri[tid] = i2; }
            }
            __syncthreads();
        }
        if (tid == 0) { g_idx[bh * U_ + it] = ri[0]; sv[ri[0]] = -CUDART_INF_F; }
        __syncthreads();
    }
}

// ---------------- V mean over L per (b,h) ------------------------------------
__global__ __launch_bounds__(256) void vmean_kernel()
{
    int bh = blockIdx.x;
    int b = bh >> 3, h = bh & 7;
    int tid = threadIdx.x;
    int d = tid & 63, g = tid >> 6;
    float sum = 0.f;
    for (int l = g; l < L_; l += 4)
        sum += g_V[((size_t)(b * L_ + l)) * DM_ + h * DK_ + d];
    __shared__ float red[4][64];
    red[g][d] = sum;
    __syncthreads();
    if (g == 0) {
        float t = red[0][d] + red[1][d] + red[2][d] + red[3][d];
        g_vmean[bh * 64 + d] = t * (1.0f / L_);
    }
}

// ---------------- sparse attention, split-L partials -------------------------
// grid (NCH, BH). Block streams a 512-key chunk through smem tiles of 64 keys;
// each warp owns u = w + 8k, maintains online-softmax state in registers.
__global__ __launch_bounds__(256) void attn_partial()
{
    int ch = blockIdx.x, bh = blockIdx.y;
    int b = bh >> 3, h = bh & 7;
    int tid = threadIdx.x, lane = tid & 31, w = tid >> 5;

    __shared__ float qs[U_ * DK_];
    __shared__ float Ks[64 * 68];
    __shared__ float Vs[64 * 68];

    for (int i = tid; i < U_ * DK_; i += 256) {
        int u = i >> 6, d = i & 63;
        int l = g_idx[bh * U_ + u];
        qs[i] = g_Q[((size_t)(b * L_ + l)) * DM_ + h * DK_ + d];
    }
    __syncthreads();

    const int nu = (w == 0) ? 6 : 5;
    float qx[6], qy[6], m[6], ss[6], ax[6], ay[6];
    for (int k = 0; k < nu; k++) {
        int u = w + 8 * k;
        qx[k] = qs[u * 64 + 2 * lane];
        qy[k] = qs[u * 64 + 2 * lane + 1];
        m[k] = -CUDART_INF_F; ss[k] = 0.f; ax[k] = 0.f; ay[k] = 0.f;
    }

    const int jbase0 = ch * CHUNK_;
    for (int t = 0; t < CHUNK_ / 64; t++) {
        __syncthreads();
        int jb = jbase0 + t * 64;
        const float4* Kg = (const float4*)(g_K + ((size_t)(b * L_ + jb)) * DM_ + h * DK_);
        const float4* Vg = (const float4*)(g_V + ((size_t)(b * L_ + jb)) * DM_ + h * DK_);
#pragma unroll
        for (int r = 0; r < 4; r++) {
            int idx = tid + 256 * r;          // 0..1023
            int row = idx >> 4, cq = idx & 15;
            float4 kv = Kg[(size_t)row * (DM_ / 4) + cq];
            *(float4*)&Ks[row * 68 + cq * 4] = kv;
            float4 vv = Vg[(size_t)row * (DM_ / 4) + cq];
            *(float4*)&Vs[row * 68 + cq * 4] = vv;
        }
        __syncthreads();

        for (int k = 0; k < nu; k++) {
            float mm = m[k], s0 = ss[k], a0 = ax[k], a1 = ay[k];
            float Qx = qx[k], Qy = qy[k];
#pragma unroll 4
            for (int jj = 0; jj < 64; jj++) {
                float2 kk = *(const float2*)&Ks[jj * 68 + 2 * lane];
                float s = Qx * kk.x + Qy * kk.y;
                s += __shfl_xor_sync(0xffffffffu, s, 16);
                s += __shfl_xor_sync(0xffffffffu, s, 8);
                s += __shfl_xor_sync(0xffffffffu, s, 4);
                s += __shfl_xor_sync(0xffffffffu, s, 2);
                s += __shfl_xor_sync(0xffffffffu, s, 1);
                s *= 0.125f;  // 1/sqrt(64)
                float mn = fmaxf(mm, s);
                float ea = __expf(s - mn);
                float eb = __expf(mm - mn);
                float2 vv = *(const float2*)&Vs[jj * 68 + 2 * lane];
                s0 = s0 * eb + ea;
                a0 = a0 * eb + ea * vv.x;
                a1 = a1 * eb + ea * vv.y;
                mm = mn;
            }
            m[k] = mm; ss[k] = s0; ax[k] = a0; ay[k] = a1;
        }
    }

    for (int k = 0; k < nu; k++) {
        int u = w + 8 * k;
        size_t base = ((size_t)(bh * NCH_ + ch) * U_ + u) * 66;
        if (lane == 0) { g_part[base] = m[k]; g_part[base + 1] = ss[k]; }
        g_part[base + 2 + 2 * lane] = ax[k];
        g_part[base + 3 + 2 * lane] = ay[k];
    }
}

// ---------------- combine split-L partials -----------------------------------
__global__ __launch_bounds__(256) void attn_combine()
{
    int gw = (blockIdx.x * blockDim.x + threadIdx.x) >> 5;   // (bh,u) task
    int lane = threadIdx.x & 31;
    if (gw >= BH_ * U_) return;
    int bh = gw / U_, u = gw % U_;

    float M = -CUDART_INF_F;
#pragma unroll
    for (int ch = 0; ch < NCH_; ch++)
        M = fmaxf(M, g_part[((size_t)(bh * NCH_ + ch) * U_ + u) * 66]);
    float S = 0.f, a0 = 0.f, a1 = 0.f;
#pragma unroll
    for (int ch = 0; ch < NCH_; ch++) {
        size_t base = ((size_t)(bh * NCH_ + ch) * U_ + u) * 66;
        float f = __expf(g_part[base] - M);
        S  += g_part[base + 1] * f;
        a0 += g_part[base + 2 + 2 * lane] * f;
        a1 += g_part[base + 3 + 2 * lane] * f;
    }
    float inv = 1.0f / S;
    g_vals[(size_t)gw * 64 + 2 * lane]     = a0 * inv;
    g_vals[(size_t)gw * 64 + 2 * lane + 1] = a1 * inv;
}

// ---------------- context: fill with per-(b,h) V-mean, then scatter ----------
__global__ __launch_bounds__(256) void ctx_fill()
{
    int i = blockIdx.x * 256 + threadIdx.x;     // < B*L*DM = 2^24
    int b = i >> 21;                            // L_*DM_ = 2^21
    int c = i & 511;                            // h*64+d
    g_ctx[i] = g_vmean[(b << 9) + c];
}

__global__ __launch_bounds__(256) void ctx_scatter()
{
    int i = blockIdx.x * 256 + threadIdx.x;
    if (i >= BH_ * U_ * DV_) return;
    int d = i & 63, gu = i >> 6;
    int bh = gu / U_;
    int b = bh >> 3, h = bh & 7;
    int l = g_idx[gu];
    g_ctx[((size_t)(b * L_ + l)) * DM_ + h * DV_ + d] = g_vals[(size_t)gu * 64 + d];
}

// ---------------- LayerNorm (in place on d_out) -------------------------------
__global__ __launch_bounds__(128) void ln_kernel(float* __restrict__ out,
                                                 const float* __restrict__ gamma,
                                                 const float* __restrict__ beta)
{
    int row = blockIdx.x, tid = threadIdx.x;
    float4 x = ((const float4*)out)[(size_t)row * 128 + tid];
    float s  = x.x + x.y + x.z + x.w;
    float sq = x.x * x.x + x.y * x.y + x.z * x.z + x.w * x.w;
#pragma unroll
    for (int o = 16; o > 0; o >>= 1) {
        s  += __shfl_xor_sync(0xffffffffu, s, o);
        sq += __shfl_xor_sync(0xffffffffu, sq, o);
    }
    __shared__ float sh[8];
    int w = tid >> 5, lane = tid & 31;
    if (lane == 0) { sh[w] = s; sh[4 + w] = sq; }
    __syncthreads();
    s  = sh[0] + sh[1] + sh[2] + sh[3];
    sq = sh[4] + sh[5] + sh[6] + sh[7];
    float mu  = s * (1.0f / 512.0f);
    float var = sq * (1.0f / 512.0f) - mu * mu;
    float r   = rsqrtf(var + EPS_);
    float4 gg = ((const float4*)gamma)[tid];
    float4 bb = ((const float4*)beta)[tid];
    float4 y;
    y.x = gg.x * (x.x - mu) * r + bb.x;
    y.y = gg.y * (x.y - mu) * r + bb.y;
    y.z = gg.z * (x.z - mu) * r + bb.z;
    y.w = gg.w * (x.w - mu) * r + bb.w;
    ((float4*)out)[(size_t)row * 128 + tid] = y;
}

// ---------------- launch --------------------------------------------------------
extern "C" void kernel_launch(void* const* d_in, const int* in_sizes, int n_in,
                              void* d_out, int out_size)
{
    const float* inQ   = (const float*)d_in[0];
    const float* inK   = (const float*)d_in[1];
    const float* inV   = (const float*)d_in[2];
    const float* WQ    = (const float*)d_in[3];
    const float* WK    = (const float*)d_in[4];
    const float* WV    = (const float*)d_in[5];
    const float* Wfc   = (const float*)d_in[6];
    const float* gamma = (const float*)d_in[7];
    const float* beta  = (const float*)d_in[8];
    const int*   isamp = (const int*)d_in[9];
    float* out = (float*)d_out;

    float *Qp, *Kp, *Vp, *ctx;
    cudaGetSymbolAddress((void**)&Qp,  g_Q);
    cudaGetSymbolAddress((void**)&Kp,  g_K);
    cudaGetSymbolAddress((void**)&Vp,  g_V);
    cudaGetSymbolAddress((void**)&ctx, g_ctx);

    const int M = B_ * L_;                     // 32768
    dim3 gemmGrid(DM_ / 128, M / 128);          // (4, 256)

    // 1. projections
    sgemm128<<<gemmGrid, 256>>>(inQ, WQ, nullptr, Qp, M, DM_, DM_);
    sgemm128<<<gemmGrid, 256>>>(inK, WK, nullptr, Kp, M, DM_, DM_);
    sgemm128<<<gemmGrid, 256>>>(inV, WV, nullptr, Vp, M, DM_, DM_);

    // 2. sparsity measure M
    qkm_kernel<<<(BH_ * L_) / 8, 256>>>(isamp);

    // 3. top-k query selection
    topk_kernel<<<BH_, 256>>>();

    // 4. V mean per (b,h)
    vmean_kernel<<<BH_, 256>>>();

    // 5. sparse attention (split-L) + combine
    attn_partial<<<dim3(NCH_, BH_), 256>>>();
    attn_combine<<<(BH_ * U_ * 32 + 255) / 256, 256>>>();

    // 6. context assembly
    ctx_fill<<<(B_ * L_ * DM_) / 256, 256>>>();
    ctx_scatter<<<(BH_ * U_ * DV_ + 255) / 256, 256>>>();

    // 7. output projection + residual
    sgemm128<<<gemmGrid, 256>>>(ctx, Wfc, inQ, out, M, DM_, DM_);

    // 8. layernorm in place
    ln_kernel<<<M, 128>>>(out, gamma, beta);
}

// round 2
// speedup vs baseline: 1.1830x; 1.1830x over previous
#include <cuda_runtime.h>
#include <math_constants.h>

#define B_    8
#define L_    4096
#define DM_   512
#define H_    8
#define DK_   64
#define DV_   64
#define U_    41
#define BH_   (B_*H_)
#define NCH_  8
#define CHUNK_ (L_/NCH_)      // 512
#define EPS_  1e-5f

// ---------------- scratch (static device globals; no allocations) ----------
__device__ float g_Q[B_*L_*DM_];          // 64 MB
__device__ float g_K[B_*L_*DM_];          // 64 MB
__device__ float g_V[B_*L_*DM_];          // 64 MB
__device__ float g_M[BH_*L_];             // 1 MB
__device__ int   g_idx[BH_*U_];
__device__ float g_vals[BH_*U_*DV_];
__device__ float g_vmean[BH_*DV_];        // also = per-batch 512-vec (contiguous over h)
__device__ float g_obase[B_*DM_];         // vmeanvec_b @ W_fc
__device__ float g_part[BH_*NCH_*U_*66];  // per-chunk {m, s, acc[64]}

// ---------------- fp32 SGEMM: C[M,N] = A[M,K] @ B[K,N] ---------------------
// 128x128 tile, BK=16, 256 threads, 8x8 micro, double-buffered smem.
// (measured ~92% of the 36 TF/s fp32 CUDA-core roofline; tensor-core rewrite
//  is the next round's job)
__global__ __launch_bounds__(256) void sgemm128(
    const float* __restrict__ A, const float* __restrict__ Bm,
    float* __restrict__ C, int M, int N, int K)
{
    __shared__ float As[2][16][128];
    __shared__ float Bs[2][16][128];
    const int tid  = threadIdx.x;
    const int row0 = blockIdx.y * 128, col0 = blockIdx.x * 128;
    const int tm   = tid >> 4, tn = tid & 15;
    const int K4   = K >> 2, N4 = N >> 2;
    const int nkt  = K >> 4;

    float acc[8][8];
#pragma unroll
    for (int i = 0; i < 8; i++)
#pragma unroll
        for (int j = 0; j < 8; j++) acc[i][j] = 0.f;

#pragma unroll
    for (int i = 0; i < 2; i++) {
        int idx = tid * 2 + i;
        int ar = idx >> 2, kq = idx & 3;
        float4 v = __ldg((const float4*)A + (size_t)(row0 + ar) * K4 + kq);
        As[0][kq*4+0][ar] = v.x; As[0][kq*4+1][ar] = v.y;
        As[0][kq*4+2][ar] = v.z; As[0][kq*4+3][ar] = v.w;
        int br = idx >> 5, bc = (idx & 31) << 2;
        float4 w2 = __ldg((const float4*)Bm + (size_t)br * N4 + ((col0 + bc) >> 2));
        *(float4*)&Bs[0][br][bc] = w2;
    }
    __syncthreads();

    for (int kt = 0; kt < nkt; kt++) {
        const int cur = kt & 1, nxt = cur ^ 1;
        float4 ra[2], rb[2];
        const bool pf = (kt + 1) < nkt;
        if (pf) {
#pragma unroll
            for (int i = 0; i < 2; i++) {
                int idx = tid * 2 + i;
                int ar = idx >> 2, kq = idx & 3;
                ra[i] = __ldg((const float4*)A + (size_t)(row0 + ar) * K4 + (kt + 1) * 4 + kq);
                int br = idx >> 5, bc = (idx & 31) << 2;
                rb[i] = __ldg((const float4*)Bm + (size_t)((kt + 1) * 16 + br) * N4 + ((col0 + bc) >> 2));
            }
        }
#pragma unroll
        for (int kk = 0; kk < 16; kk++) {
            float a[8], b[8];
            *(float4*)&a[0] = *(const float4*)&As[cur][kk][tm * 8];
            *(float4*)&a[4] = *(const float4*)&As[cur][kk][tm * 8 + 4];
            *(float4*)&b[0] = *(const float4*)&Bs[cur][kk][tn * 8];
            *(float4*)&b[4] = *(const float4*)&Bs[cur][kk][tn * 8 + 4];
#pragma unroll
            for (int i = 0; i < 8; i++)
#pragma unroll
                for (int j = 0; j < 8; j++)
                    acc[i][j] = fmaf(a[i], b[j], acc[i][j]);
        }
        if (pf) {
#pragma unroll
            for (int i = 0; i < 2; i++) {
                int idx = tid * 2 + i;
                int ar = idx >> 2, kq = idx & 3;
                As[nxt][kq*4+0][ar] = ra[i].x; As[nxt][kq*4+1][ar] = ra[i].y;
                As[nxt][kq*4+2][ar] = ra[i].z; As[nxt][kq*4+3][ar] = ra[i].w;
                int br = idx >> 5, bc = (idx & 31) << 2;
                *(float4*)&Bs[nxt][br][bc] = rb[i];
            }
        }
        __syncthreads();
    }

#pragma unroll
    for (int i = 0; i < 8; i++) {
        size_t r = (size_t)(row0 + tm * 8 + i);
#pragma unroll
        for (int j4 = 0; j4 < 2; j4++) {
            size_t off = r * N + col0 + tn * 8 + j4 * 4;
            float4 v;
            v.x = acc[i][j4*4+0]; v.y = acc[i][j4*4+1];
            v.z = acc[i][j4*4+2]; v.w = acc[i][j4*4+3];
            *(float4*)(C + off) = v;
        }
    }
}

// ---------------- QK_samp -> M : one warp per (b,l), all 8 heads ------------
// Lane owns dims [16*lane, 16*lane+16); head = lane>>2. Per sample: 16 FMA +
// 2 SHFL (vs 5 SHFL x 8 head-warps before). Gather traffic unchanged
// (K stays L2-resident).
__global__ __launch_bounds__(256) void qkm2_kernel(const int* __restrict__ isamp)
{
    int gw   = (blockIdx.x * 256 + threadIdx.x) >> 5;   // (b,l) in [0, B*L)
    int lane = threadIdx.x & 31;
    int l = gw & (L_ - 1);
    int b = gw >> 12;

    const float4* q4 = (const float4*)(g_Q + ((size_t)(b * L_ + l)) * DM_) + lane * 4;
    float4 q0 = q4[0], q1 = q4[1], q2 = q4[2], q3 = q4[3];

    float smax = -CUDART_INF_F, ssum = 0.f;
    const int* ip = isamp + l * U_;
#pragma unroll 2
    for (int u = 0; u < U_; u++) {
        int j = __ldg(ip + u);
        const float4* k4 = (const float4*)(g_K + ((size_t)(b * L_ + j)) * DM_) + lane * 4;
        float4 k0 = k4[0], k1 = k4[1], k2 = k4[2], k3 = k4[3];
        float s = q0.x * k0.x;
        s = fmaf(q0.y, k0.y, s); s = fmaf(q0.z, k0.z, s); s = fmaf(q0.w, k0.w, s);
        s = fmaf(q1.x, k1.x, s); s = fmaf(q1.y, k1.y, s); s = fmaf(q1.z, k1.z, s); s = fmaf(q1.w, k1.w, s);
        s = fmaf(q2.x, k2.x, s); s = fmaf(q2.y, k2.y, s); s = fmaf(q2.z, k2.z, s); s = fmaf(q2.w, k2.w, s);
        s = fmaf(q3.x, k3.x, s); s = fmaf(q3.y, k3.y, s); s = fmaf(q3.z, k3.z, s); s = fmaf(q3.w, k3.w, s);
        s += __shfl_xor_sync(0xffffffffu, s, 1);
        s += __shfl_xor_sync(0xffffffffu, s, 2);
        smax = fmaxf(smax, s);
        ssum += s;
    }
    if ((lane & 3) == 0) {
        int h = lane >> 2;
        g_M[((size_t)(b * 8 + h)) * L_ + l] = smax - ssum * (1.0f / U_);
    }
}

// ---------------- top-k (U=41) per (b,h), iterative argmax ------------------
__global__ __launch_bounds__(256) void topk_kernel()
{
    int bh = blockIdx.x;
    __shared__ float sv[L_];
    __shared__ float rv[256];
    __shared__ int   ri[256];
    int tid = threadIdx.x;
    for (int i = tid; i < L_; i += 256) sv[i] = g_M[bh * L_ + i];
    __syncthreads();
    for (int it = 0; it < U_; it++) {
        float best = -CUDART_INF_F; int bi = L_;
        for (int i = tid; i < L_; i += 256) {
            float v = sv[i];
            if (v > best) { best = v; bi = i; }
        }
        rv[tid] = best; ri[tid] = bi;
        __syncthreads();
        for (int s = 128; s > 0; s >>= 1) {
            if (tid < s) {
                float v2 = rv[tid + s]; int i2 = ri[tid + s];
                if (v2 > rv[tid] || (v2 == rv[tid] && i2 < ri[tid])) { rv[tid] = v2; ri[tid] = i2; }
            }
            __syncthreads();
        }
        if (tid == 0) { g_idx[bh * U_ + it] = ri[0]; sv[ri[0]] = -CUDART_INF_F; }
        __syncthreads();
    }
}

// ---------------- V mean over L per (b,h) ------------------------------------
__global__ __launch_bounds__(256) void vmean_kernel()
{
    int bh = blockIdx.x;
    int b = bh >> 3, h = bh & 7;
    int tid = threadIdx.x;
    int d = tid & 63, g = tid >> 6;
    float sum = 0.f;
    for (int l = g; l < L_; l += 4)
        sum += g_V[((size_t)(b * L_ + l)) * DM_ + h * DK_ + d];
    __shared__ float red[4][64];
    red[g][d] = sum;
    __syncthreads();
    if (g == 0) {
        float t = red[0][d] + red[1][d] + red[2][d] + red[3][d];
        g_vmean[bh * 64 + d] = t * (1.0f / L_);
    }
}

// ---------------- sparse attention, split-L partials -------------------------
__global__ __launch_bounds__(256) void attn_partial()
{
    int ch = blockIdx.x, bh = blockIdx.y;
    int b = bh >> 3, h = bh & 7;
    int tid = threadIdx.x, lane = tid & 31, w = tid >> 5;

    __shared__ float qs[U_ * DK_];
    __shared__ float Ks[64 * 68];
    __shared__ float Vs[64 * 68];

    for (int i = tid; i < U_ * DK_; i += 256) {
        int u = i >> 6, d = i & 63;
        int l = g_idx[bh * U_ + u];
        qs[i] = g_Q[((size_t)(b * L_ + l)) * DM_ + h * DK_ + d];
    }
    __syncthreads();

    const int nu = (w == 0) ? 6 : 5;
    float qx[6], qy[6], m[6], ss[6], ax[6], ay[6];
    for (int k = 0; k < nu; k++) {
        int u = w + 8 * k;
        qx[k] = qs[u * 64 + 2 * lane];
        qy[k] = qs[u * 64 + 2 * lane + 1];
        m[k] = -CUDART_INF_F; ss[k] = 0.f; ax[k] = 0.f; ay[k] = 0.f;
    }

    const int jbase0 = ch * CHUNK_;
    for (int t = 0; t < CHUNK_ / 64; t++) {
        __syncthreads();
        int jb = jbase0 + t * 64;
        const float4* Kg = (const float4*)(g_K + ((size_t)(b * L_ + jb)) * DM_ + h * DK_);
        const float4* Vg = (const float4*)(g_V + ((size_t)(b * L_ + jb)) * DM_ + h * DK_);
#pragma unroll
        for (int r = 0; r < 4; r++) {
            int idx = tid + 256 * r;
            int row = idx >> 4, cq = idx & 15;
            float4 kv = Kg[(size_t)row * (DM_ / 4) + cq];
            *(float4*)&Ks[row * 68 + cq * 4] = kv;
            float4 vv = Vg[(size_t)row * (DM_ / 4) + cq];
            *(float4*)&Vs[row * 68 + cq * 4] = vv;
        }
        __syncthreads();

        for (int k = 0; k < nu; k++) {
            float mm = m[k], s0 = ss[k], a0 = ax[k], a1 = ay[k];
            float Qx = qx[k], Qy = qy[k];
#pragma unroll 4
            for (int jj = 0; jj < 64; jj++) {
                float2 kk = *(const float2*)&Ks[jj * 68 + 2 * lane];
                float s = Qx * kk.x + Qy * kk.y;
                s += __shfl_xor_sync(0xffffffffu, s, 16);
                s += __shfl_xor_sync(0xffffffffu, s, 8);
                s += __shfl_xor_sync(0xffffffffu, s, 4);
                s += __shfl_xor_sync(0xffffffffu, s, 2);
                s += __shfl_xor_sync(0xffffffffu, s, 1);
                s *= 0.125f;
                float mn = fmaxf(mm, s);
                float ea = __expf(s - mn);
                float eb = __expf(mm - mn);
                float2 vv = *(const float2*)&Vs[jj * 68 + 2 * lane];
                s0 = s0 * eb + ea;
                a0 = a0 * eb + ea * vv.x;
                a1 = a1 * eb + ea * vv.y;
                mm = mn;
            }
            m[k] = mm; ss[k] = s0; ax[k] = a0; ay[k] = a1;
        }
    }

    for (int k = 0; k < nu; k++) {
        int u = w + 8 * k;
        size_t base = ((size_t)(bh * NCH_ + ch) * U_ + u) * 66;
        if (lane == 0) { g_part[base] = m[k]; g_part[base + 1] = ss[k]; }
        g_part[base + 2 + 2 * lane] = ax[k];
        g_part[base + 3 + 2 * lane] = ay[k];
    }
}

// ---------------- combine split-L partials -----------------------------------
__global__ __launch_bounds__(256) void attn_combine()
{
    int gw = (blockIdx.x * blockDim.x + threadIdx.x) >> 5;
    int lane = threadIdx.x & 31;
    if (gw >= BH_ * U_) return;
    int bh = gw / U_, u = gw % U_;

    float M = -CUDART_INF_F;
#pragma unroll
    for (int ch = 0; ch < NCH_; ch++)
        M = fmaxf(M, g_part[((size_t)(bh * NCH_ + ch) * U_ + u) * 66]);
    float S = 0.f, a0 = 0.f, a1 = 0.f;
#pragma unroll
    for (int ch = 0; ch < NCH_; ch++) {
        size_t base = ((size_t)(bh * NCH_ + ch) * U_ + u) * 66;
        float f = __expf(g_part[base] - M);
        S  += g_part[base + 1] * f;
        a0 += g_part[base + 2 + 2 * lane] * f;
        a1 += g_part[base + 3 + 2 * lane] * f;
    }
    float inv = 1.0f / S;
    g_vals[(size_t)gw * 64 + 2 * lane]     = a0 * inv;
    g_vals[(size_t)gw * 64 + 2 * lane + 1] = a1 * inv;
}

// ---------------- low-rank output path ---------------------------------------
// obase[b,:] = vmeanvec_b @ W_fc   (g_vmean is contiguous: bh*64+d = b*512+c)
__global__ __launch_bounds__(256) void obase_kernel(const float* __restrict__ Wfc)
{
    int b = blockIdx.x, tid = threadIdx.x;
    __shared__ float vm[512];
    vm[tid]       = g_vmean[b * 512 + tid];
    vm[tid + 256] = g_vmean[b * 512 + tid + 256];
    __syncthreads();
    float a0 = 0.f, a1 = 0.f;
    const float2* W2 = (const float2*)Wfc + tid;
#pragma unroll 8
    for (int r = 0; r < 512; r++) {
        float2 w = __ldg(W2 + (size_t)r * 256);
        float v = vm[r];
        a0 = fmaf(v, w.x, a0);
        a1 = fmaf(v, w.y, a1);
    }
    g_obase[b * 512 + 2 * tid]     = a0;
    g_obase[b * 512 + 2 * tid + 1] = a1;
}

// out[b,l,:] = obase[b,:] + inQ[b,l,:]   (float4, pure stream)
__global__ __launch_bounds__(256) void out_assemble(const float* __restrict__ inQ,
                                                    float* __restrict__ out)
{
    int i4 = blockIdx.x * 256 + threadIdx.x;   // < B*L*DM/4 = 2^22
    int b  = i4 >> 19;                         // L*DM/4 = 2^19
    int c4 = i4 & 127;                         // DM/4 = 128
    float4 x = ((const float4*)inQ)[i4];
    float4 o = __ldg((const float4*)g_obase + (b << 7) + c4);
    x.x += o.x; x.y += o.y; x.z += o.z; x.w += o.w;
    ((float4*)out)[i4] = x;
}

// per-selected-row rank-64 correction: out[b,l,:] += (vals-vmean_h) @ Wfc[h*64:,:]
__global__ __launch_bounds__(128) void correction_kernel(float* __restrict__ out,
                                                         const float* __restrict__ Wfc)
{
    int gu = blockIdx.x;                 // bh*U + u
    int bh = gu / U_;
    int b = bh >> 3, h = bh & 7;
    int l = g_idx[gu];
    int tid = threadIdx.x;

    __shared__ float delta[64];
    if (tid < 64)
        delta[tid] = g_vals[(size_t)gu * 64 + tid] - g_vmean[bh * 64 + tid];
    __syncthreads();

    float4 acc = make_float4(0.f, 0.f, 0.f, 0.f);
    const float4* W4 = (const float4*)Wfc + (size_t)(h * 64) * 128 + tid;
#pragma unroll 8
    for (int k = 0; k < 64; k++) {
        float d = delta[k];
        float4 w = __ldg(W4 + (size_t)k * 128);
        acc.x = fmaf(d, w.x, acc.x);
        acc.y = fmaf(d, w.y, acc.y);
        acc.z = fmaf(d, w.z, acc.z);
        acc.w = fmaf(d, w.w, acc.w);
    }
    float* o = out + ((size_t)(b * L_ + l)) * 512 + tid * 4;
    atomicAdd(o + 0, acc.x);
    atomicAdd(o + 1, acc.y);
    atomicAdd(o + 2, acc.z);
    atomicAdd(o + 3, acc.w);
}

// ---------------- LayerNorm (in place on d_out) -------------------------------
__global__ __launch_bounds__(128) void ln_kernel(float* __restrict__ out,
                                                 const float* __restrict__ gamma,
                                                 const float* __restrict__ beta)
{
    int row = blockIdx.x, tid = threadIdx.x;
    float4 x = ((const float4*)out)[(size_t)row * 128 + tid];
    float s  = x.x + x.y + x.z + x.w;
    float sq = x.x * x.x + x.y * x.y + x.z * x.z + x.w * x.w;
#pragma unroll
    for (int o = 16; o > 0; o >>= 1) {
        s  += __shfl_xor_sync(0xffffffffu, s, o);
        sq += __shfl_xor_sync(0xffffffffu, sq, o);
    }
    __shared__ float sh[8];
    int w = tid >> 5, lane = tid & 31;
    if (lane == 0) { sh[w] = s; sh[4 + w] = sq; }
    __syncthreads();
    s  = sh[0] + sh[1] + sh[2] + sh[3];
    sq = sh[4] + sh[5] + sh[6] + sh[7];
    float mu  = s * (1.0f / 512.0f);
    float var = sq * (1.0f / 512.0f) - mu * mu;
    float r   = rsqrtf(var + EPS_);
    float4 gg = ((const float4*)gamma)[tid];
    float4 bb = ((const float4*)beta)[tid];
    float4 y;
    y.x = gg.x * (x.x - mu) * r + bb.x;
    y.y = gg.y * (x.y - mu) * r + bb.y;
    y.z = gg.z * (x.z - mu) * r + bb.z;
    y.w = gg.w * (x.w - mu) * r + bb.w;
    ((float4*)out)[(size_t)row * 128 + tid] = y;
}

// ---------------- launch --------------------------------------------------------
extern "C" void kernel_launch(void* const* d_in, const int* in_sizes, int n_in,
                              void* d_out, int out_size)
{
    const float* inQ   = (const float*)d_in[0];
    const float* inK   = (const float*)d_in[1];
    const float* inV   = (const float*)d_in[2];
    const float* WQ    = (const float*)d_in[3];
    const float* WK    = (const float*)d_in[4];
    const float* WV    = (const float*)d_in[5];
    const float* Wfc   = (const float*)d_in[6];
    const float* gamma = (const float*)d_in[7];
    const float* beta  = (const float*)d_in[8];
    const int*   isamp = (const int*)d_in[9];
    float* out = (float*)d_out;

    float *Qp, *Kp, *Vp;
    cudaGetSymbolAddress((void**)&Qp, g_Q);
    cudaGetSymbolAddress((void**)&Kp, g_K);
    cudaGetSymbolAddress((void**)&Vp, g_V);

    const int M = B_ * L_;                     // 32768
    dim3 gemmGrid(DM_ / 128, M / 128);          // (4, 256)

    // 1. projections (fp32 CUDA-core roofline; tcgen05 rewrite next)
    sgemm128<<<gemmGrid, 256>>>(inQ, WQ, Qp, M, DM_, DM_);
    sgemm128<<<gemmGrid, 256>>>(inK, WK, Kp, M, DM_, DM_);
    sgemm128<<<gemmGrid, 256>>>(inV, WV, Vp, M, DM_, DM_);

    // 2. sparsity measure (all heads per warp)
    qkm2_kernel<<<(B_ * L_ * 32) / 256, 256>>>(isamp);

    // 3. top-k query selection
    topk_kernel<<<BH_, 256>>>();

    // 4. V mean per (b,h)
    vmean_kernel<<<BH_, 256>>>();

    // 5. sparse attention (split-L) + combine
    attn_partial<<<dim3(NCH_, BH_), 256>>>();
    attn_combine<<<(BH_ * U_ * 32 + 255) / 256, 256>>>();

    // 6. low-rank output: base GEMV + broadcast-assemble + sparse corrections
    obase_kernel<<<B_, 256>>>(Wfc);
    out_assemble<<<(B_ * L_ * DM_ / 4) / 256, 256>>>(inQ, out);
    correction_kernel<<<BH_ * U_, 128>>>(out, Wfc);

    // 7. layernorm in place
    ln_kernel<<<M, 128>>>(out, gamma, beta);
}

// round 4
// speedup vs baseline: 1.4083x; 1.1905x over previous
#include <cuda_runtime.h>
#include <math_constants.h>
#include <cstdint>

#define B_    8
#define L_    4096
#define DM_   512
#define H_    8
#define DK_   64
#define DV_   64
#define U_    41
#define BH_   (B_*H_)
#define NCH_  8
#define CHUNK_ (L_/NCH_)
#define EPS_  1e-5f

// ---------------- scratch ----------------------------------------------------
__device__ float g_Q[B_*L_*DM_];
__device__ float g_K[B_*L_*DM_];
__device__ float g_V[B_*L_*DM_];
__device__ float g_Ahi[B_*L_*DM_];
__device__ float g_Alo[B_*L_*DM_];
__device__ float g_Wthi[DM_*DM_];         // W^T tf32 hi  ([N][K])
__device__ float g_Wtlo[DM_*DM_];
__device__ float g_M[BH_*L_];
__device__ int   g_idx[BH_*U_];
__device__ float g_vals[BH_*U_*DV_];
__device__ float g_vmean[BH_*DV_];
__device__ float g_obase[B_*DM_];
__device__ float g_part[BH_*NCH_*U_*66];

// ---------------- helpers ------------------------------------------------------
__device__ __forceinline__ uint32_t smem_u32(const void* p) {
    uint32_t a;
    asm("{ .reg .u64 t; cvta.to.shared.u64 t, %1; cvt.u32.u64 %0, t; }" : "=r"(a) : "l"(p));
    return a;
}
__device__ __forceinline__ float tf32_rna(float x) {
    float r; asm("cvt.rna.tf32.f32 %0, %1;" : "=f"(r) : "f"(x)); return r;
}
#define CP_ASYNC_CG(dst, src) \
    asm volatile("cp.async.cg.shared.global [%0], [%1], 16;" :: "r"(dst), "l"(src) : "memory")
#define CP_COMMIT() asm volatile("cp.async.commit_group;" ::: "memory")
#define CP_WAIT1()  asm volatile("cp.async.wait_group 1;" ::: "memory")
#define CP_WAIT0()  asm volatile("cp.async.wait_group 0;" ::: "memory")

#define MMA_TF32(c, a, b) \
    asm volatile("mma.sync.aligned.m16n8k8.row.col.f32.tf32.tf32.f32 " \
        "{%0,%1,%2,%3}, {%4,%5,%6,%7}, {%8,%9}, {%0,%1,%2,%3};" \
        : "+f"((c)[0]), "+f"((c)[1]), "+f"((c)[2]), "+f"((c)[3]) \
        : "r"(__float_as_uint((a)[0])), "r"(__float_as_uint((a)[1])), \
          "r"(__float_as_uint((a)[2])), "r"(__float_as_uint((a)[3])), \
          "r"(__float_as_uint((b)[0])), "r"(__float_as_uint((b)[1])))

// ---------------- tf32 split: activations (row-major pass-through) -------------
__global__ __launch_bounds__(256) void splitA_kernel(const float* __restrict__ A)
{
    int i = blockIdx.x * 256 + threadIdx.x;
    float4 x = __ldg((const float4*)A + i);
    float4 h, lo;
    h.x = tf32_rna(x.x); lo.x = tf32_rna(x.x - h.x);
    h.y = tf32_rna(x.y); lo.y = tf32_rna(x.y - h.y);
    h.z = tf32_rna(x.z); lo.z = tf32_rna(x.z - h.z);
    h.w = tf32_rna(x.w); lo.w = tf32_rna(x.w - h.w);
    ((float4*)g_Ahi)[i] = h;
    ((float4*)g_Alo)[i] = lo;
}

// ---------------- tf32 split + transpose for W (smem-tiled) ---------------------
__global__ __launch_bounds__(256) void splitWT_kernel(const float* __restrict__ W)
{
    __shared__ float tile[32][33];
    int bx = blockIdx.x * 32;         // n block
    int by = blockIdx.y * 32;         // k block
    int tx = threadIdx.x & 31, ty = threadIdx.x >> 5;
#pragma unroll
    for (int i = 0; i < 4; i++)
        tile[ty + 8 * i][tx] = __ldg(&W[(size_t)(by + ty + 8 * i) * 512 + bx + tx]);
    __syncthreads();
#pragma unroll
    for (int i = 0; i < 4; i++) {
        int n = bx + ty + 8 * i, k = by + tx;
        float v = tile[tx][ty + 8 * i];
        float h = tf32_rna(v);
        g_Wthi[(size_t)n * 512 + k] = h;
        g_Wtlo[(size_t)n * 512 + k] = tf32_rna(v - h);
    }
}

// ---------------- HMMA tf32x3 GEMM ----------------------------------------------
// C[128 x 128] tile, K=512 in 16 chunks of 32, cp.async double buffer.
// smem per stage: 4 matrices (Ahi, Alo, Bhi, Blo) of 128x32, row pad 36.
#define PADK 36
#define MATF (128 * PADK)             // 4608 floats
#define STAGEF (4 * MATF)             // 18432 floats
#define GSMEM_BYTES (2 * STAGEF * 4)  // 147456

__device__ __forceinline__ void g_load_stage(
    float* sm, int stage, int c, int tid,
    const float* a0, const float* a1, const float* b0, const float* b1)
{
    const float* srcs[4] = { a0, a1, b0, b1 };
    float* dst = sm + stage * STAGEF;
#pragma unroll
    for (int i = 0; i < 16; i++) {
        int u = i * 256 + tid;
        int mat = u >> 10, rem = u & 1023;
        int row = rem >> 3, q = rem & 7;
        uint32_t d = smem_u32(dst + mat * MATF + row * PADK + q * 4);
        const float* sp = srcs[mat] + (size_t)row * 512 + c * 32 + q * 4;
        CP_ASYNC_CG(d, sp);
    }
    CP_COMMIT();
}

__global__ __launch_bounds__(256, 1) void gemm_hmma(float* __restrict__ C)
{
    extern __shared__ float sm[];
    const int tid = threadIdx.x;
    const int wid = tid >> 5, lane = tid & 31;
    const int g = lane >> 2, tg = lane & 3;
    const int wm = wid & 1, wn = wid >> 1;          // 2 x 4 warp grid
    const int row0 = blockIdx.y * 128, col0 = blockIdx.x * 128;

    const float* a0 = g_Ahi + (size_t)row0 * 512;
    const float* a1 = g_Alo + (size_t)row0 * 512;
    const float* b0 = g_Wthi + (size_t)col0 * 512;
    const float* b1 = g_Wtlo + (size_t)col0 * 512;

    float acc[4][4][4];
#pragma unroll
    for (int i = 0; i < 4; i++)
#pragma unroll
        for (int j = 0; j < 4; j++)
#pragma unroll
            for (int r = 0; r < 4; r++) acc[i][j][r] = 0.f;

    g_load_stage(sm, 0, 0, tid, a0, a1, b0, b1);

    for (int c = 0; c < 16; c++) {
        const int buf = c & 1;
        if (c < 15) g_load_stage(sm, buf ^ 1, c + 1, tid, a0, a1, b0, b1);
        if (c < 15) { CP_WAIT1(); } else { CP_WAIT0(); }
        __syncthreads();

        const float* Ah = sm + buf * STAGEF;
        const float* Al = Ah + MATF;
        const float* Bh = Ah + 2 * MATF;
        const float* Bl = Ah + 3 * MATF;

#pragma unroll
        for (int k8 = 0; k8 < 4; k8++) {
            const int k0 = k8 * 8;
            float ah[4][4], al[4][4], bh[4][2], bl[4][2];
#pragma unroll
            for (int i = 0; i < 4; i++) {
                int r = wm * 64 + i * 16 + g;
                ah[i][0] = Ah[r * PADK + k0 + tg];
                ah[i][1] = Ah[(r + 8) * PADK + k0 + tg];
                ah[i][2] = Ah[r * PADK + k0 + tg + 4];
                ah[i][3] = Ah[(r + 8) * PADK + k0 + tg + 4];
                al[i][0] = Al[r * PADK + k0 + tg];
                al[i][1] = Al[(r + 8) * PADK + k0 + tg];
                al[i][2] = Al[r * PADK + k0 + tg + 4];
                al[i][3] = Al[(r + 8) * PADK + k0 + tg + 4];
            }
#pragma unroll
            for (int j = 0; j < 4; j++) {
                int n = wn * 32 + j * 8 + g;
                bh[j][0] = Bh[n * PADK + k0 + tg];
                bh[j][1] = Bh[n * PADK + k0 + tg + 4];
                bl[j][0] = Bl[n * PADK + k0 + tg];
                bl[j][1] = Bl[n * PADK + k0 + tg + 4];
            }
            // three products; (i,j) inner so dependent MMAs are 16 apart
#pragma unroll
            for (int i = 0; i < 4; i++)
#pragma unroll
                for (int j = 0; j < 4; j++) MMA_TF32(acc[i][j], ah[i], bh[j]);
#pragma unroll
            for (int i = 0; i < 4; i++)
#pragma unroll
                for (int j = 0; j < 4; j++) MMA_TF32(acc[i][j], ah[i], bl[j]);
#pragma unroll
            for (int i = 0; i < 4; i++)
#pragma unroll
                for (int j = 0; j < 4; j++) MMA_TF32(acc[i][j], al[i], bh[j]);
        }
        __syncthreads();
    }

#pragma unroll
    for (int i = 0; i < 4; i++) {
#pragma unroll
        for (int j = 0; j < 4; j++) {
            int row = row0 + wm * 64 + i * 16 + g;
            int col = col0 + wn * 32 + j * 8 + tg * 2;
            float2 v0 = make_float2(acc[i][j][0], acc[i][j][1]);
            float2 v1 = make_float2(acc[i][j][2], acc[i][j][3]);
            *(float2*)(C + (size_t)row * 512 + col) = v0;
            *(float2*)(C + (size_t)(row + 8) * 512 + col) = v1;
        }
    }
}

// ---------------- QK_samp -> M : coalesced gathers, 16-lane-group reduce -------
__global__ __launch_bounds__(256) void qkm3_kernel(const int* __restrict__ isamp)
{
    int gw   = (blockIdx.x * 256 + threadIdx.x) >> 5;   // (b,l)
    int lane = threadIdx.x & 31;
    int l = gw & (L_ - 1);
    int b = gw >> 12;

    const float4* qb = (const float4*)(g_Q + ((size_t)(b * L_ + l)) * DM_);
    float4 q0 = qb[lane], q1 = qb[lane + 32], q2 = qb[lane + 64], q3 = qb[lane + 96];

    float smax0 = -CUDART_INF_F, smax1 = -CUDART_INF_F, smax2 = -CUDART_INF_F, smax3 = -CUDART_INF_F;
    float ssum0 = 0.f, ssum1 = 0.f, ssum2 = 0.f, ssum3 = 0.f;
    const int* ip = isamp + l * U_;

#pragma unroll 2
    for (int u = 0; u < U_; u++) {
        int j = __ldg(ip + u);
        const float4* kb = (const float4*)(g_K + ((size_t)(b * L_ + j)) * DM_);
        float4 k0 = kb[lane], k1 = kb[lane + 32], k2 = kb[lane + 64], k3 = kb[lane + 96];
        float s0 = q0.x * k0.x; s0 = fmaf(q0.y, k0.y, s0); s0 = fmaf(q0.z, k0.z, s0); s0 = fmaf(q0.w, k0.w, s0);
        float s1 = q1.x * k1.x; s1 = fmaf(q1.y, k1.y, s1); s1 = fmaf(q1.z, k1.z, s1); s1 = fmaf(q1.w, k1.w, s1);
        float s2 = q2.x * k2.x; s2 = fmaf(q2.y, k2.y, s2); s2 = fmaf(q2.z, k2.z, s2); s2 = fmaf(q2.w, k2.w, s2);
        float s3 = q3.x * k3.x; s3 = fmaf(q3.y, k3.y, s3); s3 = fmaf(q3.z, k3.z, s3); s3 = fmaf(q3.w, k3.w, s3);
#pragma unroll
        for (int m = 1; m <= 8; m <<= 1) {
            s0 += __shfl_xor_sync(0xffffffffu, s0, m);
            s1 += __shfl_xor_sync(0xffffffffu, s1, m);
            s2 += __shfl_xor_sync(0xffffffffu, s2, m);
            s3 += __shfl_xor_sync(0xffffffffu, s3, m);
        }
        smax0 = fmaxf(smax0, s0); ssum0 += s0;
        smax1 = fmaxf(smax1, s1); ssum1 += s1;
        smax2 = fmaxf(smax2, s2); ssum2 += s2;
        smax3 = fmaxf(smax3, s3); ssum3 += s3;
    }
    if ((lane & 15) == 0) {
        int g = lane >> 4;
        size_t base = ((size_t)b * 8) * L_ + l;
        g_M[base + (size_t)(g + 0) * L_] = smax0 - ssum0 * (1.0f / U_);
        g_M[base + (size_t)(g + 2) * L_] = smax1 - ssum1 * (1.0f / U_);
        g_M[base + (size_t)(g + 4) * L_] = smax2 - ssum2 * (1.0f / U_);
        g_M[base + (size_t)(g + 6) * L_] = smax3 - ssum3 * (1.0f / U_);
    }
}

// ---------------- top-k (U=41) per (b,h) ---------------------------------------
__global__ __launch_bounds__(256) void topk_kernel()
{
    int bh = blockIdx.x;
    __shared__ float sv[L_];
    __shared__ float rv[256];
    __shared__ int   ri[256];
    int tid = threadIdx.x;
    for (int i = tid; i < L_; i += 256) sv[i] = g_M[bh * L_ + i];
    __syncthreads();
    for (int it = 0; it < U_; it++) {
        float best = -CUDART_INF_F; int bi = L_;
        for (int i = tid; i < L_; i += 256) {
            float v = sv[i];
            if (v > best) { best = v; bi = i; }
        }
        rv[tid] = best; ri[tid] = bi;
        __syncthreads();
        for (int s = 128; s > 0; s >>= 1) {
            if (tid < s) {
                float v2 = rv[tid + s]; int i2 = ri[tid + s];
                if (v2 > rv[tid] || (v2 == rv[tid] && i2 < ri[tid])) { rv[tid] = v2; ri[tid] = i2; }
            }
            __syncthreads();
        }
        if (tid == 0) { g_idx[bh * U_ + it] = ri[0]; sv[ri[0]] = -CUDART_INF_F; }
        __syncthreads();
    }
}

// ---------------- V mean per (b,h) -----------------------------------------------
__global__ __launch_bounds__(256) void vmean_kernel()
{
    int bh = blockIdx.x;
    int b = bh >> 3, h = bh & 7;
    int tid = threadIdx.x;
    int d = tid & 63, g = tid >> 6;
    float sum = 0.f;
    for (int l = g; l < L_; l += 4)
        sum += g_V[((size_t)(b * L_ + l)) * DM_ + h * DK_ + d];
    __shared__ float red[4][64];
    red[g][d] = sum;
    __syncthreads();
    if (g == 0) {
        float t = red[0][d] + red[1][d] + red[2][d] + red[3][d];
        g_vmean[bh * 64 + d] = t * (1.0f / L_);
    }
}

// ---------------- sparse attention, split-L partials ------------------------------
__global__ __launch_bounds__(256) void attn_partial()
{
    int ch = blockIdx.x, bh = blockIdx.y;
    int b = bh >> 3, h = bh & 7;
    int tid = threadIdx.x, lane = tid & 31, w = tid >> 5;

    __shared__ float qs[U_ * DK_];
    __shared__ float Ks[64 * 68];
    __shared__ float Vs[64 * 68];

    for (int i = tid; i < U_ * DK_; i += 256) {
        int u = i >> 6, d = i & 63;
        int l = g_idx[bh * U_ + u];
        qs[i] = g_Q[((size_t)(b * L_ + l)) * DM_ + h * DK_ + d];
    }
    __syncthreads();

    const int nu = (w == 0) ? 6 : 5;
    float qx[6], qy[6], m[6], ss[6], ax[6], ay[6];
    for (int k = 0; k < nu; k++) {
        int u = w + 8 * k;
        qx[k] = qs[u * 64 + 2 * lane];
        qy[k] = qs[u * 64 + 2 * lane + 1];
        m[k] = -CUDART_INF_F; ss[k] = 0.f; ax[k] = 0.f; ay[k] = 0.f;
    }

    const int jbase0 = ch * CHUNK_;
    for (int t = 0; t < CHUNK_ / 64; t++) {
        __syncthreads();
        int jb = jbase0 + t * 64;
        const float4* Kg = (const float4*)(g_K + ((size_t)(b * L_ + jb)) * DM_ + h * DK_);
        const float4* Vg = (const float4*)(g_V + ((size_t)(b * L_ + jb)) * DM_ + h * DK_);
#pragma unroll
        for (int r = 0; r < 4; r++) {
            int idx = tid + 256 * r;
            int row = idx >> 4, cq = idx & 15;
            float4 kv = Kg[(size_t)row * (DM_ / 4) + cq];
            *(float4*)&Ks[row * 68 + cq * 4] = kv;
            float4 vv = Vg[(size_t)row * (DM_ / 4) + cq];
            *(float4*)&Vs[row * 68 + cq * 4] = vv;
        }
        __syncthreads();

        for (int k = 0; k < nu; k++) {
            float mm = m[k], s0 = ss[k], a0 = ax[k], a1 = ay[k];
            float Qx = qx[k], Qy = qy[k];
#pragma unroll 4
            for (int jj = 0; jj < 64; jj++) {
                float2 kk = *(const float2*)&Ks[jj * 68 + 2 * lane];
                float s = Qx * kk.x + Qy * kk.y;
                s += __shfl_xor_sync(0xffffffffu, s, 16);
                s += __shfl_xor_sync(0xffffffffu, s, 8);
                s += __shfl_xor_sync(0xffffffffu, s, 4);
                s += __shfl_xor_sync(0xffffffffu, s, 2);
                s += __shfl_xor_sync(0xffffffffu, s, 1);
                s *= 0.125f;
                float mn = fmaxf(mm, s);
                float ea = __expf(s - mn);
                float eb = __expf(mm - mn);
                float2 vv = *(const float2*)&Vs[jj * 68 + 2 * lane];
                s0 = s0 * eb + ea;
                a0 = a0 * eb + ea * vv.x;
                a1 = a1 * eb + ea * vv.y;
                mm = mn;
            }
            m[k] = mm; ss[k] = s0; ax[k] = a0; ay[k] = a1;
        }
    }

    for (int k = 0; k < nu; k++) {
        int u = w + 8 * k;
        size_t base = ((size_t)(bh * NCH_ + ch) * U_ + u) * 66;
        if (lane == 0) { g_part[base] = m[k]; g_part[base + 1] = ss[k]; }
        g_part[base + 2 + 2 * lane] = ax[k];
        g_part[base + 3 + 2 * lane] = ay[k];
    }
}

// ---------------- combine split-L partials ----------------------------------------
__global__ __launch_bounds__(256) void attn_combine()
{
    int gw = (blockIdx.x * blockDim.x + threadIdx.x) >> 5;
    int lane = threadIdx.x & 31;
    if (gw >= BH_ * U_) return;
    int bh = gw / U_, u = gw % U_;

    float M = -CUDART_INF_F;
#pragma unroll
    for (int ch = 0; ch < NCH_; ch++)
        M = fmaxf(M, g_part[((size_t)(bh * NCH_ + ch) * U_ + u) * 66]);
    float S = 0.f, a0 = 0.f, a1 = 0.f;
#pragma unroll
    for (int ch = 0; ch < NCH_; ch++) {
        size_t base = ((size_t)(bh * NCH_ + ch) * U_ + u) * 66;
        float f = __expf(g_part[base] - M);
        S  += g_part[base + 1] * f;
        a0 += g_part[base + 2 + 2 * lane] * f;
        a1 += g_part[base + 3 + 2 * lane] * f;
    }
    float inv = 1.0f / S;
    g_vals[(size_t)gw * 64 + 2 * lane]     = a0 * inv;
    g_vals[(size_t)gw * 64 + 2 * lane + 1] = a1 * inv;
}

// ---------------- low-rank output path ---------------------------------------------
__global__ __launch_bounds__(256) void obase_kernel(const float* __restrict__ Wfc)
{
    int b = blockIdx.x, tid = threadIdx.x;
    __shared__ float vm[512];
    vm[tid]       = g_vmean[b * 512 + tid];
    vm[tid + 256] = g_vmean[b * 512 + tid + 256];
    __syncthreads();
    float a0 = 0.f, a1 = 0.f;
    const float2* W2 = (const float2*)Wfc + tid;
#pragma unroll 8
    for (int r = 0; r < 512; r++) {
        float2 w = __ldg(W2 + (size_t)r * 256);
        float v = vm[r];
        a0 = fmaf(v, w.x, a0);
        a1 = fmaf(v, w.y, a1);
    }
    g_obase[b * 512 + 2 * tid]     = a0;
    g_obase[b * 512 + 2 * tid + 1] = a1;
}

__global__ __launch_bounds__(256) void out_assemble(const float* __restrict__ inQ,
                                                    float* __restrict__ out)
{
    int i4 = blockIdx.x * 256 + threadIdx.x;
    int b  = i4 >> 19;
    int c4 = i4 & 127;
    float4 x = ((const float4*)inQ)[i4];
    float4 o = __ldg((const float4*)g_obase + (b << 7) + c4);
    x.x += o.x; x.y += o.y; x.z += o.z; x.w += o.w;
    ((float4*)out)[i4] = x;
}

__global__ __launch_bounds__(128) void correction_kernel(float* __restrict__ out,
                                                         const float* __restrict__ Wfc)
{
    int gu = blockIdx.x;
    int bh = gu / U_;
    int b = bh >> 3, h = bh & 7;
    int l = g_idx[gu];
    int tid = threadIdx.x;

    __shared__ float delta[64];
    if (tid < 64)
        delta[tid] = g_vals[(size_t)gu * 64 + tid] - g_vmean[bh * 64 + tid];
    __syncthreads();

    float4 acc = make_float4(0.f, 0.f, 0.f, 0.f);
    const float4* W4 = (const float4*)Wfc + (size_t)(h * 64) * 128 + tid;
#pragma unroll 8
    for (int k = 0; k < 64; k++) {
        float d = delta[k];
        float4 w = __ldg(W4 + (size_t)k * 128);
        acc.x = fmaf(d, w.x, acc.x);
        acc.y = fmaf(d, w.y, acc.y);
        acc.z = fmaf(d, w.z, acc.z);
        acc.w = fmaf(d, w.w, acc.w);
    }
    float* o = out + ((size_t)(b * L_ + l)) * 512 + tid * 4;
    atomicAdd(o + 0, acc.x);
    atomicAdd(o + 1, acc.y);
    atomicAdd(o + 2, acc.z);
    atomicAdd(o + 3, acc.w);
}

// ---------------- LayerNorm -----------------------------------------------------------
__global__ __launch_bounds__(128) void ln_kernel(float* __restrict__ out,
                                                 const float* __restrict__ gamma,
                                                 const float* __restrict__ beta)
{
    int row = blockIdx.x, tid = threadIdx.x;
    float4 x = ((const float4*)out)[(size_t)row * 128 + tid];
    float s  = x.x + x.y + x.z + x.w;
    float sq = x.x * x.x + x.y * x.y + x.z * x.z + x.w * x.w;
#pragma unroll
    for (int o = 16; o > 0; o >>= 1) {
        s  += __shfl_xor_sync(0xffffffffu, s, o);
        sq += __shfl_xor_sync(0xffffffffu, sq, o);
    }
    __shared__ float sh[8];
    int w = tid >> 5, lane = tid & 31;
    if (lane == 0) { sh[w] = s; sh[4 + w] = sq; }
    __syncthreads();
    s  = sh[0] + sh[1] + sh[2] + sh[3];
    sq = sh[4] + sh[5] + sh[6] + sh[7];
    float mu  = s * (1.0f / 512.0f);
    float var = sq * (1.0f / 512.0f) - mu * mu;
    float r   = rsqrtf(var + EPS_);
    float4 gg = ((const float4*)gamma)[tid];
    float4 bb = ((const float4*)beta)[tid];
    float4 y;
    y.x = gg.x * (x.x - mu) * r + bb.x;
    y.y = gg.y * (x.y - mu) * r + bb.y;
    y.z = gg.z * (x.z - mu) * r + bb.z;
    y.w = gg.w * (x.w - mu) * r + bb.w;
    ((float4*)out)[(size_t)row * 128 + tid] = y;
}

// ---------------- launch ------------------------------------------------------------
extern "C" void kernel_launch(void* const* d_in, const int* in_sizes, int n_in,
                              void* d_out, int out_size)
{
    const float* inQ   = (const float*)d_in[0];
    const float* inK   = (const float*)d_in[1];
    const float* inV   = (const float*)d_in[2];
    const float* WQ    = (const float*)d_in[3];
    const float* WK    = (const float*)d_in[4];
    const float* WV    = (const float*)d_in[5];
    const float* Wfc   = (const float*)d_in[6];
    const float* gamma = (const float*)d_in[7];
    const float* beta  = (const float*)d_in[8];
    const int*   isamp = (const int*)d_in[9];
    float* out = (float*)d_out;

    float *Qp, *Kp, *Vp;
    cudaGetSymbolAddress((void**)&Qp, g_Q);
    cudaGetSymbolAddress((void**)&Kp, g_K);
    cudaGetSymbolAddress((void**)&Vp, g_V);

    cudaFuncSetAttribute(gemm_hmma, cudaFuncAttributeMaxDynamicSharedMemorySize,
                         GSMEM_BYTES);

    const int splitA_grid = (B_ * L_ * DM_ / 4) / 256;   // 16384
    dim3 wtGrid(16, 16);
    dim3 gGrid(DM_ / 128, (B_ * L_) / 128);               // (4, 256)

    // 1. projections: tf32 split + HMMA tf32x3 GEMM
    splitA_kernel<<<splitA_grid, 256>>>(inQ);
    splitWT_kernel<<<wtGrid, 256>>>(WQ);
    gemm_hmma<<<gGrid, 256, GSMEM_BYTES>>>(Qp);

    splitA_kernel<<<splitA_grid, 256>>>(inK);
    splitWT_kernel<<<wtGrid, 256>>>(WK);
    gemm_hmma<<<gGrid, 256, GSMEM_BYTES>>>(Kp);

    splitA_kernel<<<splitA_grid, 256>>>(inV);
    splitWT_kernel<<<wtGrid, 256>>>(WV);
    gemm_hmma<<<gGrid, 256, GSMEM_BYTES>>>(Vp);

    // 2. sparsity measure
    qkm3_kernel<<<(B_ * L_ * 32) / 256, 256>>>(isamp);

    // 3. top-k
    topk_kernel<<<BH_, 256>>>();

    // 4. V mean
    vmean_kernel<<<BH_, 256>>>();

    // 5. sparse attention + combine
    attn_partial<<<dim3(NCH_, BH_), 256>>>();
    attn_combine<<<(BH_ * U_ * 32 + 255) / 256, 256>>>();

    // 6. low-rank output
    obase_kernel<<<B_, 256>>>(Wfc);
    out_assemble<<<(B_ * L_ * DM_ / 4) / 256, 256>>>(inQ, out);
    correction_kernel<<<BH_ * U_, 128>>>(out, Wfc);

    // 7. layernorm
    ln_kernel<<<(B_ * L_), 128>>>(out, gamma, beta);
}

// round 5
// speedup vs baseline: 1.5055x; 1.0690x over previous
#include <cuda_runtime.h>
#include <math_constants.h>
#include <cstdint>

#define B_    8
#define L_    4096
#define DM_   512
#define H_    8
#define DK_   64
#define DV_   64
#define U_    41
#define BH_   (B_*H_)
#define NCH_  8
#define CHUNK_ (L_/NCH_)
#define EPS_  1e-5f

// ---------------- scratch ----------------------------------------------------
__device__ float g_Q[B_*L_*DM_];
__device__ float g_K[B_*L_*DM_];
__device__ float g_V[B_*L_*DM_];
__device__ float g_Wt[3*DM_*DM_];         // W^T fp32, [which][N][K]
__device__ float g_M[BH_*L_];
__device__ int   g_idx[BH_*U_];
__device__ float g_vals[BH_*U_*DV_];
__device__ float g_vmean[BH_*DV_];
__device__ float g_obase[B_*DM_];
__device__ float g_part[BH_*NCH_*U_*66];

// ---------------- helpers ------------------------------------------------------
__device__ __forceinline__ uint32_t smem_u32(const void* p) {
    uint32_t a;
    asm("{ .reg .u64 t; cvta.to.shared.u64 t, %1; cvt.u32.u64 %0, t; }" : "=r"(a) : "l"(p));
    return a;
}
__device__ __forceinline__ float tf32_rna(float x) {
    float r; asm("cvt.rna.tf32.f32 %0, %1;" : "=f"(r) : "f"(x)); return r;
}
#define CP_ASYNC_CG(dst, src) \
    asm volatile("cp.async.cg.shared.global [%0], [%1], 16;" :: "r"(dst), "l"(src) : "memory")
#define CP_COMMIT() asm volatile("cp.async.commit_group;" ::: "memory")
#define CP_WAIT1()  asm volatile("cp.async.wait_group 1;" ::: "memory")
#define CP_WAIT0()  asm volatile("cp.async.wait_group 0;" ::: "memory")

#define MMA_TF32(c, a, b) \
    asm volatile("mma.sync.aligned.m16n8k8.row.col.f32.tf32.tf32.f32 " \
        "{%0,%1,%2,%3}, {%4,%5,%6,%7}, {%8,%9}, {%0,%1,%2,%3};" \
        : "+f"((c)[0]), "+f"((c)[1]), "+f"((c)[2]), "+f"((c)[3]) \
        : "r"(__float_as_uint((a)[0])), "r"(__float_as_uint((a)[1])), \
          "r"(__float_as_uint((a)[2])), "r"(__float_as_uint((a)[3])), \
          "r"(__float_as_uint((b)[0])), "r"(__float_as_uint((b)[1])))

// ---------------- W transpose (fp32 only), all 3 weights ------------------------
__global__ __launch_bounds__(256) void transW_kernel(
    const float* __restrict__ W0, const float* __restrict__ W1,
    const float* __restrict__ W2)
{
    __shared__ float tile[32][33];
    const float* W = (blockIdx.z == 0) ? W0 : (blockIdx.z == 1) ? W1 : W2;
    float* dst = g_Wt + (size_t)blockIdx.z * DM_ * DM_;
    int bx = blockIdx.x * 32;         // n block
    int by = blockIdx.y * 32;         // k block
    int tx = threadIdx.x & 31, ty = threadIdx.x >> 5;
#pragma unroll
    for (int i = 0; i < 4; i++)
        tile[ty + 8 * i][tx] = __ldg(&W[(size_t)(by + ty + 8 * i) * 512 + bx + tx]);
    __syncthreads();
#pragma unroll
    for (int i = 0; i < 4; i++)
        dst[(size_t)(bx + ty + 8 * i) * 512 + by + tx] = tile[tx][ty + 8 * i];
}

// ---------------- HMMA tf32x3 GEMM, fused in-register split ---------------------
// C[128x128] tile, K=512, 16 chunks of 32. smem holds fp32 A and B tiles only.
#define PADK 36
#define MATF (128 * PADK)             // 4608 floats
#define STAGEF (2 * MATF)             // A + B
#define GSMEM_BYTES (2 * STAGEF * 4)  // 73728

__device__ __forceinline__ void g_load_stage(
    float* sm, int stage, int c, int tid,
    const float* __restrict__ A, const float* __restrict__ Bt)
{
    float* dst = sm + stage * STAGEF;
#pragma unroll
    for (int i = 0; i < 4; i++) {
        int idx = i * 256 + tid;           // 0..1023
        int row = idx >> 3, q = idx & 7;
        CP_ASYNC_CG(smem_u32(dst + row * PADK + q * 4),
                    A + (size_t)row * 512 + c * 32 + q * 4);
    }
#pragma unroll
    for (int i = 0; i < 4; i++) {
        int idx = i * 256 + tid;
        int row = idx >> 3, q = idx & 7;
        CP_ASYNC_CG(smem_u32(dst + MATF + row * PADK + q * 4),
                    Bt + (size_t)row * 512 + c * 32 + q * 4);
    }
    CP_COMMIT();
}

__global__ __launch_bounds__(256, 1) void gemm3_hmma(
    const float* __restrict__ inQ, const float* __restrict__ inK,
    const float* __restrict__ inV)
{
    extern __shared__ float sm[];
    const int tid = threadIdx.x;
    const int wid = tid >> 5, lane = tid & 31;
    const int g = lane >> 2, tg = lane & 3;
    const int wm = wid & 1, wn = wid >> 1;          // 2 x 4 warp grid
    const int row0 = blockIdx.y * 128, col0 = blockIdx.x * 128;
    const int which = blockIdx.z;

    const float* Asrc = (which == 0) ? inQ : (which == 1) ? inK : inV;
    const float* A  = Asrc + (size_t)row0 * 512;
    const float* Bt = g_Wt + (size_t)which * DM_ * DM_ + (size_t)col0 * 512;
    float* C = (which == 0) ? g_Q : (which == 1) ? g_K : g_V;

    float acc[4][4][4];
#pragma unroll
    for (int i = 0; i < 4; i++)
#pragma unroll
        for (int j = 0; j < 4; j++)
#pragma unroll
            for (int r = 0; r < 4; r++) acc[i][j][r] = 0.f;

    g_load_stage(sm, 0, 0, tid, A, Bt);

    for (int c = 0; c < 16; c++) {
        const int buf = c & 1;
        if (c < 15) g_load_stage(sm, buf ^ 1, c + 1, tid, A, Bt);
        if (c < 15) { CP_WAIT1(); } else { CP_WAIT0(); }
        __syncthreads();

        const float* sA = sm + buf * STAGEF;
        const float* sB = sA + MATF;

#pragma unroll
        for (int k8 = 0; k8 < 4; k8++) {
            const int k0 = k8 * 8;
            // load fp32 fragments, split hi/lo in registers
            float ah[4][4], al[4][4], bh[4][2], bl[4][2];
#pragma unroll
            for (int i = 0; i < 4; i++) {
                int r = wm * 64 + i * 16 + g;
                float x0 = sA[r * PADK + k0 + tg];
                float x1 = sA[(r + 8) * PADK + k0 + tg];
                float x2 = sA[r * PADK + k0 + tg + 4];
                float x3 = sA[(r + 8) * PADK + k0 + tg + 4];
                ah[i][0] = tf32_rna(x0); al[i][0] = x0 - ah[i][0];
                ah[i][1] = tf32_rna(x1); al[i][1] = x1 - ah[i][1];
                ah[i][2] = tf32_rna(x2); al[i][2] = x2 - ah[i][2];
                ah[i][3] = tf32_rna(x3); al[i][3] = x3 - ah[i][3];
            }
#pragma unroll
            for (int j = 0; j < 4; j++) {
                int n = wn * 32 + j * 8 + g;
                float y0 = sB[n * PADK + k0 + tg];
                float y1 = sB[n * PADK + k0 + tg + 4];
                bh[j][0] = tf32_rna(y0); bl[j][0] = y0 - bh[j][0];
                bh[j][1] = tf32_rna(y1); bl[j][1] = y1 - bh[j][1];
            }
            // three products; (i,j) inner so dependent MMAs are 16 apart
#pragma unroll
            for (int i = 0; i < 4; i++)
#pragma unroll
                for (int j = 0; j < 4; j++) MMA_TF32(acc[i][j], ah[i], bh[j]);
#pragma unroll
            for (int i = 0; i < 4; i++)
#pragma unroll
                for (int j = 0; j < 4; j++) MMA_TF32(acc[i][j], ah[i], bl[j]);
#pragma unroll
            for (int i = 0; i < 4; i++)
#pragma unroll
                for (int j = 0; j < 4; j++) MMA_TF32(acc[i][j], al[i], bh[j]);
        }
        __syncthreads();
    }

#pragma unroll
    for (int i = 0; i < 4; i++) {
#pragma unroll
        for (int j = 0; j < 4; j++) {
            int row = row0 + wm * 64 + i * 16 + g;
            int col = col0 + wn * 32 + j * 8 + tg * 2;
            float2 v0 = make_float2(acc[i][j][0], acc[i][j][1]);
            float2 v1 = make_float2(acc[i][j][2], acc[i][j][3]);
            *(float2*)(C + (size_t)row * 512 + col) = v0;
            *(float2*)(C + (size_t)(row + 8) * 512 + col) = v1;
        }
    }
}

// ---------------- QK_samp -> M : coalesced gathers, 16-lane-group reduce -------
__global__ __launch_bounds__(256) void qkm3_kernel(const int* __restrict__ isamp)
{
    int gw   = (blockIdx.x * 256 + threadIdx.x) >> 5;   // (b,l)
    int lane = threadIdx.x & 31;
    int l = gw & (L_ - 1);
    int b = gw >> 12;

    const float4* qb = (const float4*)(g_Q + ((size_t)(b * L_ + l)) * DM_);
    float4 q0 = qb[lane], q1 = qb[lane + 32], q2 = qb[lane + 64], q3 = qb[lane + 96];

    float smax0 = -CUDART_INF_F, smax1 = -CUDART_INF_F, smax2 = -CUDART_INF_F, smax3 = -CUDART_INF_F;
    float ssum0 = 0.f, ssum1 = 0.f, ssum2 = 0.f, ssum3 = 0.f;
    const int* ip = isamp + l * U_;

#pragma unroll 2
    for (int u = 0; u < U_; u++) {
        int j = __ldg(ip + u);
        const float4* kb = (const float4*)(g_K + ((size_t)(b * L_ + j)) * DM_);
        float4 k0 = kb[lane], k1 = kb[lane + 32], k2 = kb[lane + 64], k3 = kb[lane + 96];
        float s0 = q0.x * k0.x; s0 = fmaf(q0.y, k0.y, s0); s0 = fmaf(q0.z, k0.z, s0); s0 = fmaf(q0.w, k0.w, s0);
        float s1 = q1.x * k1.x; s1 = fmaf(q1.y, k1.y, s1); s1 = fmaf(q1.z, k1.z, s1); s1 = fmaf(q1.w, k1.w, s1);
        float s2 = q2.x * k2.x; s2 = fmaf(q2.y, k2.y, s2); s2 = fmaf(q2.z, k2.z, s2); s2 = fmaf(q2.w, k2.w, s2);
        float s3 = q3.x * k3.x; s3 = fmaf(q3.y, k3.y, s3); s3 = fmaf(q3.z, k3.z, s3); s3 = fmaf(q3.w, k3.w, s3);
#pragma unroll
        for (int m = 1; m <= 8; m <<= 1) {
            s0 += __shfl_xor_sync(0xffffffffu, s0, m);
            s1 += __shfl_xor_sync(0xffffffffu, s1, m);
            s2 += __shfl_xor_sync(0xffffffffu, s2, m);
            s3 += __shfl_xor_sync(0xffffffffu, s3, m);
        }
        smax0 = fmaxf(smax0, s0); ssum0 += s0;
        smax1 = fmaxf(smax1, s1); ssum1 += s1;
        smax2 = fmaxf(smax2, s2); ssum2 += s2;
        smax3 = fmaxf(smax3, s3); ssum3 += s3;
    }
    if ((lane & 15) == 0) {
        int g = lane >> 4;
        size_t base = ((size_t)b * 8) * L_ + l;
        g_M[base + (size_t)(g + 0) * L_] = smax0 - ssum0 * (1.0f / U_);
        g_M[base + (size_t)(g + 2) * L_] = smax1 - ssum1 * (1.0f / U_);
        g_M[base + (size_t)(g + 4) * L_] = smax2 - ssum2 * (1.0f / U_);
        g_M[base + (size_t)(g + 6) * L_] = smax3 - ssum3 * (1.0f / U_);
    }
}

// ---------------- top-k (U=41) per (b,h) ---------------------------------------
__global__ __launch_bounds__(256) void topk_kernel()
{
    int bh = blockIdx.x;
    __shared__ float sv[L_];
    __shared__ float rv[256];
    __shared__ int   ri[256];
    int tid = threadIdx.x;
    for (int i = tid; i < L_; i += 256) sv[i] = g_M[bh * L_ + i];
    __syncthreads();
    for (int it = 0; it < U_; it++) {
        float best = -CUDART_INF_F; int bi = L_;
        for (int i = tid; i < L_; i += 256) {
            float v = sv[i];
            if (v > best) { best = v; bi = i; }
        }
        rv[tid] = best; ri[tid] = bi;
        __syncthreads();
        for (int s = 128; s > 0; s >>= 1) {
            if (tid < s) {
                float v2 = rv[tid + s]; int i2 = ri[tid + s];
                if (v2 > rv[tid] || (v2 == rv[tid] && i2 < ri[tid])) { rv[tid] = v2; ri[tid] = i2; }
            }
            __syncthreads();
        }
        if (tid == 0) { g_idx[bh * U_ + it] = ri[0]; sv[ri[0]] = -CUDART_INF_F; }
        __syncthreads();
    }
}

// ---------------- V mean per (b,h) -----------------------------------------------
__global__ __launch_bounds__(256) void vmean_kernel()
{
    int bh = blockIdx.x;
    int b = bh >> 3, h = bh & 7;
    int tid = threadIdx.x;
    int d = tid & 63, g = tid >> 6;
    float sum = 0.f;
    for (int l = g; l < L_; l += 4)
        sum += g_V[((size_t)(b * L_ + l)) * DM_ + h * DK_ + d];
    __shared__ float red[4][64];
    red[g][d] = sum;
    __syncthreads();
    if (g == 0) {
        float t = red[0][d] + red[1][d] + red[2][d] + red[3][d];
        g_vmean[bh * 64 + d] = t * (1.0f / L_);
    }
}

// ---------------- sparse attention, split-L partials ------------------------------
__global__ __launch_bounds__(256) void attn_partial()
{
    int ch = blockIdx.x, bh = blockIdx.y;
    int b = bh >> 3, h = bh & 7;
    int tid = threadIdx.x, lane = tid & 31, w = tid >> 5;

    __shared__ float qs[U_ * DK_];
    __shared__ float Ks[64 * 68];
    __shared__ float Vs[64 * 68];

    for (int i = tid; i < U_ * DK_; i += 256) {
        int u = i >> 6, d = i & 63;
        int l = g_idx[bh * U_ + u];
        qs[i] = g_Q[((size_t)(b * L_ + l)) * DM_ + h * DK_ + d];
    }
    __syncthreads();

    const int nu = (w == 0) ? 6 : 5;
    float qx[6], qy[6], m[6], ss[6], ax[6], ay[6];
    for (int k = 0; k < nu; k++) {
        int u = w + 8 * k;
        qx[k] = qs[u * 64 + 2 * lane];
        qy[k] = qs[u * 64 + 2 * lane + 1];
        m[k] = -CUDART_INF_F; ss[k] = 0.f; ax[k] = 0.f; ay[k] = 0.f;
    }

    const int jbase0 = ch * CHUNK_;
    for (int t = 0; t < CHUNK_ / 64; t++) {
        __syncthreads();
        int jb = jbase0 + t * 64;
        const float4* Kg = (const float4*)(g_K + ((size_t)(b * L_ + jb)) * DM_ + h * DK_);
        const float4* Vg = (const float4*)(g_V + ((size_t)(b * L_ + jb)) * DM_ + h * DK_);
#pragma unroll
        for (int r = 0; r < 4; r++) {
            int idx = tid + 256 * r;
            int row = idx >> 4, cq = idx & 15;
            float4 kv = Kg[(size_t)row * (DM_ / 4) + cq];
            *(float4*)&Ks[row * 68 + cq * 4] = kv;
            float4 vv = Vg[(size_t)row * (DM_ / 4) + cq];
            *(float4*)&Vs[row * 68 + cq * 4] = vv;
        }
        __syncthreads();

        for (int k = 0; k < nu; k++) {
            float mm = m[k], s0 = ss[k], a0 = ax[k], a1 = ay[k];
            float Qx = qx[k], Qy = qy[k];
#pragma unroll 4
            for (int jj = 0; jj < 64; jj++) {
                float2 kk = *(const float2*)&Ks[jj * 68 + 2 * lane];
                float s = Qx * kk.x + Qy * kk.y;
                s += __shfl_xor_sync(0xffffffffu, s, 16);
                s += __shfl_xor_sync(0xffffffffu, s, 8);
                s += __shfl_xor_sync(0xffffffffu, s, 4);
                s += __shfl_xor_sync(0xffffffffu, s, 2);
                s += __shfl_xor_sync(0xffffffffu, s, 1);
                s *= 0.125f;
                float mn = fmaxf(mm, s);
                float ea = __expf(s - mn);
                float eb = __expf(mm - mn);
                float2 vv = *(const float2*)&Vs[jj * 68 + 2 * lane];
                s0 = s0 * eb + ea;
                a0 = a0 * eb + ea * vv.x;
                a1 = a1 * eb + ea * vv.y;
                mm = mn;
            }
            m[k] = mm; ss[k] = s0; ax[k] = a0; ay[k] = a1;
        }
    }

    for (int k = 0; k < nu; k++) {
        int u = w + 8 * k;
        size_t base = ((size_t)(bh * NCH_ + ch) * U_ + u) * 66;
        if (lane == 0) { g_part[base] = m[k]; g_part[base + 1] = ss[k]; }
        g_part[base + 2 + 2 * lane] = ax[k];
        g_part[base + 3 + 2 * lane] = ay[k];
    }
}

// ---------------- combine split-L partials ----------------------------------------
__global__ __launch_bounds__(256) void attn_combine()
{
    int gw = (blockIdx.x * blockDim.x + threadIdx.x) >> 5;
    int lane = threadIdx.x & 31;
    if (gw >= BH_ * U_) return;
    int bh = gw / U_, u = gw % U_;

    float M = -CUDART_INF_F;
#pragma unroll
    for (int ch = 0; ch < NCH_; ch++)
        M = fmaxf(M, g_part[((size_t)(bh * NCH_ + ch) * U_ + u) * 66]);
    float S = 0.f, a0 = 0.f, a1 = 0.f;
#pragma unroll
    for (int ch = 0; ch < NCH_; ch++) {
        size_t base = ((size_t)(bh * NCH_ + ch) * U_ + u) * 66;
        float f = __expf(g_part[base] - M);
        S  += g_part[base + 1] * f;
        a0 += g_part[base + 2 + 2 * lane] * f;
        a1 += g_part[base + 3 + 2 * lane] * f;
    }
    float inv = 1.0f / S;
    g_vals[(size_t)gw * 64 + 2 * lane]     = a0 * inv;
    g_vals[(size_t)gw * 64 + 2 * lane + 1] = a1 * inv;
}

// ---------------- low-rank output path ---------------------------------------------
__global__ __launch_bounds__(256) void obase_kernel(const float* __restrict__ Wfc)
{
    int b = blockIdx.x, tid = threadIdx.x;
    __shared__ float vm[512];
    vm[tid]       = g_vmean[b * 512 + tid];
    vm[tid + 256] = g_vmean[b * 512 + tid + 256];
    __syncthreads();
    float a0 = 0.f, a1 = 0.f;
    const float2* W2 = (const float2*)Wfc + tid;
#pragma unroll 8
    for (int r = 0; r < 512; r++) {
        float2 w = __ldg(W2 + (size_t)r * 256);
        float v = vm[r];
        a0 = fmaf(v, w.x, a0);
        a1 = fmaf(v, w.y, a1);
    }
    g_obase[b * 512 + 2 * tid]     = a0;
    g_obase[b * 512 + 2 * tid + 1] = a1;
}

__global__ __launch_bounds__(256) void out_assemble(const float* __restrict__ inQ,
                                                    float* __restrict__ out)
{
    int i4 = blockIdx.x * 256 + threadIdx.x;
    int b  = i4 >> 19;
    int c4 = i4 & 127;
    float4 x = ((const float4*)inQ)[i4];
    float4 o = __ldg((const float4*)g_obase + (b << 7) + c4);
    x.x += o.x; x.y += o.y; x.z += o.z; x.w += o.w;
    ((float4*)out)[i4] = x;
}

__global__ __launch_bounds__(128) void correction_kernel(float* __restrict__ out,
                                                         const float* __restrict__ Wfc)
{
    int gu = blockIdx.x;
    int bh = gu / U_;
    int b = bh >> 3, h = bh & 7;
    int l = g_idx[gu];
    int tid = threadIdx.x;

    __shared__ float delta[64];
    if (tid < 64)
        delta[tid] = g_vals[(size_t)gu * 64 + tid] - g_vmean[bh * 64 + tid];
    __syncthreads();

    float4 acc = make_float4(0.f, 0.f, 0.f, 0.f);
    const float4* W4 = (const float4*)Wfc + (size_t)(h * 64) * 128 + tid;
#pragma unroll 8
    for (int k = 0; k < 64; k++) {
        float d = delta[k];
        float4 w = __ldg(W4 + (size_t)k * 128);
        acc.x = fmaf(d, w.x, acc.x);
        acc.y = fmaf(d, w.y, acc.y);
        acc.z = fmaf(d, w.z, acc.z);
        acc.w = fmaf(d, w.w, acc.w);
    }
    float* o = out + ((size_t)(b * L_ + l)) * 512 + tid * 4;
    atomicAdd(o + 0, acc.x);
    atomicAdd(o + 1, acc.y);
    atomicAdd(o + 2, acc.z);
    atomicAdd(o + 3, acc.w);
}

// ---------------- LayerNorm -----------------------------------------------------------
__global__ __launch_bounds__(128) void ln_kernel(float* __restrict__ out,
                                                 const float* __restrict__ gamma,
                                                 const float* __restrict__ beta)
{
    int row = blockIdx.x, tid = threadIdx.x;
    float4 x = ((const float4*)out)[(size_t)row * 128 + tid];
    float s  = x.x + x.y + x.z + x.w;
    float sq = x.x * x.x + x.y * x.y + x.z * x.z + x.w * x.w;
#pragma unroll
    for (int o = 16; o > 0; o >>= 1) {
        s  += __shfl_xor_sync(0xffffffffu, s, o);
        sq += __shfl_xor_sync(0xffffffffu, sq, o);
    }
    __shared__ float sh[8];
    int w = tid >> 5, lane = tid & 31;
    if (lane == 0) { sh[w] = s; sh[4 + w] = sq; }
    __syncthreads();
    s  = sh[0] + sh[1] + sh[2] + sh[3];
    sq = sh[4] + sh[5] + sh[6] + sh[7];
    float mu  = s * (1.0f / 512.0f);
    float var = sq * (1.0f / 512.0f) - mu * mu;
    float r   = rsqrtf(var + EPS_);
    float4 gg = ((const float4*)gamma)[tid];
    float4 bb = ((const float4*)beta)[tid];
    float4 y;
    y.x = gg.x * (x.x - mu) * r + bb.x;
    y.y = gg.y * (x.y - mu) * r + bb.y;
    y.z = gg.z * (x.z - mu) * r + bb.z;
    y.w = gg.w * (x.w - mu) * r + bb.w;
    ((float4*)out)[(size_t)row * 128 + tid] = y;
}

// ---------------- launch ------------------------------------------------------------
extern "C" void kernel_launch(void* const* d_in, const int* in_sizes, int n_in,
                              void* d_out, int out_size)
{
    const float* inQ   = (const float*)d_in[0];
    const float* inK   = (const float*)d_in[1];
    const float* inV   = (const float*)d_in[2];
    const float* WQ    = (const float*)d_in[3];
    const float* WK    = (const float*)d_in[4];
    const float* WV    = (const float*)d_in[5];
    const float* Wfc   = (const float*)d_in[6];
    const float* gamma = (const float*)d_in[7];
    const float* beta  = (const float*)d_in[8];
    const int*   isamp = (const int*)d_in[9];
    float* out = (float*)d_out;

    cudaFuncSetAttribute(gemm3_hmma, cudaFuncAttributeMaxDynamicSharedMemorySize,
                         GSMEM_BYTES);

    // 1. projections: transpose weights, then fused tf32x3 HMMA GEMM (split in regs)
    transW_kernel<<<dim3(16, 16, 3), 256>>>(WQ, WK, WV);
    gemm3_hmma<<<dim3(DM_ / 128, (B_ * L_) / 128, 3), 256, GSMEM_BYTES>>>(inQ, inK, inV);

    // 2. sparsity measure
    qkm3_kernel<<<(B_ * L_ * 32) / 256, 256>>>(isamp);

    // 3. top-k
    topk_kernel<<<BH_, 256>>>();

    // 4. V mean
    vmean_kernel<<<BH_, 256>>>();

    // 5. sparse attention + combine
    attn_partial<<<dim3(NCH_, BH_), 256>>>();
    attn_combine<<<(BH_ * U_ * 32 + 255) / 256, 256>>>();

    // 6. low-rank output
    obase_kernel<<<B_, 256>>>(Wfc);
    out_assemble<<<(B_ * L_ * DM_ / 4) / 256, 256>>>(inQ, out);
    correction_kernel<<<BH_ * U_, 128>>>(out, Wfc);

    // 7. layernorm
    ln_kernel<<<(B_ * L_), 128>>>(out, gamma, beta);
}

// round 6
// speedup vs baseline: 1.6753x; 1.1127x over previous
#include <cuda_runtime.h>
#include <math_constants.h>
#include <cstdint>

#define B_    8
#define L_    4096
#define DM_   512
#define H_    8
#define DK_   64
#define DV_   64
#define U_    41
#define BH_   (B_*H_)
#define NCH_  8
#define CHUNK_ (L_/NCH_)
#define EPS_  1e-5f

// ---------------- scratch ----------------------------------------------------
__device__ float g_Q[B_*L_*DM_];
__device__ float g_K[B_*L_*DM_];
__device__ float g_V[B_*L_*DM_];
__device__ float g_Wt[3*DM_*DM_];         // W^T fp32, [which][N][K]
__device__ float g_M[BH_*L_];
__device__ int   g_idx[BH_*U_];
__device__ float g_vals[BH_*U_*DV_];
__device__ float g_vmean[BH_*DV_];
__device__ float g_obase[B_*DM_];
__device__ float g_part[BH_*NCH_*U_*66];

// ---------------- helpers ------------------------------------------------------
__device__ __forceinline__ uint32_t smem_u32(const void* p) {
    uint32_t a;
    asm("{ .reg .u64 t; cvta.to.shared.u64 t, %1; cvt.u32.u64 %0, t; }" : "=r"(a) : "l"(p));
    return a;
}
__device__ __forceinline__ float tf32_rna(float x) {
    float r; asm("cvt.rna.tf32.f32 %0, %1;" : "=f"(r) : "f"(x)); return r;
}
#define CP_ASYNC_CG(dst, src) \
    asm volatile("cp.async.cg.shared.global [%0], [%1], 16;" :: "r"(dst), "l"(src) : "memory")
#define CP_COMMIT() asm volatile("cp.async.commit_group;" ::: "memory")
#define CP_WAIT1()  asm volatile("cp.async.wait_group 1;" ::: "memory")
#define CP_WAIT0()  asm volatile("cp.async.wait_group 0;" ::: "memory")

#define MMA_TF32(c, a, b) \
    asm volatile("mma.sync.aligned.m16n8k8.row.col.f32.tf32.tf32.f32 " \
        "{%0,%1,%2,%3}, {%4,%5,%6,%7}, {%8,%9}, {%0,%1,%2,%3};" \
        : "+f"((c)[0]), "+f"((c)[1]), "+f"((c)[2]), "+f"((c)[3]) \
        : "r"(__float_as_uint((a)[0])), "r"(__float_as_uint((a)[1])), \
          "r"(__float_as_uint((a)[2])), "r"(__float_as_uint((a)[3])), \
          "r"(__float_as_uint((b)[0])), "r"(__float_as_uint((b)[1])))

// ---------------- W transpose (fp32 only), all 3 weights ------------------------
__global__ __launch_bounds__(256) void transW_kernel(
    const float* __restrict__ W0, const float* __restrict__ W1,
    const float* __restrict__ W2)
{
    __shared__ float tile[32][33];
    const float* W = (blockIdx.z == 0) ? W0 : (blockIdx.z == 1) ? W1 : W2;
    float* dst = g_Wt + (size_t)blockIdx.z * DM_ * DM_;
    int bx = blockIdx.x * 32;
    int by = blockIdx.y * 32;
    int tx = threadIdx.x & 31, ty = threadIdx.x >> 5;
#pragma unroll
    for (int i = 0; i < 4; i++)
        tile[ty + 8 * i][tx] = __ldg(&W[(size_t)(by + ty + 8 * i) * 512 + bx + tx]);
    __syncthreads();
#pragma unroll
    for (int i = 0; i < 4; i++)
        dst[(size_t)(bx + ty + 8 * i) * 512 + by + tx] = tile[tx][ty + 8 * i];
}

// ---------------- HMMA tf32 GEMM, fused in-register split -----------------------
// z=0 (Q), z=1 (K): tf32x3 (fp32-accurate; protects top-k selection).
// z=2 (V): single tf32 product (error ~1e-4, benign downstream).
#define PADK 36
#define MATF (128 * PADK)
#define STAGEF (2 * MATF)
#define GSMEM_BYTES (2 * STAGEF * 4)  // 73728

__device__ __forceinline__ void g_load_stage(
    float* sm, int stage, int c, int tid,
    const float* __restrict__ A, const float* __restrict__ Bt)
{
    float* dst = sm + stage * STAGEF;
#pragma unroll
    for (int i = 0; i < 4; i++) {
        int idx = i * 256 + tid;
        int row = idx >> 3, q = idx & 7;
        CP_ASYNC_CG(smem_u32(dst + row * PADK + q * 4),
                    A + (size_t)row * 512 + c * 32 + q * 4);
    }
#pragma unroll
    for (int i = 0; i < 4; i++) {
        int idx = i * 256 + tid;
        int row = idx >> 3, q = idx & 7;
        CP_ASYNC_CG(smem_u32(dst + MATF + row * PADK + q * 4),
                    Bt + (size_t)row * 512 + c * 32 + q * 4);
    }
    CP_COMMIT();
}

__global__ __launch_bounds__(256, 1) void gemm3_hmma(
    const float* __restrict__ inQ, const float* __restrict__ inK,
    const float* __restrict__ inV)
{
    extern __shared__ float sm[];
    const int tid = threadIdx.x;
    const int wid = tid >> 5, lane = tid & 31;
    const int g = lane >> 2, tg = lane & 3;
    const int wm = wid & 1, wn = wid >> 1;
    const int row0 = blockIdx.y * 128, col0 = blockIdx.x * 128;
    const int which = blockIdx.z;
    const bool full = (which != 2);          // Q,K accurate; V single-product

    const float* Asrc = (which == 0) ? inQ : (which == 1) ? inK : inV;
    const float* A  = Asrc + (size_t)row0 * 512;
    const float* Bt = g_Wt + (size_t)which * DM_ * DM_ + (size_t)col0 * 512;
    float* C = (which == 0) ? g_Q : (which == 1) ? g_K : g_V;

    float acc[4][4][4];
#pragma unroll
    for (int i = 0; i < 4; i++)
#pragma unroll
        for (int j = 0; j < 4; j++)
#pragma unroll
            for (int r = 0; r < 4; r++) acc[i][j][r] = 0.f;

    g_load_stage(sm, 0, 0, tid, A, Bt);

    for (int c = 0; c < 16; c++) {
        const int buf = c & 1;
        if (c < 15) g_load_stage(sm, buf ^ 1, c + 1, tid, A, Bt);
        if (c < 15) { CP_WAIT1(); } else { CP_WAIT0(); }
        __syncthreads();

        const float* sA = sm + buf * STAGEF;
        const float* sB = sA + MATF;

#pragma unroll
        for (int k8 = 0; k8 < 4; k8++) {
            const int k0 = k8 * 8;
            float ah[4][4], al[4][4], bh[4][2], bl[4][2];
#pragma unroll
            for (int i = 0; i < 4; i++) {
                int r = wm * 64 + i * 16 + g;
                float x0 = sA[r * PADK + k0 + tg];
                float x1 = sA[(r + 8) * PADK + k0 + tg];
                float x2 = sA[r * PADK + k0 + tg + 4];
                float x3 = sA[(r + 8) * PADK + k0 + tg + 4];
                ah[i][0] = tf32_rna(x0); ah[i][1] = tf32_rna(x1);
                ah[i][2] = tf32_rna(x2); ah[i][3] = tf32_rna(x3);
                if (full) {
                    al[i][0] = x0 - ah[i][0]; al[i][1] = x1 - ah[i][1];
                    al[i][2] = x2 - ah[i][2]; al[i][3] = x3 - ah[i][3];
                }
            }
#pragma unroll
            for (int j = 0; j < 4; j++) {
                int n = wn * 32 + j * 8 + g;
                float y0 = sB[n * PADK + k0 + tg];
                float y1 = sB[n * PADK + k0 + tg + 4];
                bh[j][0] = tf32_rna(y0); bh[j][1] = tf32_rna(y1);
                if (full) {
                    bl[j][0] = y0 - bh[j][0];
                    bl[j][1] = y1 - bh[j][1];
                }
            }
#pragma unroll
            for (int i = 0; i < 4; i++)
#pragma unroll
                for (int j = 0; j < 4; j++) MMA_TF32(acc[i][j], ah[i], bh[j]);
            if (full) {
#pragma unroll
                for (int i = 0; i < 4; i++)
#pragma unroll
                    for (int j = 0; j < 4; j++) MMA_TF32(acc[i][j], ah[i], bl[j]);
#pragma unroll
                for (int i = 0; i < 4; i++)
#pragma unroll
                    for (int j = 0; j < 4; j++) MMA_TF32(acc[i][j], al[i], bh[j]);
            }
        }
        __syncthreads();
    }

#pragma unroll
    for (int i = 0; i < 4; i++) {
#pragma unroll
        for (int j = 0; j < 4; j++) {
            int row = row0 + wm * 64 + i * 16 + g;
            int col = col0 + wn * 32 + j * 8 + tg * 2;
            float2 v0 = make_float2(acc[i][j][0], acc[i][j][1]);
            float2 v1 = make_float2(acc[i][j][2], acc[i][j][3]);
            *(float2*)(C + (size_t)row * 512 + col) = v0;
            *(float2*)(C + (size_t)(row + 8) * 512 + col) = v1;
        }
    }
}

// ---------------- QK_samp -> M : coalesced gathers, 16-lane-group reduce -------
__global__ __launch_bounds__(256) void qkm3_kernel(const int* __restrict__ isamp)
{
    int gw   = (blockIdx.x * 256 + threadIdx.x) >> 5;
    int lane = threadIdx.x & 31;
    int l = gw & (L_ - 1);
    int b = gw >> 12;

    const float4* qb = (const float4*)(g_Q + ((size_t)(b * L_ + l)) * DM_);
    float4 q0 = qb[lane], q1 = qb[lane + 32], q2 = qb[lane + 64], q3 = qb[lane + 96];

    float smax0 = -CUDART_INF_F, smax1 = -CUDART_INF_F, smax2 = -CUDART_INF_F, smax3 = -CUDART_INF_F;
    float ssum0 = 0.f, ssum1 = 0.f, ssum2 = 0.f, ssum3 = 0.f;
    const int* ip = isamp + l * U_;

#pragma unroll 2
    for (int u = 0; u < U_; u++) {
        int j = __ldg(ip + u);
        const float4* kb = (const float4*)(g_K + ((size_t)(b * L_ + j)) * DM_);
        float4 k0 = kb[lane], k1 = kb[lane + 32], k2 = kb[lane + 64], k3 = kb[lane + 96];
        float s0 = q0.x * k0.x; s0 = fmaf(q0.y, k0.y, s0); s0 = fmaf(q0.z, k0.z, s0); s0 = fmaf(q0.w, k0.w, s0);
        float s1 = q1.x * k1.x; s1 = fmaf(q1.y, k1.y, s1); s1 = fmaf(q1.z, k1.z, s1); s1 = fmaf(q1.w, k1.w, s1);
        float s2 = q2.x * k2.x; s2 = fmaf(q2.y, k2.y, s2); s2 = fmaf(q2.z, k2.z, s2); s2 = fmaf(q2.w, k2.w, s2);
        float s3 = q3.x * k3.x; s3 = fmaf(q3.y, k3.y, s3); s3 = fmaf(q3.z, k3.z, s3); s3 = fmaf(q3.w, k3.w, s3);
#pragma unroll
        for (int m = 1; m <= 8; m <<= 1) {
            s0 += __shfl_xor_sync(0xffffffffu, s0, m);
            s1 += __shfl_xor_sync(0xffffffffu, s1, m);
            s2 += __shfl_xor_sync(0xffffffffu, s2, m);
            s3 += __shfl_xor_sync(0xffffffffu, s3, m);
        }
        smax0 = fmaxf(smax0, s0); ssum0 += s0;
        smax1 = fmaxf(smax1, s1); ssum1 += s1;
        smax2 = fmaxf(smax2, s2); ssum2 += s2;
        smax3 = fmaxf(smax3, s3); ssum3 += s3;
    }
    if ((lane & 15) == 0) {
        int g = lane >> 4;
        size_t base = ((size_t)b * 8) * L_ + l;
        g_M[base + (size_t)(g + 0) * L_] = smax0 - ssum0 * (1.0f / U_);
        g_M[base + (size_t)(g + 2) * L_] = smax1 - ssum1 * (1.0f / U_);
        g_M[base + (size_t)(g + 4) * L_] = smax2 - ssum2 * (1.0f / U_);
        g_M[base + (size_t)(g + 6) * L_] = smax3 - ssum3 * (1.0f / U_);
    }
}

// ---------------- top-k (U=41) per (b,h) ---------------------------------------
__global__ __launch_bounds__(256) void topk_kernel()
{
    int bh = blockIdx.x;
    __shared__ float sv[L_];
    __shared__ float rv[256];
    __shared__ int   ri[256];
    int tid = threadIdx.x;
    for (int i = tid; i < L_; i += 256) sv[i] = g_M[bh * L_ + i];
    __syncthreads();
    for (int it = 0; it < U_; it++) {
        float best = -CUDART_INF_F; int bi = L_;
        for (int i = tid; i < L_; i += 256) {
            float v = sv[i];
            if (v > best) { best = v; bi = i; }
        }
        rv[tid] = best; ri[tid] = bi;
        __syncthreads();
        for (int s = 128; s > 0; s >>= 1) {
            if (tid < s) {
                float v2 = rv[tid + s]; int i2 = ri[tid + s];
                if (v2 > rv[tid] || (v2 == rv[tid] && i2 < ri[tid])) { rv[tid] = v2; ri[tid] = i2; }
            }
            __syncthreads();
        }
        if (tid == 0) { g_idx[bh * U_ + it] = ri[0]; sv[ri[0]] = -CUDART_INF_F; }
        __syncthreads();
    }
}

// ---------------- V mean per (b,h) -----------------------------------------------
__global__ __launch_bounds__(256) void vmean_kernel()
{
    int bh = blockIdx.x;
    int b = bh >> 3, h = bh & 7;
    int tid = threadIdx.x;
    int d = tid & 63, g = tid >> 6;
    float sum = 0.f;
    for (int l = g; l < L_; l += 4)
        sum += g_V[((size_t)(b * L_ + l)) * DM_ + h * DK_ + d];
    __shared__ float red[4][64];
    red[g][d] = sum;
    __syncthreads();
    if (g == 0) {
        float t = red[0][d] + red[1][d] + red[2][d] + red[3][d];
        g_vmean[bh * 64 + d] = t * (1.0f / L_);
    }
}

// ---------------- sparse attention, split-L partials ------------------------------
// jj-outer / u-inner: 6 independent SHFL reduction trees in flight per key.
__global__ __launch_bounds__(256) void attn_partial()
{
    int ch = blockIdx.x, bh = blockIdx.y;
    int b = bh >> 3, h = bh & 7;
    int tid = threadIdx.x, lane = tid & 31, w = tid >> 5;

    __shared__ float qs[U_ * DK_];
    __shared__ float Ks[64 * 68];
    __shared__ float Vs[64 * 68];

    for (int i = tid; i < U_ * DK_; i += 256) {
        int u = i >> 6, d = i & 63;
        int l = g_idx[bh * U_ + u];
        qs[i] = g_Q[((size_t)(b * L_ + l)) * DM_ + h * DK_ + d];
    }
    __syncthreads();

    const int nu = (w == 0) ? 6 : 5;
    float qx[6], qy[6], m[6], ss[6], ax[6], ay[6];
#pragma unroll
    for (int k = 0; k < 6; k++) {
        if (k < nu) {
            int u = w + 8 * k;
            qx[k] = qs[u * 64 + 2 * lane];
            qy[k] = qs[u * 64 + 2 * lane + 1];
        } else {
            qx[k] = 0.f; qy[k] = 0.f;            // dead slot: harmless math
        }
        m[k] = -CUDART_INF_F; ss[k] = 0.f; ax[k] = 0.f; ay[k] = 0.f;
    }

    const int jbase0 = ch * CHUNK_;
    for (int t = 0; t < CHUNK_ / 64; t++) {
        __syncthreads();
        int jb = jbase0 + t * 64;
        const float4* Kg = (const float4*)(g_K + ((size_t)(b * L_ + jb)) * DM_ + h * DK_);
        const float4* Vg = (const float4*)(g_V + ((size_t)(b * L_ + jb)) * DM_ + h * DK_);
#pragma unroll
        for (int r = 0; r < 4; r++) {
            int idx = tid + 256 * r;
            int row = idx >> 4, cq = idx & 15;
            float4 kv = Kg[(size_t)row * (DM_ / 4) + cq];
            *(float4*)&Ks[row * 68 + cq * 4] = kv;
            float4 vv = Vg[(size_t)row * (DM_ / 4) + cq];
            *(float4*)&Vs[row * 68 + cq * 4] = vv;
        }
        __syncthreads();

#pragma unroll 2
        for (int jj = 0; jj < 64; jj++) {
            float2 kk = *(const float2*)&Ks[jj * 68 + 2 * lane];
            float2 vv = *(const float2*)&Vs[jj * 68 + 2 * lane];
            float sc[6];
#pragma unroll
            for (int k = 0; k < 6; k++)
                sc[k] = fmaf(qy[k], kk.y, qx[k] * kk.x);
#pragma unroll
            for (int o = 16; o > 0; o >>= 1) {
#pragma unroll
                for (int k = 0; k < 6; k++)
                    sc[k] += __shfl_xor_sync(0xffffffffu, sc[k], o);
            }
#pragma unroll
            for (int k = 0; k < 6; k++) {
                float s = sc[k] * 0.125f;
                float mn = fmaxf(m[k], s);
                float ea = __expf(s - mn);
                float eb = __expf(m[k] - mn);
                ss[k] = ss[k] * eb + ea;
                ax[k] = ax[k] * eb + ea * vv.x;
                ay[k] = ay[k] * eb + ea * vv.y;
                m[k] = mn;
            }
        }
    }

#pragma unroll
    for (int k = 0; k < 6; k++) {
        if (k < nu) {
            int u = w + 8 * k;
            size_t base = ((size_t)(bh * NCH_ + ch) * U_ + u) * 66;
            if (lane == 0) { g_part[base] = m[k]; g_part[base + 1] = ss[k]; }
            g_part[base + 2 + 2 * lane] = ax[k];
            g_part[base + 3 + 2 * lane] = ay[k];
        }
    }
}

// ---------------- combine split-L partials ----------------------------------------
__global__ __launch_bounds__(256) void attn_combine()
{
    int gw = (blockIdx.x * blockDim.x + threadIdx.x) >> 5;
    int lane = threadIdx.x & 31;
    if (gw >= BH_ * U_) return;
    int bh = gw / U_, u = gw % U_;

    float M = -CUDART_INF_F;
#pragma unroll
    for (int ch = 0; ch < NCH_; ch++)
        M = fmaxf(M, g_part[((size_t)(bh * NCH_ + ch) * U_ + u) * 66]);
    float S = 0.f, a0 = 0.f, a1 = 0.f;
#pragma unroll
    for (int ch = 0; ch < NCH_; ch++) {
        size_t base = ((size_t)(bh * NCH_ + ch) * U_ + u) * 66;
        float f = __expf(g_part[base] - M);
        S  += g_part[base + 1] * f;
        a0 += g_part[base + 2 + 2 * lane] * f;
        a1 += g_part[base + 3 + 2 * lane] * f;
    }
    float inv = 1.0f / S;
    g_vals[(size_t)gw * 64 + 2 * lane]     = a0 * inv;
    g_vals[(size_t)gw * 64 + 2 * lane + 1] = a1 * inv;
}

// ---------------- low-rank output path ---------------------------------------------
__global__ __launch_bounds__(256) void obase_kernel(const float* __restrict__ Wfc)
{
    int b = blockIdx.x, tid = threadIdx.x;
    __shared__ float vm[512];
    vm[tid]       = g_vmean[b * 512 + tid];
    vm[tid + 256] = g_vmean[b * 512 + tid + 256];
    __syncthreads();
    float a0 = 0.f, a1 = 0.f;
    const float2* W2 = (const float2*)Wfc + tid;
#pragma unroll 8
    for (int r = 0; r < 512; r++) {
        float2 w = __ldg(W2 + (size_t)r * 256);
        float v = vm[r];
        a0 = fmaf(v, w.x, a0);
        a1 = fmaf(v, w.y, a1);
    }
    g_obase[b * 512 + 2 * tid]     = a0;
    g_obase[b * 512 + 2 * tid + 1] = a1;
}

__global__ __launch_bounds__(256) void out_assemble(const float* __restrict__ inQ,
                                                    float* __restrict__ out)
{
    int i4 = blockIdx.x * 256 + threadIdx.x;
    int b  = i4 >> 19;
    int c4 = i4 & 127;
    float4 x = ((const float4*)inQ)[i4];
    float4 o = __ldg((const float4*)g_obase + (b << 7) + c4);
    x.x += o.x; x.y += o.y; x.z += o.z; x.w += o.w;
    ((float4*)out)[i4] = x;
}

__global__ __launch_bounds__(128) void correction_kernel(float* __restrict__ out,
                                                         const float* __restrict__ Wfc)
{
    int gu = blockIdx.x;
    int bh = gu / U_;
    int b = bh >> 3, h = bh & 7;
    int l = g_idx[gu];
    int tid = threadIdx.x;

    __shared__ float delta[64];
    if (tid < 64)
        delta[tid] = g_vals[(size_t)gu * 64 + tid] - g_vmean[bh * 64 + tid];
    __syncthreads();

    float4 acc = make_float4(0.f, 0.f, 0.f, 0.f);
    const float4* W4 = (const float4*)Wfc + (size_t)(h * 64) * 128 + tid;
#pragma unroll 8
    for (int k = 0; k < 64; k++) {
        float d = delta[k];
        float4 w = __ldg(W4 + (size_t)k * 128);
        acc.x = fmaf(d, w.x, acc.x);
        acc.y = fmaf(d, w.y, acc.y);
        acc.z = fmaf(d, w.z, acc.z);
        acc.w = fmaf(d, w.w, acc.w);
    }
    float* o = out + ((size_t)(b * L_ + l)) * 512 + tid * 4;
    atomicAdd(o + 0, acc.x);
    atomicAdd(o + 1, acc.y);
    atomicAdd(o + 2, acc.z);
    atomicAdd(o + 3, acc.w);
}

// ---------------- LayerNorm -----------------------------------------------------------
__global__ __launch_bounds__(128) void ln_kernel(float* __restrict__ out,
                                                 const float* __restrict__ gamma,
                                                 const float* __restrict__ beta)
{
    int row = blockIdx.x, tid = threadIdx.x;
    float4 x = ((const float4*)out)[(size_t)row * 128 + tid];
    float s  = x.x + x.y + x.z + x.w;
    float sq = x.x * x.x + x.y * x.y + x.z * x.z + x.w * x.w;
#pragma unroll
    for (int o = 16; o > 0; o >>= 1) {
        s  += __shfl_xor_sync(0xffffffffu, s, o);
        sq += __shfl_xor_sync(0xffffffffu, sq, o);
    }
    __shared__ float sh[8];
    int w = tid >> 5, lane = tid & 31;
    if (lane == 0) { sh[w] = s; sh[4 + w] = sq; }
    __syncthreads();
    s  = sh[0] + sh[1] + sh[2] + sh[3];
    sq = sh[4] + sh[5] + sh[6] + sh[7];
    float mu  = s * (1.0f / 512.0f);
    float var = sq * (1.0f / 512.0f) - mu * mu;
    float r   = rsqrtf(var + EPS_);
    float4 gg = ((const float4*)gamma)[tid];
    float4 bb = ((const float4*)beta)[tid];
    float4 y;
    y.x = gg.x * (x.x - mu) * r + bb.x;
    y.y = gg.y * (x.y - mu) * r + bb.y;
    y.z = gg.z * (x.z - mu) * r + bb.z;
    y.w = gg.w * (x.w - mu) * r + bb.w;
    ((float4*)out)[(size_t)row * 128 + tid] = y;
}

// ---------------- launch ------------------------------------------------------------
extern "C" void kernel_launch(void* const* d_in, const int* in_sizes, int n_in,
                              void* d_out, int out_size)
{
    const float* inQ   = (const float*)d_in[0];
    const float* inK   = (const float*)d_in[1];
    const float* inV   = (const float*)d_in[2];
    const float* WQ    = (const float*)d_in[3];
    const float* WK    = (const float*)d_in[4];
    const float* WV    = (const float*)d_in[5];
    const float* Wfc   = (const float*)d_in[6];
    const float* gamma = (const float*)d_in[7];
    const float* beta  = (const float*)d_in[8];
    const int*   isamp = (const int*)d_in[9];
    float* out = (float*)d_out;

    cudaFuncSetAttribute(gemm3_hmma, cudaFuncAttributeMaxDynamicSharedMemorySize,
                         GSMEM_BYTES);

    // 1. projections: Q,K tf32x3; V tf32x1
    transW_kernel<<<dim3(16, 16, 3), 256>>>(WQ, WK, WV);
    gemm3_hmma<<<dim3(DM_ / 128, (B_ * L_) / 128, 3), 256, GSMEM_BYTES>>>(inQ, inK, inV);

    // 2. sparsity measure
    qkm3_kernel<<<(B_ * L_ * 32) / 256, 256>>>(isamp);

    // 3. top-k
    topk_kernel<<<BH_, 256>>>();

    // 4. V mean
    vmean_kernel<<<BH_, 256>>>();

    // 5. sparse attention + combine
    attn_partial<<<dim3(NCH_, BH_), 256>>>();
    attn_combine<<<(BH_ * U_ * 32 + 255) / 256, 256>>>();

    // 6. low-rank output
    obase_kernel<<<B_, 256>>>(Wfc);
    out_assemble<<<(B_ * L_ * DM_ / 4) / 256, 256>>>(inQ, out);
    correction_kernel<<<BH_ * U_, 128>>>(out, Wfc);

    // 7. layernorm
    ln_kernel<<<(B_ * L_), 128>>>(out, gamma, beta);
}

// round 7
// speedup vs baseline: 1.9731x; 1.1778x over previous
#include <cuda_runtime.h>
#include <math_constants.h>
#include <cstdint>

#define B_    8
#define L_    4096
#define DM_   512
#define H_    8
#define DK_   64
#define DV_   64
#define U_    41
#define BH_   (B_*H_)
#define NCH_  8
#define CHUNK_ (L_/NCH_)
#define EPS_  1e-5f

// ---------------- scratch ----------------------------------------------------
__device__ float g_Q[B_*L_*DM_];
__device__ float g_K[B_*L_*DM_];
__device__ float g_V[B_*L_*DM_];
__device__ float g_Wt[3*DM_*DM_];         // W^T fp32, [which][N][K]
__device__ float g_M[BH_*L_];
__device__ int   g_idx[BH_*U_];
__device__ float g_vals[BH_*U_*DV_];
__device__ float g_vmean[BH_*DV_];
__device__ float g_obase[B_*DM_];
__device__ float g_part[BH_*NCH_*U_*66];

// ---------------- helpers ------------------------------------------------------
__device__ __forceinline__ uint32_t smem_u32(const void* p) {
    uint32_t a;
    asm("{ .reg .u64 t; cvta.to.shared.u64 t, %1; cvt.u32.u64 %0, t; }" : "=r"(a) : "l"(p));
    return a;
}
#define CP_ASYNC_CG(dst, src) \
    asm volatile("cp.async.cg.shared.global [%0], [%1], 16;" :: "r"(dst), "l"(src) : "memory")
#define CP_COMMIT() asm volatile("cp.async.commit_group;" ::: "memory")
#define CP_WAIT1()  asm volatile("cp.async.wait_group 1;" ::: "memory")
#define CP_WAIT0()  asm volatile("cp.async.wait_group 0;" ::: "memory")

// pack two fp32 into bf16x2 (low half = e0)
__device__ __forceinline__ uint32_t packbf(float e0, float e1) {
    uint32_t r;
    asm("cvt.rn.bf16x2.f32 %0, %1, %2;" : "=r"(r) : "f"(e1), "f"(e0));
    return r;
}
// hi/lo split: x = bf16(hi) + bf16(lo) + O(2^-17 x)
__device__ __forceinline__ void splitbf(float2 x, uint32_t& h, uint32_t& l) {
    h = packbf(x.x, x.y);
    float r0 = x.x - __uint_as_float(h << 16);
    float r1 = x.y - __uint_as_float(h & 0xffff0000u);
    l = packbf(r0, r1);
}

#define MMA_BF16(c, a, b) \
    asm volatile("mma.sync.aligned.m16n8k16.row.col.f32.bf16.bf16.f32 " \
        "{%0,%1,%2,%3}, {%4,%5,%6,%7}, {%8,%9}, {%0,%1,%2,%3};" \
        : "+f"((c)[0]), "+f"((c)[1]), "+f"((c)[2]), "+f"((c)[3]) \
        : "r"((a)[0]), "r"((a)[1]), "r"((a)[2]), "r"((a)[3]), \
          "r"((b)[0]), "r"((b)[1]))

// ---------------- W transpose (fp32 only), all 3 weights ------------------------
__global__ __launch_bounds__(256) void transW_kernel(
    const float* __restrict__ W0, const float* __restrict__ W1,
    const float* __restrict__ W2)
{
    __shared__ float tile[32][33];
    const float* W = (blockIdx.z == 0) ? W0 : (blockIdx.z == 1) ? W1 : W2;
    float* dst = g_Wt + (size_t)blockIdx.z * DM_ * DM_;
    int bx = blockIdx.x * 32;
    int by = blockIdx.y * 32;
    int tx = threadIdx.x & 31, ty = threadIdx.x >> 5;
#pragma unroll
    for (int i = 0; i < 4; i++)
        tile[ty + 8 * i][tx] = __ldg(&W[(size_t)(by + ty + 8 * i) * 512 + bx + tx]);
    __syncthreads();
#pragma unroll
    for (int i = 0; i < 4; i++)
        dst[(size_t)(bx + ty + 8 * i) * 512 + by + tx] = tile[tx][ty + 8 * i];
}

// ---------------- HMMA bf16 GEMM, fused in-register hi/lo split ------------------
// z=0 (Q), z=1 (K): bf16x3 (hi.hi + hi.lo + lo.hi; ~1e-5 rel, protects top-k).
// z=2 (V): bf16x1 (error enters only via tiny vmean + 2624 correction rows).
#define PADK 40                        // 40 % 32 == 8 -> conflict-free frag loads
#define MATF (128 * PADK)              // 5120 floats
#define STAGEF (2 * MATF)
#define GSMEM_BYTES (2 * STAGEF * 4)   // 81920

__device__ __forceinline__ void g_load_stage(
    float* sm, int stage, int c, int tid,
    const float* __restrict__ A, const float* __restrict__ Bt)
{
    float* dst = sm + stage * STAGEF;
#pragma unroll
    for (int i = 0; i < 4; i++) {
        int idx = i * 256 + tid;
        int row = idx >> 3, q = idx & 7;
        CP_ASYNC_CG(smem_u32(dst + row * PADK + q * 4),
                    A + (size_t)row * 512 + c * 32 + q * 4);
    }
#pragma unroll
    for (int i = 0; i < 4; i++) {
        int idx = i * 256 + tid;
        int row = idx >> 3, q = idx & 7;
        CP_ASYNC_CG(smem_u32(dst + MATF + row * PADK + q * 4),
                    Bt + (size_t)row * 512 + c * 32 + q * 4);
    }
    CP_COMMIT();
}

__global__ __launch_bounds__(256, 1) void gemm3_hmma(
    const float* __restrict__ inQ, const float* __restrict__ inK,
    const float* __restrict__ inV)
{
    extern __shared__ float sm[];
    const int tid = threadIdx.x;
    const int wid = tid >> 5, lane = tid & 31;
    const int g = lane >> 2, tg = lane & 3;
    const int wm = wid & 1, wn = wid >> 1;
    const int row0 = blockIdx.y * 128, col0 = blockIdx.x * 128;
    const int which = blockIdx.z;
    const bool full = (which != 2);

    const float* Asrc = (which == 0) ? inQ : (which == 1) ? inK : inV;
    const float* A  = Asrc + (size_t)row0 * 512;
    const float* Bt = g_Wt + (size_t)which * DM_ * DM_ + (size_t)col0 * 512;
    float* C = (which == 0) ? g_Q : (which == 1) ? g_K : g_V;

    float acc[4][4][4];
#pragma unroll
    for (int i = 0; i < 4; i++)
#pragma unroll
        for (int j = 0; j < 4; j++)
#pragma unroll
            for (int r = 0; r < 4; r++) acc[i][j][r] = 0.f;

    g_load_stage(sm, 0, 0, tid, A, Bt);

    for (int c = 0; c < 16; c++) {
        const int buf = c & 1;
        if (c < 15) g_load_stage(sm, buf ^ 1, c + 1, tid, A, Bt);
        if (c < 15) { CP_WAIT1(); } else { CP_WAIT0(); }
        __syncthreads();

        const float* sA = sm + buf * STAGEF;
        const float* sB = sA + MATF;

#pragma unroll
        for (int ks = 0; ks < 2; ks++) {
            const int k0 = ks * 16;
            uint32_t ah[4][4], al[4][4], bh[4][2], bl[4][2];
#pragma unroll
            for (int i = 0; i < 4; i++) {
                int r = wm * 64 + i * 16 + g;
                float2 x0 = *(const float2*)&sA[r * PADK + k0 + 2 * tg];
                float2 x1 = *(const float2*)&sA[(r + 8) * PADK + k0 + 2 * tg];
                float2 x2 = *(const float2*)&sA[r * PADK + k0 + 2 * tg + 8];
                float2 x3 = *(const float2*)&sA[(r + 8) * PADK + k0 + 2 * tg + 8];
                if (full) {
                    splitbf(x0, ah[i][0], al[i][0]);
                    splitbf(x1, ah[i][1], al[i][1]);
                    splitbf(x2, ah[i][2], al[i][2]);
                    splitbf(x3, ah[i][3], al[i][3]);
                } else {
                    ah[i][0] = packbf(x0.x, x0.y);
                    ah[i][1] = packbf(x1.x, x1.y);
                    ah[i][2] = packbf(x2.x, x2.y);
                    ah[i][3] = packbf(x3.x, x3.y);
                }
            }
#pragma unroll
            for (int j = 0; j < 4; j++) {
                int n = wn * 32 + j * 8 + g;
                float2 y0 = *(const float2*)&sB[n * PADK + k0 + 2 * tg];
                float2 y1 = *(const float2*)&sB[n * PADK + k0 + 2 * tg + 8];
                if (full) {
                    splitbf(y0, bh[j][0], bl[j][0]);
                    splitbf(y1, bh[j][1], bl[j][1]);
                } else {
                    bh[j][0] = packbf(y0.x, y0.y);
                    bh[j][1] = packbf(y1.x, y1.y);
                }
            }
#pragma unroll
            for (int i = 0; i < 4; i++)
#pragma unroll
                for (int j = 0; j < 4; j++) MMA_BF16(acc[i][j], ah[i], bh[j]);
            if (full) {
#pragma unroll
                for (int i = 0; i < 4; i++)
#pragma unroll
                    for (int j = 0; j < 4; j++) MMA_BF16(acc[i][j], ah[i], bl[j]);
#pragma unroll
                for (int i = 0; i < 4; i++)
#pragma unroll
                    for (int j = 0; j < 4; j++) MMA_BF16(acc[i][j], al[i], bh[j]);
            }
        }
        __syncthreads();
    }

#pragma unroll
    for (int i = 0; i < 4; i++) {
#pragma unroll
        for (int j = 0; j < 4; j++) {
            int row = row0 + wm * 64 + i * 16 + g;
            int col = col0 + wn * 32 + j * 8 + tg * 2;
            float2 v0 = make_float2(acc[i][j][0], acc[i][j][1]);
            float2 v1 = make_float2(acc[i][j][2], acc[i][j][3]);
            *(float2*)(C + (size_t)row * 512 + col) = v0;
            *(float2*)(C + (size_t)(row + 8) * 512 + col) = v1;
        }
    }
}

// ---------------- QK_samp -> M : coalesced gathers, 16-lane-group reduce -------
__global__ __launch_bounds__(256) void qkm3_kernel(const int* __restrict__ isamp)
{
    int gw   = (blockIdx.x * 256 + threadIdx.x) >> 5;
    int lane = threadIdx.x & 31;
    int l = gw & (L_ - 1);
    int b = gw >> 12;

    const float4* qb = (const float4*)(g_Q + ((size_t)(b * L_ + l)) * DM_);
    float4 q0 = qb[lane], q1 = qb[lane + 32], q2 = qb[lane + 64], q3 = qb[lane + 96];

    float smax0 = -CUDART_INF_F, smax1 = -CUDART_INF_F, smax2 = -CUDART_INF_F, smax3 = -CUDART_INF_F;
    float ssum0 = 0.f, ssum1 = 0.f, ssum2 = 0.f, ssum3 = 0.f;
    const int* ip = isamp + l * U_;

#pragma unroll 2
    for (int u = 0; u < U_; u++) {
        int j = __ldg(ip + u);
        const float4* kb = (const float4*)(g_K + ((size_t)(b * L_ + j)) * DM_);
        float4 k0 = kb[lane], k1 = kb[lane + 32], k2 = kb[lane + 64], k3 = kb[lane + 96];
        float s0 = q0.x * k0.x; s0 = fmaf(q0.y, k0.y, s0); s0 = fmaf(q0.z, k0.z, s0); s0 = fmaf(q0.w, k0.w, s0);
        float s1 = q1.x * k1.x; s1 = fmaf(q1.y, k1.y, s1); s1 = fmaf(q1.z, k1.z, s1); s1 = fmaf(q1.w, k1.w, s1);
        float s2 = q2.x * k2.x; s2 = fmaf(q2.y, k2.y, s2); s2 = fmaf(q2.z, k2.z, s2); s2 = fmaf(q2.w, k2.w, s2);
        float s3 = q3.x * k3.x; s3 = fmaf(q3.y, k3.y, s3); s3 = fmaf(q3.z, k3.z, s3); s3 = fmaf(q3.w, k3.w, s3);
#pragma unroll
        for (int m = 1; m <= 8; m <<= 1) {
            s0 += __shfl_xor_sync(0xffffffffu, s0, m);
            s1 += __shfl_xor_sync(0xffffffffu, s1, m);
            s2 += __shfl_xor_sync(0xffffffffu, s2, m);
            s3 += __shfl_xor_sync(0xffffffffu, s3, m);
        }
        smax0 = fmaxf(smax0, s0); ssum0 += s0;
        smax1 = fmaxf(smax1, s1); ssum1 += s1;
        smax2 = fmaxf(smax2, s2); ssum2 += s2;
        smax3 = fmaxf(smax3, s3); ssum3 += s3;
    }
    if ((lane & 15) == 0) {
        int g = lane >> 4;
        size_t base = ((size_t)b * 8) * L_ + l;
        g_M[base + (size_t)(g + 0) * L_] = smax0 - ssum0 * (1.0f / U_);
        g_M[base + (size_t)(g + 2) * L_] = smax1 - ssum1 * (1.0f / U_);
        g_M[base + (size_t)(g + 4) * L_] = smax2 - ssum2 * (1.0f / U_);
        g_M[base + (size_t)(g + 6) * L_] = smax3 - ssum3 * (1.0f / U_);
    }
}

// ---------------- top-k (U=41) per (b,h) ---------------------------------------
__global__ __launch_bounds__(256) void topk_kernel()
{
    int bh = blockIdx.x;
    __shared__ float sv[L_];
    __shared__ float rv[256];
    __shared__ int   ri[256];
    int tid = threadIdx.x;
    for (int i = tid; i < L_; i += 256) sv[i] = g_M[bh * L_ + i];
    __syncthreads();
    for (int it = 0; it < U_; it++) {
        float best = -CUDART_INF_F; int bi = L_;
        for (int i = tid; i < L_; i += 256) {
            float v = sv[i];
            if (v > best) { best = v; bi = i; }
        }
        rv[tid] = best; ri[tid] = bi;
        __syncthreads();
        for (int s = 128; s > 0; s >>= 1) {
            if (tid < s) {
                float v2 = rv[tid + s]; int i2 = ri[tid + s];
                if (v2 > rv[tid] || (v2 == rv[tid] && i2 < ri[tid])) { rv[tid] = v2; ri[tid] = i2; }
            }
            __syncthreads();
        }
        if (tid == 0) { g_idx[bh * U_ + it] = ri[0]; sv[ri[0]] = -CUDART_INF_F; }
        __syncthreads();
    }
}

// ---------------- V mean per (b,h) -----------------------------------------------
__global__ __launch_bounds__(256) void vmean_kernel()
{
    int bh = blockIdx.x;
    int b = bh >> 3, h = bh & 7;
    int tid = threadIdx.x;
    int d = tid & 63, g = tid >> 6;
    float sum = 0.f;
    for (int l = g; l < L_; l += 4)
        sum += g_V[((size_t)(b * L_ + l)) * DM_ + h * DK_ + d];
    __shared__ float red[4][64];
    red[g][d] = sum;
    __syncthreads();
    if (g == 0) {
        float t = red[0][d] + red[1][d] + red[2][d] + red[3][d];
        g_vmean[bh * 64 + d] = t * (1.0f / L_);
    }
}

// ---------------- sparse attention, split-L partials ------------------------------
__global__ __launch_bounds__(256) void attn_partial()
{
    int ch = blockIdx.x, bh = blockIdx.y;
    int b = bh >> 3, h = bh & 7;
    int tid = threadIdx.x, lane = tid & 31, w = tid >> 5;

    __shared__ float qs[U_ * DK_];
    __shared__ float Ks[64 * 68];
    __shared__ float Vs[64 * 68];

    for (int i = tid; i < U_ * DK_; i += 256) {
        int u = i >> 6, d = i & 63;
        int l = g_idx[bh * U_ + u];
        qs[i] = g_Q[((size_t)(b * L_ + l)) * DM_ + h * DK_ + d];
    }
    __syncthreads();

    const int nu = (w == 0) ? 6 : 5;
    float qx[6], qy[6], m[6], ss[6], ax[6], ay[6];
#pragma unroll
    for (int k = 0; k < 6; k++) {
        if (k < nu) {
            int u = w + 8 * k;
            qx[k] = qs[u * 64 + 2 * lane];
            qy[k] = qs[u * 64 + 2 * lane + 1];
        } else {
            qx[k] = 0.f; qy[k] = 0.f;
        }
        m[k] = -CUDART_INF_F; ss[k] = 0.f; ax[k] = 0.f; ay[k] = 0.f;
    }

    const int jbase0 = ch * CHUNK_;
    for (int t = 0; t < CHUNK_ / 64; t++) {
        __syncthreads();
        int jb = jbase0 + t * 64;
        const float4* Kg = (const float4*)(g_K + ((size_t)(b * L_ + jb)) * DM_ + h * DK_);
        const float4* Vg = (const float4*)(g_V + ((size_t)(b * L_ + jb)) * DM_ + h * DK_);
#pragma unroll
        for (int r = 0; r < 4; r++) {
            int idx = tid + 256 * r;
            int row = idx >> 4, cq = idx & 15;
            float4 kv = Kg[(size_t)row * (DM_ / 4) + cq];
            *(float4*)&Ks[row * 68 + cq * 4] = kv;
            float4 vv = Vg[(size_t)row * (DM_ / 4) + cq];
            *(float4*)&Vs[row * 68 + cq * 4] = vv;
        }
        __syncthreads();

#pragma unroll 2
        for (int jj = 0; jj < 64; jj++) {
            float2 kk = *(const float2*)&Ks[jj * 68 + 2 * lane];
            float2 vv = *(const float2*)&Vs[jj * 68 + 2 * lane];
            float sc[6];
#pragma unroll
            for (int k = 0; k < 6; k++)
                sc[k] = fmaf(qy[k], kk.y, qx[k] * kk.x);
#pragma unroll
            for (int o = 16; o > 0; o >>= 1) {
#pragma unroll
                for (int k = 0; k < 6; k++)
                    sc[k] += __shfl_xor_sync(0xffffffffu, sc[k], o);
            }
#pragma unroll
            for (int k = 0; k < 6; k++) {
                float s = sc[k] * 0.125f;
                float mn = fmaxf(m[k], s);
                float ea = __expf(s - mn);
                float eb = __expf(m[k] - mn);
                ss[k] = ss[k] * eb + ea;
                ax[k] = ax[k] * eb + ea * vv.x;
                ay[k] = ay[k] * eb + ea * vv.y;
                m[k] = mn;
            }
        }
    }

#pragma unroll
    for (int k = 0; k < 6; k++) {
        if (k < nu) {
            int u = w + 8 * k;
            size_t base = ((size_t)(bh * NCH_ + ch) * U_ + u) * 66;
            if (lane == 0) { g_part[base] = m[k]; g_part[base + 1] = ss[k]; }
            g_part[base + 2 + 2 * lane] = ax[k];
            g_part[base + 3 + 2 * lane] = ay[k];
        }
    }
}

// ---------------- combine split-L partials ----------------------------------------
__global__ __launch_bounds__(256) void attn_combine()
{
    int gw = (blockIdx.x * blockDim.x + threadIdx.x) >> 5;
    int lane = threadIdx.x & 31;
    if (gw >= BH_ * U_) return;
    int bh = gw / U_, u = gw % U_;

    float M = -CUDART_INF_F;
#pragma unroll
    for (int ch = 0; ch < NCH_; ch++)
        M = fmaxf(M, g_part[((size_t)(bh * NCH_ + ch) * U_ + u) * 66]);
    float S = 0.f, a0 = 0.f, a1 = 0.f;
#pragma unroll
    for (int ch = 0; ch < NCH_; ch++) {
        size_t base = ((size_t)(bh * NCH_ + ch) * U_ + u) * 66;
        float f = __expf(g_part[base] - M);
        S  += g_part[base + 1] * f;
        a0 += g_part[base + 2 + 2 * lane] * f;
        a1 += g_part[base + 3 + 2 * lane] * f;
    }
    float inv = 1.0f / S;
    g_vals[(size_t)gw * 64 + 2 * lane]     = a0 * inv;
    g_vals[(size_t)gw * 64 + 2 * lane + 1] = a1 * inv;
}

// ---------------- low-rank output path ---------------------------------------------
__global__ __launch_bounds__(256) void obase_kernel(const float* __restrict__ Wfc)
{
    int b = blockIdx.x, tid = threadIdx.x;
    __shared__ float vm[512];
    vm[tid]       = g_vmean[b * 512 + tid];
    vm[tid + 256] = g_vmean[b * 512 + tid + 256];
    __syncthreads();
    float a0 = 0.f, a1 = 0.f;
    const float2* W2 = (const float2*)Wfc + tid;
#pragma unroll 8
    for (int r = 0; r < 512; r++) {
        float2 w = __ldg(W2 + (size_t)r * 256);
        float v = vm[r];
        a0 = fmaf(v, w.x, a0);
        a1 = fmaf(v, w.y, a1);
    }
    g_obase[b * 512 + 2 * tid]     = a0;
    g_obase[b * 512 + 2 * tid + 1] = a1;
}

__global__ __launch_bounds__(256) void out_assemble(const float* __restrict__ inQ,
                                                    float* __restrict__ out)
{
    int i4 = blockIdx.x * 256 + threadIdx.x;
    int b  = i4 >> 19;
    int c4 = i4 & 127;
    float4 x = ((const float4*)inQ)[i4];
    float4 o = __ldg((const float4*)g_obase + (b << 7) + c4);
    x.x += o.x; x.y += o.y; x.z += o.z; x.w += o.w;
    ((float4*)out)[i4] = x;
}

__global__ __launch_bounds__(128) void correction_kernel(float* __restrict__ out,
                                                         const float* __restrict__ Wfc)
{
    int gu = blockIdx.x;
    int bh = gu / U_;
    int b = bh >> 3, h = bh & 7;
    int l = g_idx[gu];
    int tid = threadIdx.x;

    __shared__ float delta[64];
    if (tid < 64)
        delta[tid] = g_vals[(size_t)gu * 64 + tid] - g_vmean[bh * 64 + tid];
    __syncthreads();

    float4 acc = make_float4(0.f, 0.f, 0.f, 0.f);
    const float4* W4 = (const float4*)Wfc + (size_t)(h * 64) * 128 + tid;
#pragma unroll 8
    for (int k = 0; k < 64; k++) {
        float d = delta[k];
        float4 w = __ldg(W4 + (size_t)k * 128);
        acc.x = fmaf(d, w.x, acc.x);
        acc.y = fmaf(d, w.y, acc.y);
        acc.z = fmaf(d, w.z, acc.z);
        acc.w = fmaf(d, w.w, acc.w);
    }
    float* o = out + ((size_t)(b * L_ + l)) * 512 + tid * 4;
    atomicAdd(o + 0, acc.x);
    atomicAdd(o + 1, acc.y);
    atomicAdd(o + 2, acc.z);
    atomicAdd(o + 3, acc.w);
}

// ---------------- LayerNorm -----------------------------------------------------------
__global__ __launch_bounds__(128) void ln_kernel(float* __restrict__ out,
                                                 const float* __restrict__ gamma,
                                                 const float* __restrict__ beta)
{
    int row = blockIdx.x, tid = threadIdx.x;
    float4 x = ((const float4*)out)[(size_t)row * 128 + tid];
    float s  = x.x + x.y + x.z + x.w;
    float sq = x.x * x.x + x.y * x.y + x.z * x.z + x.w * x.w;
#pragma unroll
    for (int o = 16; o > 0; o >>= 1) {
        s  += __shfl_xor_sync(0xffffffffu, s, o);
        sq += __shfl_xor_sync(0xffffffffu, sq, o);
    }
    __shared__ float sh[8];
    int w = tid >> 5, lane = tid & 31;
    if (lane == 0) { sh[w] = s; sh[4 + w] = sq; }
    __syncthreads();
    s  = sh[0] + sh[1] + sh[2] + sh[3];
    sq = sh[4] + sh[5] + sh[6] + sh[7];
    float mu  = s * (1.0f / 512.0f);
    float var = sq * (1.0f / 512.0f) - mu * mu;
    float r   = rsqrtf(var + EPS_);
    float4 gg = ((const float4*)gamma)[tid];
    float4 bb = ((const float4*)beta)[tid];
    float4 y;
    y.x = gg.x * (x.x - mu) * r + bb.x;
    y.y = gg.y * (x.y - mu) * r + bb.y;
    y.z = gg.z * (x.z - mu) * r + bb.z;
    y.w = gg.w * (x.w - mu) * r + bb.w;
    ((float4*)out)[(size_t)row * 128 + tid] = y;
}

// ---------------- launch ------------------------------------------------------------
extern "C" void kernel_launch(void* const* d_in, const int* in_sizes, int n_in,
                              void* d_out, int out_size)
{
    const float* inQ   = (const float*)d_in[0];
    const float* inK   = (const float*)d_in[1];
    const float* inV   = (const float*)d_in[2];
    const float* WQ    = (const float*)d_in[3];
    const float* WK    = (const float*)d_in[4];
    const float* WV    = (const float*)d_in[5];
    const float* Wfc   = (const float*)d_in[6];
    const float* gamma = (const float*)d_in[7];
    const float* beta  = (const float*)d_in[8];
    const int*   isamp = (const int*)d_in[9];
    float* out = (float*)d_out;

    cudaFuncSetAttribute(gemm3_hmma, cudaFuncAttributeMaxDynamicSharedMemorySize,
                         GSMEM_BYTES);

    // 1. projections: Q,K bf16x3; V bf16x1 (m16n8k16)
    transW_kernel<<<dim3(16, 16, 3), 256>>>(WQ, WK, WV);
    gemm3_hmma<<<dim3(DM_ / 128, (B_ * L_) / 128, 3), 256, GSMEM_BYTES>>>(inQ, inK, inV);

    // 2. sparsity measure
    qkm3_kernel<<<(B_ * L_ * 32) / 256, 256>>>(isamp);

    // 3. top-k
    topk_kernel<<<BH_, 256>>>();

    // 4. V mean
    vmean_kernel<<<BH_, 256>>>();

    // 5. sparse attention + combine
    attn_partial<<<dim3(NCH_, BH_), 256>>>();
    attn_combine<<<(BH_ * U_ * 32 + 255) / 256, 256>>>();

    // 6. low-rank output
    obase_kernel<<<B_, 256>>>(Wfc);
    out_assemble<<<(B_ * L_ * DM_ / 4) / 256, 256>>>(inQ, out);
    correction_kernel<<<BH_ * U_, 128>>>(out, Wfc);

    // 7. layernorm
    ln_kernel<<<(B_ * L_), 128>>>(out, gamma, beta);
}

// round 8
// speedup vs baseline: 2.1547x; 1.0920x over previous
#include <cuda_runtime.h>
#include <math_constants.h>
#include <cstdint>

#define B_    8
#define L_    4096
#define DM_   512
#define H_    8
#define DK_   64
#define DV_   64
#define U_    41
#define BH_   (B_*H_)
#define NCH_  8
#define CHUNK_ (L_/NCH_)
#define EPS_  1e-5f

// ---------------- scratch ----------------------------------------------------
__device__ float g_Q[B_*L_*DM_];
__device__ float g_K[B_*L_*DM_];
__device__ float g_V[B_*L_*DM_];
__device__ float g_Wt[3*DM_*DM_];
__device__ float g_M[BH_*L_];
__device__ int   g_idx[BH_*U_];
__device__ float g_cval[BH_*8*U_];
__device__ int   g_cidx[BH_*8*U_];
__device__ float g_vals[BH_*U_*DV_];
__device__ float g_vmean[BH_*DV_];
__device__ float g_obase[B_*DM_];
__device__ float g_part[BH_*NCH_*U_*66];

// ---------------- helpers ------------------------------------------------------
__device__ __forceinline__ uint32_t smem_u32(const void* p) {
    uint32_t a;
    asm("{ .reg .u64 t; cvta.to.shared.u64 t, %1; cvt.u32.u64 %0, t; }" : "=r"(a) : "l"(p));
    return a;
}
#define CP_ASYNC_CG(dst, src) \
    asm volatile("cp.async.cg.shared.global [%0], [%1], 16;" :: "r"(dst), "l"(src) : "memory")
#define CP_COMMIT() asm volatile("cp.async.commit_group;" ::: "memory")
#define CP_WAIT1()  asm volatile("cp.async.wait_group 1;" ::: "memory")
#define CP_WAIT0()  asm volatile("cp.async.wait_group 0;" ::: "memory")

__device__ __forceinline__ uint32_t packbf(float e0, float e1) {
    uint32_t r;
    asm("cvt.rn.bf16x2.f32 %0, %1, %2;" : "=r"(r) : "f"(e1), "f"(e0));
    return r;
}
__device__ __forceinline__ void splitbf(float2 x, uint32_t& h, uint32_t& l) {
    h = packbf(x.x, x.y);
    float r0 = x.x - __uint_as_float(h << 16);
    float r1 = x.y - __uint_as_float(h & 0xffff0000u);
    l = packbf(r0, r1);
}

#define MMA_BF16(c, a, b) \
    asm volatile("mma.sync.aligned.m16n8k16.row.col.f32.bf16.bf16.f32 " \
        "{%0,%1,%2,%3}, {%4,%5,%6,%7}, {%8,%9}, {%0,%1,%2,%3};" \
        : "+f"((c)[0]), "+f"((c)[1]), "+f"((c)[2]), "+f"((c)[3]) \
        : "r"((a)[0]), "r"((a)[1]), "r"((a)[2]), "r"((a)[3]), \
          "r"((b)[0]), "r"((b)[1]))

// ---------------- W transpose (fp32 only), all 3 weights ------------------------
__global__ __launch_bounds__(256) void transW_kernel(
    const float* __restrict__ W0, const float* __restrict__ W1,
    const float* __restrict__ W2)
{
    __shared__ float tile[32][33];
    const float* W = (blockIdx.z == 0) ? W0 : (blockIdx.z == 1) ? W1 : W2;
    float* dst = g_Wt + (size_t)blockIdx.z * DM_ * DM_;
    int bx = blockIdx.x * 32;
    int by = blockIdx.y * 32;
    int tx = threadIdx.x & 31, ty = threadIdx.x >> 5;
#pragma unroll
    for (int i = 0; i < 4; i++)
        tile[ty + 8 * i][tx] = __ldg(&W[(size_t)(by + ty + 8 * i) * 512 + bx + tx]);
    __syncthreads();
#pragma unroll
    for (int i = 0; i < 4; i++)
        dst[(size_t)(bx + ty + 8 * i) * 512 + by + tx] = tile[tx][ty + 8 * i];
}

// ---------------- HMMA bf16 GEMM, fused in-register hi/lo split ------------------
#define PADK 40
#define MATF (128 * PADK)
#define STAGEF (2 * MATF)
#define GSMEM_BYTES (2 * STAGEF * 4)

__device__ __forceinline__ void g_load_stage(
    float* sm, int stage, int c, int tid,
    const float* __restrict__ A, const float* __restrict__ Bt)
{
    float* dst = sm + stage * STAGEF;
#pragma unroll
    for (int i = 0; i < 4; i++) {
        int idx = i * 256 + tid;
        int row = idx >> 3, q = idx & 7;
        CP_ASYNC_CG(smem_u32(dst + row * PADK + q * 4),
                    A + (size_t)row * 512 + c * 32 + q * 4);
    }
#pragma unroll
    for (int i = 0; i < 4; i++) {
        int idx = i * 256 + tid;
        int row = idx >> 3, q = idx & 7;
        CP_ASYNC_CG(smem_u32(dst + MATF + row * PADK + q * 4),
                    Bt + (size_t)row * 512 + c * 32 + q * 4);
    }
    CP_COMMIT();
}

__global__ __launch_bounds__(256, 1) void gemm3_hmma(
    const float* __restrict__ inQ, const float* __restrict__ inK,
    const float* __restrict__ inV, int base)
{
    extern __shared__ float sm[];
    const int tid = threadIdx.x;
    const int wid = tid >> 5, lane = tid & 31;
    const int g = lane >> 2, tg = lane & 3;
    const int wm = wid & 1, wn = wid >> 1;
    const int row0 = blockIdx.y * 128, col0 = blockIdx.x * 128;
    const int which = base + blockIdx.z;
    const bool full = (which != 2);

    const float* Asrc = (which == 0) ? inQ : (which == 1) ? inK : inV;
    const float* A  = Asrc + (size_t)row0 * 512;
    const float* Bt = g_Wt + (size_t)which * DM_ * DM_ + (size_t)col0 * 512;
    float* C = (which == 0) ? g_Q : (which == 1) ? g_K : g_V;

    float acc[4][4][4];
#pragma unroll
    for (int i = 0; i < 4; i++)
#pragma unroll
        for (int j = 0; j < 4; j++)
#pragma unroll
            for (int r = 0; r < 4; r++) acc[i][j][r] = 0.f;

    g_load_stage(sm, 0, 0, tid, A, Bt);

    for (int c = 0; c < 16; c++) {
        const int buf = c & 1;
        if (c < 15) g_load_stage(sm, buf ^ 1, c + 1, tid, A, Bt);
        if (c < 15) { CP_WAIT1(); } else { CP_WAIT0(); }
        __syncthreads();

        const float* sA = sm + buf * STAGEF;
        const float* sB = sA + MATF;

#pragma unroll
        for (int ks = 0; ks < 2; ks++) {
            const int k0 = ks * 16;
            uint32_t ah[4][4], al[4][4], bh[4][2], bl[4][2];
#pragma unroll
            for (int i = 0; i < 4; i++) {
                int r = wm * 64 + i * 16 + g;
                float2 x0 = *(const float2*)&sA[r * PADK + k0 + 2 * tg];
                float2 x1 = *(const float2*)&sA[(r + 8) * PADK + k0 + 2 * tg];
                float2 x2 = *(const float2*)&sA[r * PADK + k0 + 2 * tg + 8];
                float2 x3 = *(const float2*)&sA[(r + 8) * PADK + k0 + 2 * tg + 8];
                if (full) {
                    splitbf(x0, ah[i][0], al[i][0]);
                    splitbf(x1, ah[i][1], al[i][1]);
                    splitbf(x2, ah[i][2], al[i][2]);
                    splitbf(x3, ah[i][3], al[i][3]);
                } else {
                    ah[i][0] = packbf(x0.x, x0.y);
                    ah[i][1] = packbf(x1.x, x1.y);
                    ah[i][2] = packbf(x2.x, x2.y);
                    ah[i][3] = packbf(x3.x, x3.y);
                }
            }
#pragma unroll
            for (int j = 0; j < 4; j++) {
                int n = wn * 32 + j * 8 + g;
                float2 y0 = *(const float2*)&sB[n * PADK + k0 + 2 * tg];
                float2 y1 = *(const float2*)&sB[n * PADK + k0 + 2 * tg + 8];
                if (full) {
                    splitbf(y0, bh[j][0], bl[j][0]);
                    splitbf(y1, bh[j][1], bl[j][1]);
                } else {
                    bh[j][0] = packbf(y0.x, y0.y);
                    bh[j][1] = packbf(y1.x, y1.y);
                }
            }
#pragma unroll
            for (int i = 0; i < 4; i++)
#pragma unroll
                for (int j = 0; j < 4; j++) MMA_BF16(acc[i][j], ah[i], bh[j]);
            if (full) {
#pragma unroll
                for (int i = 0; i < 4; i++)
#pragma unroll
                    for (int j = 0; j < 4; j++) MMA_BF16(acc[i][j], ah[i], bl[j]);
#pragma unroll
                for (int i = 0; i < 4; i++)
#pragma unroll
                    for (int j = 0; j < 4; j++) MMA_BF16(acc[i][j], al[i], bh[j]);
            }
        }
        __syncthreads();
    }

#pragma unroll
    for (int i = 0; i < 4; i++) {
#pragma unroll
        for (int j = 0; j < 4; j++) {
            int row = row0 + wm * 64 + i * 16 + g;
            int col = col0 + wn * 32 + j * 8 + tg * 2;
            float2 v0 = make_float2(acc[i][j][0], acc[i][j][1]);
            float2 v1 = make_float2(acc[i][j][2], acc[i][j][3]);
            *(float2*)(C + (size_t)row * 512 + col) = v0;
            *(float2*)(C + (size_t)(row + 8) * 512 + col) = v1;
        }
    }
}

// ---------------- QK_samp -> M --------------------------------------------------
__global__ __launch_bounds__(256) void qkm3_kernel(const int* __restrict__ isamp)
{
    int gw   = (blockIdx.x * 256 + threadIdx.x) >> 5;
    int lane = threadIdx.x & 31;
    int l = gw & (L_ - 1);
    int b = gw >> 12;

    const float4* qb = (const float4*)(g_Q + ((size_t)(b * L_ + l)) * DM_);
    float4 q0 = qb[lane], q1 = qb[lane + 32], q2 = qb[lane + 64], q3 = qb[lane + 96];

    float smax0 = -CUDART_INF_F, smax1 = -CUDART_INF_F, smax2 = -CUDART_INF_F, smax3 = -CUDART_INF_F;
    float ssum0 = 0.f, ssum1 = 0.f, ssum2 = 0.f, ssum3 = 0.f;
    const int* ip = isamp + l * U_;

#pragma unroll 2
    for (int u = 0; u < U_; u++) {
        int j = __ldg(ip + u);
        const float4* kb = (const float4*)(g_K + ((size_t)(b * L_ + j)) * DM_);
        float4 k0 = kb[lane], k1 = kb[lane + 32], k2 = kb[lane + 64], k3 = kb[lane + 96];
        float s0 = q0.x * k0.x; s0 = fmaf(q0.y, k0.y, s0); s0 = fmaf(q0.z, k0.z, s0); s0 = fmaf(q0.w, k0.w, s0);
        float s1 = q1.x * k1.x; s1 = fmaf(q1.y, k1.y, s1); s1 = fmaf(q1.z, k1.z, s1); s1 = fmaf(q1.w, k1.w, s1);
        float s2 = q2.x * k2.x; s2 = fmaf(q2.y, k2.y, s2); s2 = fmaf(q2.z, k2.z, s2); s2 = fmaf(q2.w, k2.w, s2);
        float s3 = q3.x * k3.x; s3 = fmaf(q3.y, k3.y, s3); s3 = fmaf(q3.z, k3.z, s3); s3 = fmaf(q3.w, k3.w, s3);
#pragma unroll
        for (int m = 1; m <= 8; m <<= 1) {
            s0 += __shfl_xor_sync(0xffffffffu, s0, m);
            s1 += __shfl_xor_sync(0xffffffffu, s1, m);
            s2 += __shfl_xor_sync(0xffffffffu, s2, m);
            s3 += __shfl_xor_sync(0xffffffffu, s3, m);
        }
        smax0 = fmaxf(smax0, s0); ssum0 += s0;
        smax1 = fmaxf(smax1, s1); ssum1 += s1;
        smax2 = fmaxf(smax2, s2); ssum2 += s2;
        smax3 = fmaxf(smax3, s3); ssum3 += s3;
    }
    if ((lane & 15) == 0) {
        int g = lane >> 4;
        size_t base = ((size_t)b * 8) * L_ + l;
        g_M[base + (size_t)(g + 0) * L_] = smax0 - ssum0 * (1.0f / U_);
        g_M[base + (size_t)(g + 2) * L_] = smax1 - ssum1 * (1.0f / U_);
        g_M[base + (size_t)(g + 4) * L_] = smax2 - ssum2 * (1.0f / U_);
        g_M[base + (size_t)(g + 6) * L_] = smax3 - ssum3 * (1.0f / U_);
    }
}

// ---------------- top-k phase A: per-slice local top-41 -------------------------
// grid (8 slices, 64 bh); each block: top-41 of its 512-element slice.
__global__ __launch_bounds__(256) void topkA_kernel()
{
    int slice = blockIdx.x, bh = blockIdx.y;
    __shared__ float sv[512];
    __shared__ float wv[8];
    __shared__ int   wi[8];
    __shared__ float bcv[1];
    __shared__ int   bci[1];
    int tid = threadIdx.x, lane = tid & 31, w = tid >> 5;

    sv[tid]       = g_M[bh * L_ + slice * 512 + tid];
    sv[tid + 256] = g_M[bh * L_ + slice * 512 + tid + 256];
    __syncthreads();

    for (int it = 0; it < U_; it++) {
        float v0 = sv[tid], v1 = sv[tid + 256];
        float bv; int bi;
        if (v1 > v0) { bv = v1; bi = tid + 256; } else { bv = v0; bi = tid; }
#pragma unroll
        for (int o = 16; o > 0; o >>= 1) {
            float ov = __shfl_xor_sync(0xffffffffu, bv, o);
            int   oi = __shfl_xor_sync(0xffffffffu, bi, o);
            if (ov > bv || (ov == bv && oi < bi)) { bv = ov; bi = oi; }
        }
        if (lane == 0) { wv[w] = bv; wi[w] = bi; }
        __syncthreads();
        if (tid == 0) {
            float fv = wv[0]; int fi = wi[0];
#pragma unroll
            for (int k = 1; k < 8; k++) {
                if (wv[k] > fv || (wv[k] == fv && wi[k] < fi)) { fv = wv[k]; fi = wi[k]; }
            }
            bcv[0] = fv; bci[0] = fi;
            sv[fi] = -CUDART_INF_F;
            g_cval[(bh * 8 + slice) * U_ + it] = fv;
            g_cidx[(bh * 8 + slice) * U_ + it] = slice * 512 + fi;
        }
        __syncthreads();
    }
}

// ---------------- top-k phase B: merge 8x41 candidates --------------------------
__global__ __launch_bounds__(256) void topkB_kernel()
{
    int bh = blockIdx.x;
    __shared__ float sv[512];
    __shared__ int   si[512];
    __shared__ float wv[8];
    __shared__ int   wi[8];
    int tid = threadIdx.x, lane = tid & 31, w = tid >> 5;

    const int NC = 8 * U_;                   // 328
#pragma unroll
    for (int r = 0; r < 2; r++) {
        int i = tid + 256 * r;
        if (i < NC) {
            sv[i] = g_cval[bh * NC + i];
            si[i] = g_cidx[bh * NC + i];
        } else if (i < 512) {
            sv[i] = -CUDART_INF_F;
            si[i] = 0x7fffffff;
        }
    }
    __syncthreads();

    for (int it = 0; it < U_; it++) {
        float v0 = sv[tid], v1 = sv[tid + 256];
        int   i0 = si[tid], i1 = si[tid + 256];
        float bv; int bi, bslot;
        if (v1 > v0 || (v1 == v0 && i1 < i0)) { bv = v1; bi = i1; bslot = tid + 256; }
        else                                   { bv = v0; bi = i0; bslot = tid; }
#pragma unroll
        for (int o = 16; o > 0; o >>= 1) {
            float ov = __shfl_xor_sync(0xffffffffu, bv, o);
            int   oi = __shfl_xor_sync(0xffffffffu, bi, o);
            int   os = __shfl_xor_sync(0xffffffffu, bslot, o);
            if (ov > bv || (ov == bv && oi < bi)) { bv = ov; bi = oi; bslot = os; }
        }
        if (lane == 0) { wv[w] = bv; wi[w] = (bslot << 16) | 0; }
        __syncthreads();
        // store packed: need idx too; redo with three smem arrays
        if (lane == 0) { wi[w] = bslot; }
        __syncthreads();
        if (tid == 0) {
            float fv = wv[0]; int fslot = wi[0];
#pragma unroll
            for (int k = 1; k < 8; k++) {
                int s2 = wi[k];
                if (wv[k] > fv || (wv[k] == fv && si[s2] < si[fslot])) { fv = wv[k]; fslot = s2; }
            }
            g_idx[bh * U_ + it] = si[fslot];
            sv[fslot] = -CUDART_INF_F;
            si[fslot] = 0x7fffffff;
        }
        __syncthreads();
    }
}

// ---------------- V mean per (b,h) -----------------------------------------------
__global__ __launch_bounds__(256) void vmean_kernel()
{
    int bh = blockIdx.x;
    int b = bh >> 3, h = bh & 7;
    int tid = threadIdx.x;
    int d = tid & 63, g = tid >> 6;
    float sum = 0.f;
    for (int l = g; l < L_; l += 4)
        sum += g_V[((size_t)(b * L_ + l)) * DM_ + h * DK_ + d];
    __shared__ float red[4][64];
    red[g][d] = sum;
    __syncthreads();
    if (g == 0) {
        float t = red[0][d] + red[1][d] + red[2][d] + red[3][d];
        g_vmean[bh * 64 + d] = t * (1.0f / L_);
    }
}

// ---------------- sparse attention, split-L partials ------------------------------
__global__ __launch_bounds__(256) void attn_partial()
{
    int ch = blockIdx.x, bh = blockIdx.y;
    int b = bh >> 3, h = bh & 7;
    int tid = threadIdx.x, lane = tid & 31, w = tid >> 5;

    __shared__ float qs[U_ * DK_];
    __shared__ float Ks[64 * 68];
    __shared__ float Vs[64 * 68];

    for (int i = tid; i < U_ * DK_; i += 256) {
        int u = i >> 6, d = i & 63;
        int l = g_idx[bh * U_ + u];
        qs[i] = g_Q[((size_t)(b * L_ + l)) * DM_ + h * DK_ + d];
    }
    __syncthreads();

    const int nu = (w == 0) ? 6 : 5;
    float qx[6], qy[6], m[6], ss[6], ax[6], ay[6];
#pragma unroll
    for (int k = 0; k < 6; k++) {
        if (k < nu) {
            int u = w + 8 * k;
            qx[k] = qs[u * 64 + 2 * lane];
            qy[k] = qs[u * 64 + 2 * lane + 1];
        } else {
            qx[k] = 0.f; qy[k] = 0.f;
        }
        m[k] = -CUDART_INF_F; ss[k] = 0.f; ax[k] = 0.f; ay[k] = 0.f;
    }

    const int jbase0 = ch * CHUNK_;
    for (int t = 0; t < CHUNK_ / 64; t++) {
        __syncthreads();
        int jb = jbase0 + t * 64;
        const float4* Kg = (const float4*)(g_K + ((size_t)(b * L_ + jb)) * DM_ + h * DK_);
        const float4* Vg = (const float4*)(g_V + ((size_t)(b * L_ + jb)) * DM_ + h * DK_);
#pragma unroll
        for (int r = 0; r < 4; r++) {
            int idx = tid + 256 * r;
            int row = idx >> 4, cq = idx & 15;
            float4 kv = Kg[(size_t)row * (DM_ / 4) + cq];
            *(float4*)&Ks[row * 68 + cq * 4] = kv;
            float4 vv = Vg[(size_t)row * (DM_ / 4) + cq];
            *(float4*)&Vs[row * 68 + cq * 4] = vv;
        }
        __syncthreads();

#pragma unroll 2
        for (int jj = 0; jj < 64; jj++) {
            float2 kk = *(const float2*)&Ks[jj * 68 + 2 * lane];
            float2 vv = *(const float2*)&Vs[jj * 68 + 2 * lane];
            float sc[6];
#pragma unroll
            for (int k = 0; k < 6; k++)
                sc[k] = fmaf(qy[k], kk.y, qx[k] * kk.x);
#pragma unroll
            for (int o = 16; o > 0; o >>= 1) {
#pragma unroll
                for (int k = 0; k < 6; k++)
                    sc[k] += __shfl_xor_sync(0xffffffffu, sc[k], o);
            }
#pragma unroll
            for (int k = 0; k < 6; k++) {
                float s = sc[k] * 0.125f;
                float mn = fmaxf(m[k], s);
                float ea = __expf(s - mn);
                float eb = __expf(m[k] - mn);
                ss[k] = ss[k] * eb + ea;
                ax[k] = ax[k] * eb + ea * vv.x;
                ay[k] = ay[k] * eb + ea * vv.y;
                m[k] = mn;
            }
        }
    }

#pragma unroll
    for (int k = 0; k < 6; k++) {
        if (k < nu) {
            int u = w + 8 * k;
            size_t base = ((size_t)(bh * NCH_ + ch) * U_ + u) * 66;
            if (lane == 0) { g_part[base] = m[k]; g_part[base + 1] = ss[k]; }
            g_part[base + 2 + 2 * lane] = ax[k];
            g_part[base + 3 + 2 * lane] = ay[k];
        }
    }
}

// ---------------- combine split-L partials ----------------------------------------
__global__ __launch_bounds__(256) void attn_combine()
{
    int gw = (blockIdx.x * blockDim.x + threadIdx.x) >> 5;
    int lane = threadIdx.x & 31;
    if (gw >= BH_ * U_) return;
    int bh = gw / U_, u = gw % U_;

    float M = -CUDART_INF_F;
#pragma unroll
    for (int ch = 0; ch < NCH_; ch++)
        M = fmaxf(M, g_part[((size_t)(bh * NCH_ + ch) * U_ + u) * 66]);
    float S = 0.f, a0 = 0.f, a1 = 0.f;
#pragma unroll
    for (int ch = 0; ch < NCH_; ch++) {
        size_t base = ((size_t)(bh * NCH_ + ch) * U_ + u) * 66;
        float f = __expf(g_part[base] - M);
        S  += g_part[base + 1] * f;
        a0 += g_part[base + 2 + 2 * lane] * f;
        a1 += g_part[base + 3 + 2 * lane] * f;
    }
    float inv = 1.0f / S;
    g_vals[(size_t)gw * 64 + 2 * lane]     = a0 * inv;
    g_vals[(size_t)gw * 64 + 2 * lane + 1] = a1 * inv;
}

// ---------------- low-rank output path ---------------------------------------------
__global__ __launch_bounds__(256) void obase_kernel(const float* __restrict__ Wfc)
{
    int b = blockIdx.x, tid = threadIdx.x;
    __shared__ float vm[512];
    vm[tid]       = g_vmean[b * 512 + tid];
    vm[tid + 256] = g_vmean[b * 512 + tid + 256];
    __syncthreads();
    float a0 = 0.f, a1 = 0.f;
    const float2* W2 = (const float2*)Wfc + tid;
#pragma unroll 8
    for (int r = 0; r < 512; r++) {
        float2 w = __ldg(W2 + (size_t)r * 256);
        float v = vm[r];
        a0 = fmaf(v, w.x, a0);
        a1 = fmaf(v, w.y, a1);
    }
    g_obase[b * 512 + 2 * tid]     = a0;
    g_obase[b * 512 + 2 * tid + 1] = a1;
}

__global__ __launch_bounds__(256) void out_assemble(const float* __restrict__ inQ,
                                                    float* __restrict__ out)
{
    int i4 = blockIdx.x * 256 + threadIdx.x;
    int b  = i4 >> 19;
    int c4 = i4 & 127;
    float4 x = ((const float4*)inQ)[i4];
    float4 o = __ldg((const float4*)g_obase + (b << 7) + c4);
    x.x += o.x; x.y += o.y; x.z += o.z; x.w += o.w;
    ((float4*)out)[i4] = x;
}

__global__ __launch_bounds__(128) void correction_kernel(float* __restrict__ out,
                                                         const float* __restrict__ Wfc)
{
    int gu = blockIdx.x;
    int bh = gu / U_;
    int b = bh >> 3, h = bh & 7;
    int l = g_idx[gu];
    int tid = threadIdx.x;

    __shared__ float delta[64];
    if (tid < 64)
        delta[tid] = g_vals[(size_t)gu * 64 + tid] - g_vmean[bh * 64 + tid];
    __syncthreads();

    float4 acc = make_float4(0.f, 0.f, 0.f, 0.f);
    const float4* W4 = (const float4*)Wfc + (size_t)(h * 64) * 128 + tid;
#pragma unroll 8
    for (int k = 0; k < 64; k++) {
        float d = delta[k];
        float4 w = __ldg(W4 + (size_t)k * 128);
        acc.x = fmaf(d, w.x, acc.x);
        acc.y = fmaf(d, w.y, acc.y);
        acc.z = fmaf(d, w.z, acc.z);
        acc.w = fmaf(d, w.w, acc.w);
    }
    float* o = out + ((size_t)(b * L_ + l)) * 512 + tid * 4;
    atomicAdd(o + 0, acc.x);
    atomicAdd(o + 1, acc.y);
    atomicAdd(o + 2, acc.z);
    atomicAdd(o + 3, acc.w);
}

// ---------------- LayerNorm -----------------------------------------------------------
__global__ __launch_bounds__(128) void ln_kernel(float* __restrict__ out,
                                                 const float* __restrict__ gamma,
                                                 const float* __restrict__ beta)
{
    int row = blockIdx.x, tid = threadIdx.x;
    float4 x = ((const float4*)out)[(size_t)row * 128 + tid];
    float s  = x.x + x.y + x.z + x.w;
    float sq = x.x * x.x + x.y * x.y + x.z * x.z + x.w * x.w;
#pragma unroll
    for (int o = 16; o > 0; o >>= 1) {
        s  += __shfl_xor_sync(0xffffffffu, s, o);
        sq += __shfl_xor_sync(0xffffffffu, sq, o);
    }
    __shared__ float sh[8];
    int w = tid >> 5, lane = tid & 31;
    if (lane == 0) { sh[w] = s; sh[4 + w] = sq; }
    __syncthreads();
    s  = sh[0] + sh[1] + sh[2] + sh[3];
    sq = sh[4] + sh[5] + sh[6] + sh[7];
    float mu  = s * (1.0f / 512.0f);
    float var = sq * (1.0f / 512.0f) - mu * mu;
    float r   = rsqrtf(var + EPS_);
    float4 gg = ((const float4*)gamma)[tid];
    float4 bb = ((const float4*)beta)[tid];
    float4 y;
    y.x = gg.x * (x.x - mu) * r + bb.x;
    y.y = gg.y * (x.y - mu) * r + bb.y;
    y.z = gg.z * (x.z - mu) * r + bb.z;
    y.w = gg.w * (x.w - mu) * r + bb.w;
    ((float4*)out)[(size_t)row * 128 + tid] = y;
}

// ---------------- launch ------------------------------------------------------------
extern "C" void kernel_launch(void* const* d_in, const int* in_sizes, int n_in,
                              void* d_out, int out_size)
{
    const float* inQ   = (const float*)d_in[0];
    const float* inK   = (const float*)d_in[1];
    const float* inV   = (const float*)d_in[2];
    const float* WQ    = (const float*)d_in[3];
    const float* WK    = (const float*)d_in[4];
    const float* WV    = (const float*)d_in[5];
    const float* Wfc   = (const float*)d_in[6];
    const float* gamma = (const float*)d_in[7];
    const float* beta  = (const float*)d_in[8];
    const int*   isamp = (const int*)d_in[9];
    float* out = (float*)d_out;

    // one-time host-side setup (no device allocations)
    static cudaStream_t s2;
    static cudaEvent_t evFork, evV, evOA;
    static bool init = false;
    if (!init) {
        cudaStreamCreateWithFlags(&s2, cudaStreamNonBlocking);
        cudaEventCreateWithFlags(&evFork, cudaEventDisableTiming);
        cudaEventCreateWithFlags(&evV, cudaEventDisableTiming);
        cudaEventCreateWithFlags(&evOA, cudaEventDisableTiming);
        cudaFuncSetAttribute(gemm3_hmma, cudaFuncAttributeMaxDynamicSharedMemorySize,
                             GSMEM_BYTES);
        init = true;
    }

    // ---- main stream: weight transpose, then fork ----
    transW_kernel<<<dim3(16, 16, 3), 256>>>(WQ, WK, WV);
    cudaEventRecord(evFork, 0);
    cudaStreamWaitEvent(s2, evFork, 0);

    // ---- main: Q,K projections (critical path) ----
    gemm3_hmma<<<dim3(4, 256, 2), 256, GSMEM_BYTES>>>(inQ, inK, inV, 0);

    // ---- s2: V projection branch (overlaps qkm/topk) ----
    gemm3_hmma<<<dim3(4, 256, 1), 256, GSMEM_BYTES, s2>>>(inQ, inK, inV, 2);
    cudaEventRecord(evV, s2);
    vmean_kernel<<<BH_, 256, 0, s2>>>();
    obase_kernel<<<B_, 256, 0, s2>>>(Wfc);
    out_assemble<<<(B_ * L_ * DM_ / 4) / 256, 256, 0, s2>>>(inQ, out);
    cudaEventRecord(evOA, s2);

    // ---- main: sparsity measure + top-k ----
    qkm3_kernel<<<(B_ * L_ * 32) / 256, 256>>>(isamp);
    topkA_kernel<<<dim3(8, BH_), 256>>>();
    topkB_kernel<<<BH_, 256>>>();

    // ---- main: attention (needs g_V from s2) ----
    cudaStreamWaitEvent(0, evV, 0);
    attn_partial<<<dim3(NCH_, BH_), 256>>>();
    attn_combine<<<(BH_ * U_ * 32 + 255) / 256, 256>>>();

    // ---- main: corrections into out (needs out_assemble from s2) ----
    cudaStreamWaitEvent(0, evOA, 0);
    correction_kernel<<<BH_ * U_, 128>>>(out, Wfc);

    // ---- layernorm ----
    ln_kernel<<<(B_ * L_), 128>>>(out, gamma, beta);
}

// round 10
// speedup vs baseline: 2.4302x; 1.1279x over previous
#include <cuda_runtime.h>
#include <math_constants.h>
#include <cstdint>

#define B_    8
#define L_    4096
#define DM_   512
#define H_    8
#define DK_   64
#define DV_   64
#define U_    41
#define BH_   (B_*H_)
#define NCH_  8
#define NCH2_ 16                      // NCH * 2 lane-groups
#define CHUNK_ (L_/NCH_)
#define PREC_ 68                      // partial record stride (floats), 16B-aligned
#define EPS_  1e-5f

// ---------------- scratch ----------------------------------------------------
__device__ float g_Q[B_*L_*DM_];
__device__ float g_K[B_*L_*DM_];
__device__ float g_V[B_*L_*DM_];
__device__ float g_Wt[3*DM_*DM_];
__device__ float g_M[BH_*L_];
__device__ int   g_idx[BH_*U_];
__device__ float g_cval[BH_*8*U_];
__device__ int   g_cidx[BH_*8*U_];
__device__ float g_vals[BH_*U_*DV_];
__device__ float g_vmean[BH_*DV_];
__device__ float g_obase[B_*DM_];
__device__ __align__(16) float g_part[BH_*NCH2_*U_*PREC_];

// ---------------- helpers ------------------------------------------------------
__device__ __forceinline__ uint32_t smem_u32(const void* p) {
    uint32_t a;
    asm("{ .reg .u64 t; cvta.to.shared.u64 t, %1; cvt.u32.u64 %0, t; }" : "=r"(a) : "l"(p));
    return a;
}
#define CP_ASYNC_CG(dst, src) \
    asm volatile("cp.async.cg.shared.global [%0], [%1], 16;" :: "r"(dst), "l"(src) : "memory")
#define CP_COMMIT() asm volatile("cp.async.commit_group;" ::: "memory")
#define CP_WAIT1()  asm volatile("cp.async.wait_group 1;" ::: "memory")
#define CP_WAIT0()  asm volatile("cp.async.wait_group 0;" ::: "memory")

__device__ __forceinline__ uint32_t packbf(float e0, float e1) {
    uint32_t r;
    asm("cvt.rn.bf16x2.f32 %0, %1, %2;" : "=r"(r) : "f"(e1), "f"(e0));
    return r;
}
__device__ __forceinline__ void splitbf(float2 x, uint32_t& h, uint32_t& l) {
    h = packbf(x.x, x.y);
    float r0 = x.x - __uint_as_float(h << 16);
    float r1 = x.y - __uint_as_float(h & 0xffff0000u);
    l = packbf(r0, r1);
}

#define MMA_BF16(c, a, b) \
    asm volatile("mma.sync.aligned.m16n8k16.row.col.f32.bf16.bf16.f32 " \
        "{%0,%1,%2,%3}, {%4,%5,%6,%7}, {%8,%9}, {%0,%1,%2,%3};" \
        : "+f"((c)[0]), "+f"((c)[1]), "+f"((c)[2]), "+f"((c)[3]) \
        : "r"((a)[0]), "r"((a)[1]), "r"((a)[2]), "r"((a)[3]), \
          "r"((b)[0]), "r"((b)[1]))

// ---------------- W transpose (fp32 only), all 3 weights ------------------------
__global__ __launch_bounds__(256) void transW_kernel(
    const float* __restrict__ W0, const float* __restrict__ W1,
    const float* __restrict__ W2)
{
    __shared__ float tile[32][33];
    const float* W = (blockIdx.z == 0) ? W0 : (blockIdx.z == 1) ? W1 : W2;
    float* dst = g_Wt + (size_t)blockIdx.z * DM_ * DM_;
    int bx = blockIdx.x * 32;
    int by = blockIdx.y * 32;
    int tx = threadIdx.x & 31, ty = threadIdx.x >> 5;
#pragma unroll
    for (int i = 0; i < 4; i++)
        tile[ty + 8 * i][tx] = __ldg(&W[(size_t)(by + ty + 8 * i) * 512 + bx + tx]);
    __syncthreads();
#pragma unroll
    for (int i = 0; i < 4; i++)
        dst[(size_t)(bx + ty + 8 * i) * 512 + by + tx] = tile[tx][ty + 8 * i];
}

// ---------------- HMMA bf16 GEMM, fused in-register hi/lo split ------------------
#define PADK 40
#define MATF (128 * PADK)
#define STAGEF (2 * MATF)
#define GSMEM_BYTES (2 * STAGEF * 4)

__device__ __forceinline__ void g_load_stage(
    float* sm, int stage, int c, int tid,
    const float* __restrict__ A, const float* __restrict__ Bt)
{
    float* dst = sm + stage * STAGEF;
#pragma unroll
    for (int i = 0; i < 4; i++) {
        int idx = i * 256 + tid;
        int row = idx >> 3, q = idx & 7;
        CP_ASYNC_CG(smem_u32(dst + row * PADK + q * 4),
                    A + (size_t)row * 512 + c * 32 + q * 4);
    }
#pragma unroll
    for (int i = 0; i < 4; i++) {
        int idx = i * 256 + tid;
        int row = idx >> 3, q = idx & 7;
        CP_ASYNC_CG(smem_u32(dst + MATF + row * PADK + q * 4),
                    Bt + (size_t)row * 512 + c * 32 + q * 4);
    }
    CP_COMMIT();
}

__global__ __launch_bounds__(256, 1) void gemm3_hmma(
    const float* __restrict__ inQ, const float* __restrict__ inK,
    const float* __restrict__ inV, int base, int rowbase)
{
    extern __shared__ float sm[];
    const int tid = threadIdx.x;
    const int wid = tid >> 5, lane = tid & 31;
    const int g = lane >> 2, tg = lane & 3;
    const int wm = wid & 1, wn = wid >> 1;
    const int row0 = rowbase + blockIdx.y * 128, col0 = blockIdx.x * 128;
    const int which = base + blockIdx.z;
    const bool full = (which != 2);

    const float* Asrc = (which == 0) ? inQ : (which == 1) ? inK : inV;
    const float* A  = Asrc + (size_t)row0 * 512;
    const float* Bt = g_Wt + (size_t)which * DM_ * DM_ + (size_t)col0 * 512;
    float* C = (which == 0) ? g_Q : (which == 1) ? g_K : g_V;

    float acc[4][4][4];
#pragma unroll
    for (int i = 0; i < 4; i++)
#pragma unroll
        for (int j = 0; j < 4; j++)
#pragma unroll
            for (int r = 0; r < 4; r++) acc[i][j][r] = 0.f;

    g_load_stage(sm, 0, 0, tid, A, Bt);

    for (int c = 0; c < 16; c++) {
        const int buf = c & 1;
        if (c < 15) g_load_stage(sm, buf ^ 1, c + 1, tid, A, Bt);
        if (c < 15) { CP_WAIT1(); } else { CP_WAIT0(); }
        __syncthreads();

        const float* sA = sm + buf * STAGEF;
        const float* sB = sA + MATF;

#pragma unroll
        for (int ks = 0; ks < 2; ks++) {
            const int k0 = ks * 16;
            uint32_t ah[4][4], al[4][4], bh[4][2], bl[4][2];
#pragma unroll
            for (int i = 0; i < 4; i++) {
                int r = wm * 64 + i * 16 + g;
                float2 x0 = *(const float2*)&sA[r * PADK + k0 + 2 * tg];
                float2 x1 = *(const float2*)&sA[(r + 8) * PADK + k0 + 2 * tg];
                float2 x2 = *(const float2*)&sA[r * PADK + k0 + 2 * tg + 8];
                float2 x3 = *(const float2*)&sA[(r + 8) * PADK + k0 + 2 * tg + 8];
                if (full) {
                    splitbf(x0, ah[i][0], al[i][0]);
                    splitbf(x1, ah[i][1], al[i][1]);
                    splitbf(x2, ah[i][2], al[i][2]);
                    splitbf(x3, ah[i][3], al[i][3]);
                } else {
                    ah[i][0] = packbf(x0.x, x0.y);
                    ah[i][1] = packbf(x1.x, x1.y);
                    ah[i][2] = packbf(x2.x, x2.y);
                    ah[i][3] = packbf(x3.x, x3.y);
                }
            }
#pragma unroll
            for (int j = 0; j < 4; j++) {
                int n = wn * 32 + j * 8 + g;
                float2 y0 = *(const float2*)&sB[n * PADK + k0 + 2 * tg];
                float2 y1 = *(const float2*)&sB[n * PADK + k0 + 2 * tg + 8];
                if (full) {
                    splitbf(y0, bh[j][0], bl[j][0]);
                    splitbf(y1, bh[j][1], bl[j][1]);
                } else {
                    bh[j][0] = packbf(y0.x, y0.y);
                    bh[j][1] = packbf(y1.x, y1.y);
                }
            }
#pragma unroll
            for (int i = 0; i < 4; i++)
#pragma unroll
                for (int j = 0; j < 4; j++) MMA_BF16(acc[i][j], ah[i], bh[j]);
            if (full) {
#pragma unroll
                for (int i = 0; i < 4; i++)
#pragma unroll
                    for (int j = 0; j < 4; j++) MMA_BF16(acc[i][j], ah[i], bl[j]);
#pragma unroll
                for (int i = 0; i < 4; i++)
#pragma unroll
                    for (int j = 0; j < 4; j++) MMA_BF16(acc[i][j], al[i], bh[j]);
            }
        }
        __syncthreads();
    }

#pragma unroll
    for (int i = 0; i < 4; i++) {
#pragma unroll
        for (int j = 0; j < 4; j++) {
            int row = row0 + wm * 64 + i * 16 + g;
            int col = col0 + wn * 32 + j * 8 + tg * 2;
            float2 v0 = make_float2(acc[i][j][0], acc[i][j][1]);
            float2 v1 = make_float2(acc[i][j][2], acc[i][j][3]);
            *(float2*)(C + (size_t)row * 512 + col) = v0;
            *(float2*)(C + (size_t)(row + 8) * 512 + col) = v1;
        }
    }
}

// ---------------- QK_samp -> M (batch-sliced for pipelining) ---------------------
__global__ __launch_bounds__(256) void qkm3_kernel(const int* __restrict__ isamp,
                                                   int boff)
{
    int gw   = ((boff + blockIdx.x) * 256 + threadIdx.x) >> 5;
    int lane = threadIdx.x & 31;
    int l = gw & (L_ - 1);
    int b = gw >> 12;

    const float4* qb = (const float4*)(g_Q + ((size_t)(b * L_ + l)) * DM_);
    float4 q0 = qb[lane], q1 = qb[lane + 32], q2 = qb[lane + 64], q3 = qb[lane + 96];

    float smax0 = -CUDART_INF_F, smax1 = -CUDART_INF_F, smax2 = -CUDART_INF_F, smax3 = -CUDART_INF_F;
    float ssum0 = 0.f, ssum1 = 0.f, ssum2 = 0.f, ssum3 = 0.f;
    const int* ip = isamp + l * U_;

#pragma unroll 2
    for (int u = 0; u < U_; u++) {
        int j = __ldg(ip + u);
        const float4* kb = (const float4*)(g_K + ((size_t)(b * L_ + j)) * DM_);
        float4 k0 = kb[lane], k1 = kb[lane + 32], k2 = kb[lane + 64], k3 = kb[lane + 96];
        float s0 = q0.x * k0.x; s0 = fmaf(q0.y, k0.y, s0); s0 = fmaf(q0.z, k0.z, s0); s0 = fmaf(q0.w, k0.w, s0);
        float s1 = q1.x * k1.x; s1 = fmaf(q1.y, k1.y, s1); s1 = fmaf(q1.z, k1.z, s1); s1 = fmaf(q1.w, k1.w, s1);
        float s2 = q2.x * k2.x; s2 = fmaf(q2.y, k2.y, s2); s2 = fmaf(q2.z, k2.z, s2); s2 = fmaf(q2.w, k2.w, s2);
        float s3 = q3.x * k3.x; s3 = fmaf(q3.y, k3.y, s3); s3 = fmaf(q3.z, k3.z, s3); s3 = fmaf(q3.w, k3.w, s3);
#pragma unroll
        for (int m = 1; m <= 8; m <<= 1) {
            s0 += __shfl_xor_sync(0xffffffffu, s0, m);
            s1 += __shfl_xor_sync(0xffffffffu, s1, m);
            s2 += __shfl_xor_sync(0xffffffffu, s2, m);
            s3 += __shfl_xor_sync(0xffffffffu, s3, m);
        }
        smax0 = fmaxf(smax0, s0); ssum0 += s0;
        smax1 = fmaxf(smax1, s1); ssum1 += s1;
        smax2 = fmaxf(smax2, s2); ssum2 += s2;
        smax3 = fmaxf(smax3, s3); ssum3 += s3;
    }
    if ((lane & 15) == 0) {
        int g = lane >> 4;
        size_t base = ((size_t)b * 8) * L_ + l;
        g_M[base + (size_t)(g + 0) * L_] = smax0 - ssum0 * (1.0f / U_);
        g_M[base + (size_t)(g + 2) * L_] = smax1 - ssum1 * (1.0f / U_);
        g_M[base + (size_t)(g + 4) * L_] = smax2 - ssum2 * (1.0f / U_);
        g_M[base + (size_t)(g + 6) * L_] = smax3 - ssum3 * (1.0f / U_);
    }
}

// ---------------- top-k phase A: per-slice local top-41 -------------------------
__global__ __launch_bounds__(256) void topkA_kernel()
{
    int slice = blockIdx.x, bh = blockIdx.y;
    __shared__ float sv[512];
    __shared__ float wv[8];
    __shared__ int   wi[8];
    int tid = threadIdx.x, lane = tid & 31, w = tid >> 5;

    sv[tid]       = g_M[bh * L_ + slice * 512 + tid];
    sv[tid + 256] = g_M[bh * L_ + slice * 512 + tid + 256];
    __syncthreads();

    for (int it = 0; it < U_; it++) {
        float v0 = sv[tid], v1 = sv[tid + 256];
        float bv; int bi;
        if (v1 > v0) { bv = v1; bi = tid + 256; } else { bv = v0; bi = tid; }
#pragma unroll
        for (int o = 16; o > 0; o >>= 1) {
            float ov = __shfl_xor_sync(0xffffffffu, bv, o);
            int   oi = __shfl_xor_sync(0xffffffffu, bi, o);
            if (ov > bv || (ov == bv && oi < bi)) { bv = ov; bi = oi; }
        }
        if (lane == 0) { wv[w] = bv; wi[w] = bi; }
        __syncthreads();
        if (tid == 0) {
            float fv = wv[0]; int fi = wi[0];
#pragma unroll
            for (int k = 1; k < 8; k++) {
                if (wv[k] > fv || (wv[k] == fv && wi[k] < fi)) { fv = wv[k]; fi = wi[k]; }
            }
            sv[fi] = -CUDART_INF_F;
            g_cval[(bh * 8 + slice) * U_ + it] = fv;
            g_cidx[(bh * 8 + slice) * U_ + it] = slice * 512 + fi;
        }
        __syncthreads();
    }
}

// ---------------- top-k phase B: merge 8x41 candidates --------------------------
__global__ __launch_bounds__(256) void topkB_kernel()
{
    int bh = blockIdx.x;
    __shared__ float sv[512];
    __shared__ int   si[512];
    __shared__ float wv[8];
    __shared__ int   wi[8];
    int tid = threadIdx.x, lane = tid & 31, w = tid >> 5;

    const int NC = 8 * U_;
#pragma unroll
    for (int r = 0; r < 2; r++) {
        int i = tid + 256 * r;
        if (i < NC) {
            sv[i] = g_cval[bh * NC + i];
            si[i] = g_cidx[bh * NC + i];
        } else if (i < 512) {
            sv[i] = -CUDART_INF_F;
            si[i] = 0x7fffffff;
        }
    }
    __syncthreads();

    for (int it = 0; it < U_; it++) {
        float v0 = sv[tid], v1 = sv[tid + 256];
        int   i0 = si[tid], i1 = si[tid + 256];
        float bv; int bi, bslot;
        if (v1 > v0 || (v1 == v0 && i1 < i0)) { bv = v1; bi = i1; bslot = tid + 256; }
        else                                   { bv = v0; bi = i0; bslot = tid; }
#pragma unroll
        for (int o = 16; o > 0; o >>= 1) {
            float ov = __shfl_xor_sync(0xffffffffu, bv, o);
            int   oi = __shfl_xor_sync(0xffffffffu, bi, o);
            int   os = __shfl_xor_sync(0xffffffffu, bslot, o);
            if (ov > bv || (ov == bv && oi < bi)) { bv = ov; bi = oi; bslot = os; }
        }
        if (lane == 0) { wv[w] = bv; wi[w] = bslot; }
        __syncthreads();
        if (tid == 0) {
            float fv = wv[0]; int fslot = wi[0];
#pragma unroll
            for (int k = 1; k < 8; k++) {
                int s2 = wi[k];
                if (wv[k] > fv || (wv[k] == fv && si[s2] < si[fslot])) { fv = wv[k]; fslot = s2; }
            }
            g_idx[bh * U_ + it] = si[fslot];
            sv[fslot] = -CUDART_INF_F;
            si[fslot] = 0x7fffffff;
        }
        __syncthreads();
    }
}

// ---------------- V mean per (b,h) -----------------------------------------------
__global__ __launch_bounds__(256) void vmean_kernel()
{
    int bh = blockIdx.x;
    int b = bh >> 3, h = bh & 7;
    int tid = threadIdx.x;
    int d = tid & 63, g = tid >> 6;
    float sum = 0.f;
    for (int l = g; l < L_; l += 4)
        sum += g_V[((size_t)(b * L_ + l)) * DM_ + h * DK_ + d];
    __shared__ float red[4][64];
    red[g][d] = sum;
    __syncthreads();
    if (g == 0) {
        float t = red[0][d] + red[1][d] + red[2][d] + red[3][d];
        g_vmean[bh * 64 + d] = t * (1.0f / L_);
    }
}

// ---------------- sparse attention: 16-lane groups, 2 keys per warp-step ----------
// partial record layout (stride PREC_=68): [acc[64], m, s, pad, pad] -> float4-aligned
__global__ __launch_bounds__(256) void attn_partial()
{
    int ch = blockIdx.x, bh = blockIdx.y;
    int b = bh >> 3, h = bh & 7;
    int tid = threadIdx.x, lane = tid & 31, w = tid >> 5;
    int grp = lane >> 4, l4 = lane & 15;

    __shared__ float qs[U_ * DK_];
    __shared__ float Ks[64 * 68];
    __shared__ float Vs[64 * 68];

    for (int i = tid; i < U_ * DK_; i += 256) {
        int u = i >> 6, d = i & 63;
        int l = g_idx[bh * U_ + u];
        qs[i] = g_Q[((size_t)(b * L_ + l)) * DM_ + h * DK_ + d];
    }
    __syncthreads();

    const int nu = (w == 0) ? 6 : 5;
    float4 q4[6], a4[6];
    float m[6], ss[6];
#pragma unroll
    for (int k = 0; k < 6; k++) {
        if (k < nu) {
            int u = w + 8 * k;
            q4[k] = *(const float4*)&qs[u * 64 + 4 * l4];
        } else {
            q4[k] = make_float4(0.f, 0.f, 0.f, 0.f);
        }
        m[k] = -CUDART_INF_F; ss[k] = 0.f;
        a4[k] = make_float4(0.f, 0.f, 0.f, 0.f);
    }

    const int jbase0 = ch * CHUNK_;
    for (int t = 0; t < CHUNK_ / 64; t++) {
        __syncthreads();
        int jb = jbase0 + t * 64;
        const float4* Kg = (const float4*)(g_K + ((size_t)(b * L_ + jb)) * DM_ + h * DK_);
        const float4* Vg = (const float4*)(g_V + ((size_t)(b * L_ + jb)) * DM_ + h * DK_);
#pragma unroll
        for (int r = 0; r < 4; r++) {
            int idx = tid + 256 * r;
            int row = idx >> 4, cq = idx & 15;
            float4 kv = Kg[(size_t)row * (DM_ / 4) + cq];
            *(float4*)&Ks[row * 68 + cq * 4] = kv;
            float4 vv = Vg[(size_t)row * (DM_ / 4) + cq];
            *(float4*)&Vs[row * 68 + cq * 4] = vv;
        }
        __syncthreads();

#pragma unroll 2
        for (int jj2 = 0; jj2 < 32; jj2++) {
            int jj = jj2 * 2 + grp;                      // group-private key
            float4 k4 = *(const float4*)&Ks[jj * 68 + 4 * l4];
            float4 v4 = *(const float4*)&Vs[jj * 68 + 4 * l4];
            float sc[6];
#pragma unroll
            for (int k = 0; k < 6; k++) {
                float s = q4[k].x * k4.x;
                s = fmaf(q4[k].y, k4.y, s);
                s = fmaf(q4[k].z, k4.z, s);
                s = fmaf(q4[k].w, k4.w, s);
                sc[k] = s;
            }
#pragma unroll
            for (int o = 1; o <= 8; o <<= 1) {
#pragma unroll
                for (int k = 0; k < 6; k++)
                    sc[k] += __shfl_xor_sync(0xffffffffu, sc[k], o);
            }
#pragma unroll
            for (int k = 0; k < 6; k++) {
                float s = sc[k] * 0.125f;
                float mn = fmaxf(m[k], s);
                float ea = __expf(s - mn);
                float eb = __expf(m[k] - mn);
                ss[k] = ss[k] * eb + ea;
                a4[k].x = a4[k].x * eb + ea * v4.x;
                a4[k].y = a4[k].y * eb + ea * v4.y;
                a4[k].z = a4[k].z * eb + ea * v4.z;
                a4[k].w = a4[k].w * eb + ea * v4.w;
                m[k] = mn;
            }
        }
    }

    const int c2 = ch * 2 + grp;                        // 16 partial chunks
#pragma unroll
    for (int k = 0; k < 6; k++) {
        if (k < nu) {
            int u = w + 8 * k;
            size_t base = ((size_t)(bh * NCH2_ + c2) * U_ + u) * PREC_;
            *(float4*)&g_part[base + 4 * l4] = a4[k];   // acc at offset 0: aligned
            if (l4 == 0) { g_part[base + 64] = m[k]; g_part[base + 65] = ss[k]; }
        }
    }
}

// ---------------- combine split-L partials ----------------------------------------
__global__ __launch_bounds__(256) void attn_combine()
{
    int gw = (blockIdx.x * blockDim.x + threadIdx.x) >> 5;
    int lane = threadIdx.x & 31;
    if (gw >= BH_ * U_) return;
    int bh = gw / U_, u = gw % U_;

    float M = -CUDART_INF_F;
#pragma unroll
    for (int ch = 0; ch < NCH2_; ch++)
        M = fmaxf(M, g_part[((size_t)(bh * NCH2_ + ch) * U_ + u) * PREC_ + 64]);
    float S = 0.f, a0 = 0.f, a1 = 0.f;
#pragma unroll
    for (int ch = 0; ch < NCH2_; ch++) {
        size_t base = ((size_t)(bh * NCH2_ + ch) * U_ + u) * PREC_;
        float f = __expf(g_part[base + 64] - M);
        S  += g_part[base + 65] * f;
        a0 += g_part[base + 2 * lane] * f;
        a1 += g_part[base + 2 * lane + 1] * f;
    }
    float inv = 1.0f / S;
    g_vals[(size_t)gw * 64 + 2 * lane]     = a0 * inv;
    g_vals[(size_t)gw * 64 + 2 * lane + 1] = a1 * inv;
}

// ---------------- low-rank output path ---------------------------------------------
__global__ __launch_bounds__(256) void obase_kernel(const float* __restrict__ Wfc)
{
    int b = blockIdx.x, tid = threadIdx.x;
    __shared__ float vm[512];
    vm[tid]       = g_vmean[b * 512 + tid];
    vm[tid + 256] = g_vmean[b * 512 + tid + 256];
    __syncthreads();
    float a0 = 0.f, a1 = 0.f;
    const float2* W2 = (const float2*)Wfc + tid;
#pragma unroll 8
    for (int r = 0; r < 512; r++) {
        float2 w = __ldg(W2 + (size_t)r * 256);
        float v = vm[r];
        a0 = fmaf(v, w.x, a0);
        a1 = fmaf(v, w.y, a1);
    }
    g_obase[b * 512 + 2 * tid]     = a0;
    g_obase[b * 512 + 2 * tid + 1] = a1;
}

__global__ __launch_bounds__(256) void out_assemble(const float* __restrict__ inQ,
                                                    float* __restrict__ out)
{
    int i4 = blockIdx.x * 256 + threadIdx.x;
    int b  = i4 >> 19;
    int c4 = i4 & 127;
    float4 x = ((const float4*)inQ)[i4];
    float4 o = __ldg((const float4*)g_obase + (b << 7) + c4);
    x.x += o.x; x.y += o.y; x.z += o.z; x.w += o.w;
    ((float4*)out)[i4] = x;
}

__global__ __launch_bounds__(128) void correction_kernel(float* __restrict__ out,
                                                         const float* __restrict__ Wfc)
{
    int gu = blockIdx.x;
    int bh = gu / U_;
    int b = bh >> 3, h = bh & 7;
    int l = g_idx[gu];
    int tid = threadIdx.x;

    __shared__ float delta[64];
    if (tid < 64)
        delta[tid] = g_vals[(size_t)gu * 64 + tid] - g_vmean[bh * 64 + tid];
    __syncthreads();

    float4 acc = make_float4(0.f, 0.f, 0.f, 0.f);
    const float4* W4 = (const float4*)Wfc + (size_t)(h * 64) * 128 + tid;
#pragma unroll 8
    for (int k = 0; k < 64; k++) {
        float d = delta[k];
        float4 w = __ldg(W4 + (size_t)k * 128);
        acc.x = fmaf(d, w.x, acc.x);
        acc.y = fmaf(d, w.y, acc.y);
        acc.z = fmaf(d, w.z, acc.z);
        acc.w = fmaf(d, w.w, acc.w);
    }
    float* o = out + ((size_t)(b * L_ + l)) * 512 + tid * 4;
    atomicAdd(o + 0, acc.x);
    atomicAdd(o + 1, acc.y);
    atomicAdd(o + 2, acc.z);
    atomicAdd(o + 3, acc.w);
}

// ---------------- LayerNorm -----------------------------------------------------------
__global__ __launch_bounds__(128) void ln_kernel(float* __restrict__ out,
                                                 const float* __restrict__ gamma,
                                                 const float* __restrict__ beta)
{
    int row = blockIdx.x, tid = threadIdx.x;
    float4 x = ((const float4*)out)[(size_t)row * 128 + tid];
    float s  = x.x + x.y + x.z + x.w;
    float sq = x.x * x.x + x.y * x.y + x.z * x.z + x.w * x.w;
#pragma unroll
    for (int o = 16; o > 0; o >>= 1) {
        s  += __shfl_xor_sync(0xffffffffu, s, o);
        sq += __shfl_xor_sync(0xffffffffu, sq, o);
    }
    __shared__ float sh[8];
    int w = tid >> 5, lane = tid & 31;
    if (lane == 0) { sh[w] = s; sh[4 + w] = sq; }
    __syncthreads();
    s  = sh[0] + sh[1] + sh[2] + sh[3];
    sq = sh[4] + sh[5] + sh[6] + sh[7];
    float mu  = s * (1.0f / 512.0f);
    float var = sq * (1.0f / 512.0f) - mu * mu;
    float r   = rsqrtf(var + EPS_);
    float4 gg = ((const float4*)gamma)[tid];
    float4 bb = ((const float4*)beta)[tid];
    float4 y;
    y.x = gg.x * (x.x - mu) * r + bb.x;
    y.y = gg.y * (x.y - mu) * r + bb.y;
    y.z = gg.z * (x.z - mu) * r + bb.z;
    y.w = gg.w * (x.w - mu) * r + bb.w;
    ((float4*)out)[(size_t)row * 128 + tid] = y;
}

// ---------------- launch ------------------------------------------------------------
extern "C" void kernel_launch(void* const* d_in, const int* in_sizes, int n_in,
                              void* d_out, int out_size)
{
    const float* inQ   = (const float*)d_in[0];
    const float* inK   = (const float*)d_in[1];
    const float* inV   = (const float*)d_in[2];
    const float* WQ    = (const float*)d_in[3];
    const float* WK    = (const float*)d_in[4];
    const float* WV    = (const float*)d_in[5];
    const float* Wfc   = (const float*)d_in[6];
    const float* gamma = (const float*)d_in[7];
    const float* beta  = (const float*)d_in[8];
    const int*   isamp = (const int*)d_in[9];
    float* out = (float*)d_out;

    static cudaStream_t s2, s3;
    static cudaEvent_t evFork, evV, evOA, evGa, evQa;
    static bool init = false;
    if (!init) {
        cudaStreamCreateWithFlags(&s2, cudaStreamNonBlocking);
        cudaStreamCreateWithFlags(&s3, cudaStreamNonBlocking);
        cudaEventCreateWithFlags(&evFork, cudaEventDisableTiming);
        cudaEventCreateWithFlags(&evV, cudaEventDisableTiming);
        cudaEventCreateWithFlags(&evOA, cudaEventDisableTiming);
        cudaEventCreateWithFlags(&evGa, cudaEventDisableTiming);
        cudaEventCreateWithFlags(&evQa, cudaEventDisableTiming);
        cudaFuncSetAttribute(gemm3_hmma, cudaFuncAttributeMaxDynamicSharedMemorySize,
                             GSMEM_BYTES);
        init = true;
    }

    // ---- main: weight transpose, then fork V branch ----
    transW_kernel<<<dim3(16, 16, 3), 256>>>(WQ, WK, WV);
    cudaEventRecord(evFork, 0);
    cudaStreamWaitEvent(s2, evFork, 0);

    // ---- s2: V projection branch ----
    gemm3_hmma<<<dim3(4, 256, 1), 256, GSMEM_BYTES, s2>>>(inQ, inK, inV, 2, 0);
    cudaEventRecord(evV, s2);
    vmean_kernel<<<BH_, 256, 0, s2>>>();
    obase_kernel<<<B_, 256, 0, s2>>>(Wfc);
    out_assemble<<<(B_ * L_ * DM_ / 4) / 256, 256, 0, s2>>>(inQ, out);
    cudaEventRecord(evOA, s2);

    // ---- main: Q,K projections batches 0-3 -> fork qkm_a onto s3 ----
    gemm3_hmma<<<dim3(4, 128, 2), 256, GSMEM_BYTES>>>(inQ, inK, inV, 0, 0);
    cudaEventRecord(evGa, 0);
    cudaStreamWaitEvent(s3, evGa, 0);

    // ---- s3: qkm for batches 0-3 (overlaps gemmQK batches 4-7) ----
    qkm3_kernel<<<2048, 256, 0, s3>>>(isamp, 0);
    cudaEventRecord(evQa, s3);

    // ---- main: Q,K projections batches 4-7, then qkm batches 4-7 ----
    gemm3_hmma<<<dim3(4, 128, 2), 256, GSMEM_BYTES>>>(inQ, inK, inV, 0, 16384);
    qkm3_kernel<<<2048, 256>>>(isamp, 2048);

    // ---- main: top-k (needs all g_M) ----
    cudaStreamWaitEvent(0, evQa, 0);
    topkA_kernel<<<dim3(8, BH_), 256>>>();
    topkB_kernel<<<BH_, 256>>>();

    // ---- main: attention (needs g_V) ----
    cudaStreamWaitEvent(0, evV, 0);
    attn_partial<<<dim3(NCH_, BH_), 256>>>();
    attn_combine<<<(BH_ * U_ * 32 + 255) / 256, 256>>>();

    // ---- main: corrections (needs out_assemble) ----
    cudaStreamWaitEvent(0, evOA, 0);
    correction_kernel<<<BH_ * U_, 128>>>(out, Wfc);

    // ---- layernorm ----
    ln_kernel<<<(B_ * L_), 128>>>(out, gamma, beta);
}

// round 11
// speedup vs baseline: 2.5495x; 1.0491x over previous
#include <cuda_runtime.h>
#include <math_constants.h>
#include <cstdint>

#define B_    8
#define L_    4096
#define DM_   512
#define H_    8
#define DK_   64
#define DV_   64
#define U_    41
#define BH_   (B_*H_)
#define NCH_  8
#define NCH2_ 16
#define CHUNK_ (L_/NCH_)
#define PREC_ 68
#define EPS_  1e-5f

// ---------------- scratch ----------------------------------------------------
__device__ float g_Q[B_*L_*DM_];
__device__ float g_K[B_*L_*DM_];
__device__ float g_V[B_*L_*DM_];
__device__ float g_Wt[3*DM_*DM_];
__device__ float g_M[BH_*L_];
__device__ int   g_idx[BH_*U_];
__device__ float g_cval[BH_*8*U_];
__device__ int   g_cidx[BH_*8*U_];
__device__ float g_vals[BH_*U_*DV_];
__device__ float g_vmean[BH_*DV_];
__device__ float g_obase[B_*DM_];
__device__ __align__(16) float g_part[BH_*NCH2_*U_*PREC_];

// ---------------- helpers ------------------------------------------------------
__device__ __forceinline__ uint32_t smem_u32(const void* p) {
    uint32_t a;
    asm("{ .reg .u64 t; cvta.to.shared.u64 t, %1; cvt.u32.u64 %0, t; }" : "=r"(a) : "l"(p));
    return a;
}
#define CP_ASYNC_CG(dst, src) \
    asm volatile("cp.async.cg.shared.global [%0], [%1], 16;" :: "r"(dst), "l"(src) : "memory")
#define CP_COMMIT() asm volatile("cp.async.commit_group;" ::: "memory")
#define CP_WAIT1()  asm volatile("cp.async.wait_group 1;" ::: "memory")
#define CP_WAIT0()  asm volatile("cp.async.wait_group 0;" ::: "memory")

__device__ __forceinline__ uint32_t packbf(float e0, float e1) {
    uint32_t r;
    asm("cvt.rn.bf16x2.f32 %0, %1, %2;" : "=r"(r) : "f"(e1), "f"(e0));
    return r;
}
__device__ __forceinline__ void splitbf(float2 x, uint32_t& h, uint32_t& l) {
    h = packbf(x.x, x.y);
    float r0 = x.x - __uint_as_float(h << 16);
    float r1 = x.y - __uint_as_float(h & 0xffff0000u);
    l = packbf(r0, r1);
}

#define MMA_BF16(c, a, b) \
    asm volatile("mma.sync.aligned.m16n8k16.row.col.f32.bf16.bf16.f32 " \
        "{%0,%1,%2,%3}, {%4,%5,%6,%7}, {%8,%9}, {%0,%1,%2,%3};" \
        : "+f"((c)[0]), "+f"((c)[1]), "+f"((c)[2]), "+f"((c)[3]) \
        : "r"((a)[0]), "r"((a)[1]), "r"((a)[2]), "r"((a)[3]), \
          "r"((b)[0]), "r"((b)[1]))

// ---------------- W transpose (fp32 only), all 3 weights ------------------------
__global__ __launch_bounds__(256) void transW_kernel(
    const float* __restrict__ W0, const float* __restrict__ W1,
    const float* __restrict__ W2)
{
    __shared__ float tile[32][33];
    const float* W = (blockIdx.z == 0) ? W0 : (blockIdx.z == 1) ? W1 : W2;
    float* dst = g_Wt + (size_t)blockIdx.z * DM_ * DM_;
    int bx = blockIdx.x * 32;
    int by = blockIdx.y * 32;
    int tx = threadIdx.x & 31, ty = threadIdx.x >> 5;
#pragma unroll
    for (int i = 0; i < 4; i++)
        tile[ty + 8 * i][tx] = __ldg(&W[(size_t)(by + ty + 8 * i) * 512 + bx + tx]);
    __syncthreads();
#pragma unroll
    for (int i = 0; i < 4; i++)
        dst[(size_t)(bx + ty + 8 * i) * 512 + by + tx] = tile[tx][ty + 8 * i];
}

// ---------------- HMMA bf16 GEMM, fused in-register hi/lo split ------------------
#define PADK 40
#define MATF (128 * PADK)
#define STAGEF (2 * MATF)
#define GSMEM_BYTES (2 * STAGEF * 4)

__device__ __forceinline__ void g_load_stage(
    float* sm, int stage, int c, int tid,
    const float* __restrict__ A, const float* __restrict__ Bt)
{
    float* dst = sm + stage * STAGEF;
#pragma unroll
    for (int i = 0; i < 4; i++) {
        int idx = i * 256 + tid;
        int row = idx >> 3, q = idx & 7;
        CP_ASYNC_CG(smem_u32(dst + row * PADK + q * 4),
                    A + (size_t)row * 512 + c * 32 + q * 4);
    }
#pragma unroll
    for (int i = 0; i < 4; i++) {
        int idx = i * 256 + tid;
        int row = idx >> 3, q = idx & 7;
        CP_ASYNC_CG(smem_u32(dst + MATF + row * PADK + q * 4),
                    Bt + (size_t)row * 512 + c * 32 + q * 4);
    }
    CP_COMMIT();
}

__global__ __launch_bounds__(256, 1) void gemm3_hmma(
    const float* __restrict__ inQ, const float* __restrict__ inK,
    const float* __restrict__ inV, int base, int rowbase)
{
    extern __shared__ float sm[];
    const int tid = threadIdx.x;
    const int wid = tid >> 5, lane = tid & 31;
    const int g = lane >> 2, tg = lane & 3;
    const int wm = wid & 1, wn = wid >> 1;
    const int row0 = rowbase + blockIdx.y * 128, col0 = blockIdx.x * 128;
    const int which = base + blockIdx.z;
    const bool full = (which != 2);

    const float* Asrc = (which == 0) ? inQ : (which == 1) ? inK : inV;
    const float* A  = Asrc + (size_t)row0 * 512;
    const float* Bt = g_Wt + (size_t)which * DM_ * DM_ + (size_t)col0 * 512;
    float* C = (which == 0) ? g_Q : (which == 1) ? g_K : g_V;

    float acc[4][4][4];
#pragma unroll
    for (int i = 0; i < 4; i++)
#pragma unroll
        for (int j = 0; j < 4; j++)
#pragma unroll
            for (int r = 0; r < 4; r++) acc[i][j][r] = 0.f;

    g_load_stage(sm, 0, 0, tid, A, Bt);

    for (int c = 0; c < 16; c++) {
        const int buf = c & 1;
        if (c < 15) g_load_stage(sm, buf ^ 1, c + 1, tid, A, Bt);
        if (c < 15) { CP_WAIT1(); } else { CP_WAIT0(); }
        __syncthreads();

        const float* sA = sm + buf * STAGEF;
        const float* sB = sA + MATF;

#pragma unroll
        for (int ks = 0; ks < 2; ks++) {
            const int k0 = ks * 16;
            uint32_t ah[4][4], al[4][4], bh[4][2], bl[4][2];
#pragma unroll
            for (int i = 0; i < 4; i++) {
                int r = wm * 64 + i * 16 + g;
                float2 x0 = *(const float2*)&sA[r * PADK + k0 + 2 * tg];
                float2 x1 = *(const float2*)&sA[(r + 8) * PADK + k0 + 2 * tg];
                float2 x2 = *(const float2*)&sA[r * PADK + k0 + 2 * tg + 8];
                float2 x3 = *(const float2*)&sA[(r + 8) * PADK + k0 + 2 * tg + 8];
                if (full) {
                    splitbf(x0, ah[i][0], al[i][0]);
                    splitbf(x1, ah[i][1], al[i][1]);
                    splitbf(x2, ah[i][2], al[i][2]);
                    splitbf(x3, ah[i][3], al[i][3]);
                } else {
                    ah[i][0] = packbf(x0.x, x0.y);
                    ah[i][1] = packbf(x1.x, x1.y);
                    ah[i][2] = packbf(x2.x, x2.y);
                    ah[i][3] = packbf(x3.x, x3.y);
                }
            }
#pragma unroll
            for (int j = 0; j < 4; j++) {
                int n = wn * 32 + j * 8 + g;
                float2 y0 = *(const float2*)&sB[n * PADK + k0 + 2 * tg];
                float2 y1 = *(const float2*)&sB[n * PADK + k0 + 2 * tg + 8];
                if (full) {
                    splitbf(y0, bh[j][0], bl[j][0]);
                    splitbf(y1, bh[j][1], bl[j][1]);
                } else {
                    bh[j][0] = packbf(y0.x, y0.y);
                    bh[j][1] = packbf(y1.x, y1.y);
                }
            }
#pragma unroll
            for (int i = 0; i < 4; i++)
#pragma unroll
                for (int j = 0; j < 4; j++) MMA_BF16(acc[i][j], ah[i], bh[j]);
            if (full) {
#pragma unroll
                for (int i = 0; i < 4; i++)
#pragma unroll
                    for (int j = 0; j < 4; j++) MMA_BF16(acc[i][j], ah[i], bl[j]);
#pragma unroll
                for (int i = 0; i < 4; i++)
#pragma unroll
                    for (int j = 0; j < 4; j++) MMA_BF16(acc[i][j], al[i], bh[j]);
            }
        }
        __syncthreads();
    }

#pragma unroll
    for (int i = 0; i < 4; i++) {
#pragma unroll
        for (int j = 0; j < 4; j++) {
            int row = row0 + wm * 64 + i * 16 + g;
            int col = col0 + wn * 32 + j * 8 + tg * 2;
            float2 v0 = make_float2(acc[i][j][0], acc[i][j][1]);
            float2 v1 = make_float2(acc[i][j][2], acc[i][j][3]);
            *(float2*)(C + (size_t)row * 512 + col) = v0;
            *(float2*)(C + (size_t)(row + 8) * 512 + col) = v1;
        }
    }
}

// ---------------- QK_samp -> M (batch-sliced) -------------------------------------
__global__ __launch_bounds__(256) void qkm3_kernel(const int* __restrict__ isamp,
                                                   int boff)
{
    int gw   = ((boff + blockIdx.x) * 256 + threadIdx.x) >> 5;
    int lane = threadIdx.x & 31;
    int l = gw & (L_ - 1);
    int b = gw >> 12;

    const float4* qb = (const float4*)(g_Q + ((size_t)(b * L_ + l)) * DM_);
    float4 q0 = qb[lane], q1 = qb[lane + 32], q2 = qb[lane + 64], q3 = qb[lane + 96];

    float smax0 = -CUDART_INF_F, smax1 = -CUDART_INF_F, smax2 = -CUDART_INF_F, smax3 = -CUDART_INF_F;
    float ssum0 = 0.f, ssum1 = 0.f, ssum2 = 0.f, ssum3 = 0.f;
    const int* ip = isamp + l * U_;

#pragma unroll 2
    for (int u = 0; u < U_; u++) {
        int j = __ldg(ip + u);
        const float4* kb = (const float4*)(g_K + ((size_t)(b * L_ + j)) * DM_);
        float4 k0 = kb[lane], k1 = kb[lane + 32], k2 = kb[lane + 64], k3 = kb[lane + 96];
        float s0 = q0.x * k0.x; s0 = fmaf(q0.y, k0.y, s0); s0 = fmaf(q0.z, k0.z, s0); s0 = fmaf(q0.w, k0.w, s0);
        float s1 = q1.x * k1.x; s1 = fmaf(q1.y, k1.y, s1); s1 = fmaf(q1.z, k1.z, s1); s1 = fmaf(q1.w, k1.w, s1);
        float s2 = q2.x * k2.x; s2 = fmaf(q2.y, k2.y, s2); s2 = fmaf(q2.z, k2.z, s2); s2 = fmaf(q2.w, k2.w, s2);
        float s3 = q3.x * k3.x; s3 = fmaf(q3.y, k3.y, s3); s3 = fmaf(q3.z, k3.z, s3); s3 = fmaf(q3.w, k3.w, s3);
#pragma unroll
        for (int m = 1; m <= 8; m <<= 1) {
            s0 += __shfl_xor_sync(0xffffffffu, s0, m);
            s1 += __shfl_xor_sync(0xffffffffu, s1, m);
            s2 += __shfl_xor_sync(0xffffffffu, s2, m);
            s3 += __shfl_xor_sync(0xffffffffu, s3, m);
        }
        smax0 = fmaxf(smax0, s0); ssum0 += s0;
        smax1 = fmaxf(smax1, s1); ssum1 += s1;
        smax2 = fmaxf(smax2, s2); ssum2 += s2;
        smax3 = fmaxf(smax3, s3); ssum3 += s3;
    }
    if ((lane & 15) == 0) {
        int g = lane >> 4;
        size_t base = ((size_t)b * 8) * L_ + l;
        g_M[base + (size_t)(g + 0) * L_] = smax0 - ssum0 * (1.0f / U_);
        g_M[base + (size_t)(g + 2) * L_] = smax1 - ssum1 * (1.0f / U_);
        g_M[base + (size_t)(g + 4) * L_] = smax2 - ssum2 * (1.0f / U_);
        g_M[base + (size_t)(g + 6) * L_] = smax3 - ssum3 * (1.0f / U_);
    }
}

// ---------------- top-k phase A: per-slice local top-41 (bh-sliced) --------------
__global__ __launch_bounds__(256) void topkA_kernel(int bhoff)
{
    int slice = blockIdx.x, bh = bhoff + blockIdx.y;
    __shared__ float sv[512];
    __shared__ float wv[8];
    __shared__ int   wi[8];
    int tid = threadIdx.x, lane = tid & 31, w = tid >> 5;

    sv[tid]       = g_M[bh * L_ + slice * 512 + tid];
    sv[tid + 256] = g_M[bh * L_ + slice * 512 + tid + 256];
    __syncthreads();

    for (int it = 0; it < U_; it++) {
        float v0 = sv[tid], v1 = sv[tid + 256];
        float bv; int bi;
        if (v1 > v0) { bv = v1; bi = tid + 256; } else { bv = v0; bi = tid; }
#pragma unroll
        for (int o = 16; o > 0; o >>= 1) {
            float ov = __shfl_xor_sync(0xffffffffu, bv, o);
            int   oi = __shfl_xor_sync(0xffffffffu, bi, o);
            if (ov > bv || (ov == bv && oi < bi)) { bv = ov; bi = oi; }
        }
        if (lane == 0) { wv[w] = bv; wi[w] = bi; }
        __syncthreads();
        if (tid == 0) {
            float fv = wv[0]; int fi = wi[0];
#pragma unroll
            for (int k = 1; k < 8; k++) {
                if (wv[k] > fv || (wv[k] == fv && wi[k] < fi)) { fv = wv[k]; fi = wi[k]; }
            }
            sv[fi] = -CUDART_INF_F;
            g_cval[(bh * 8 + slice) * U_ + it] = fv;
            g_cidx[(bh * 8 + slice) * U_ + it] = slice * 512 + fi;
        }
        __syncthreads();
    }
}

// ---------------- top-k phase B: merge 8x41 candidates (bh-sliced) ---------------
__global__ __launch_bounds__(256) void topkB_kernel(int bhoff)
{
    int bh = bhoff + blockIdx.x;
    __shared__ float sv[512];
    __shared__ int   si[512];
    __shared__ float wv[8];
    __shared__ int   wi[8];
    int tid = threadIdx.x, lane = tid & 31, w = tid >> 5;

    const int NC = 8 * U_;
#pragma unroll
    for (int r = 0; r < 2; r++) {
        int i = tid + 256 * r;
        if (i < NC) {
            sv[i] = g_cval[bh * NC + i];
            si[i] = g_cidx[bh * NC + i];
        } else if (i < 512) {
            sv[i] = -CUDART_INF_F;
            si[i] = 0x7fffffff;
        }
    }
    __syncthreads();

    for (int it = 0; it < U_; it++) {
        float v0 = sv[tid], v1 = sv[tid + 256];
        int   i0 = si[tid], i1 = si[tid + 256];
        float bv; int bi, bslot;
        if (v1 > v0 || (v1 == v0 && i1 < i0)) { bv = v1; bi = i1; bslot = tid + 256; }
        else                                   { bv = v0; bi = i0; bslot = tid; }
#pragma unroll
        for (int o = 16; o > 0; o >>= 1) {
            float ov = __shfl_xor_sync(0xffffffffu, bv, o);
            int   oi = __shfl_xor_sync(0xffffffffu, bi, o);
            int   os = __shfl_xor_sync(0xffffffffu, bslot, o);
            if (ov > bv || (ov == bv && oi < bi)) { bv = ov; bi = oi; bslot = os; }
        }
        if (lane == 0) { wv[w] = bv; wi[w] = bslot; }
        __syncthreads();
        if (tid == 0) {
            float fv = wv[0]; int fslot = wi[0];
#pragma unroll
            for (int k = 1; k < 8; k++) {
                int s2 = wi[k];
                if (wv[k] > fv || (wv[k] == fv && si[s2] < si[fslot])) { fv = wv[k]; fslot = s2; }
            }
            g_idx[bh * U_ + it] = si[fslot];
            sv[fslot] = -CUDART_INF_F;
            si[fslot] = 0x7fffffff;
        }
        __syncthreads();
    }
}

// ---------------- V mean per (b,h) -----------------------------------------------
__global__ __launch_bounds__(256) void vmean_kernel()
{
    int bh = blockIdx.x;
    int b = bh >> 3, h = bh & 7;
    int tid = threadIdx.x;
    int d = tid & 63, g = tid >> 6;
    float sum = 0.f;
    for (int l = g; l < L_; l += 4)
        sum += g_V[((size_t)(b * L_ + l)) * DM_ + h * DK_ + d];
    __shared__ float red[4][64];
    red[g][d] = sum;
    __syncthreads();
    if (g == 0) {
        float t = red[0][d] + red[1][d] + red[2][d] + red[3][d];
        g_vmean[bh * 64 + d] = t * (1.0f / L_);
    }
}

// ---------------- sparse attention: 16-lane groups (bh-sliced) --------------------
__global__ __launch_bounds__(256) void attn_partial(int bhoff)
{
    int ch = blockIdx.x, bh = bhoff + blockIdx.y;
    int b = bh >> 3, h = bh & 7;
    int tid = threadIdx.x, lane = tid & 31, w = tid >> 5;
    int grp = lane >> 4, l4 = lane & 15;

    __shared__ float qs[U_ * DK_];
    __shared__ float Ks[64 * 68];
    __shared__ float Vs[64 * 68];

    for (int i = tid; i < U_ * DK_; i += 256) {
        int u = i >> 6, d = i & 63;
        int l = g_idx[bh * U_ + u];
        qs[i] = g_Q[((size_t)(b * L_ + l)) * DM_ + h * DK_ + d];
    }
    __syncthreads();

    const int nu = (w == 0) ? 6 : 5;
    float4 q4[6], a4[6];
    float m[6], ss[6];
#pragma unroll
    for (int k = 0; k < 6; k++) {
        if (k < nu) {
            int u = w + 8 * k;
            q4[k] = *(const float4*)&qs[u * 64 + 4 * l4];
        } else {
            q4[k] = make_float4(0.f, 0.f, 0.f, 0.f);
        }
        m[k] = -CUDART_INF_F; ss[k] = 0.f;
        a4[k] = make_float4(0.f, 0.f, 0.f, 0.f);
    }

    const int jbase0 = ch * CHUNK_;
    for (int t = 0; t < CHUNK_ / 64; t++) {
        __syncthreads();
        int jb = jbase0 + t * 64;
        const float4* Kg = (const float4*)(g_K + ((size_t)(b * L_ + jb)) * DM_ + h * DK_);
        const float4* Vg = (const float4*)(g_V + ((size_t)(b * L_ + jb)) * DM_ + h * DK_);
#pragma unroll
        for (int r = 0; r < 4; r++) {
            int idx = tid + 256 * r;
            int row = idx >> 4, cq = idx & 15;
            float4 kv = Kg[(size_t)row * (DM_ / 4) + cq];
            *(float4*)&Ks[row * 68 + cq * 4] = kv;
            float4 vv = Vg[(size_t)row * (DM_ / 4) + cq];
            *(float4*)&Vs[row * 68 + cq * 4] = vv;
        }
        __syncthreads();

#pragma unroll 2
        for (int jj2 = 0; jj2 < 32; jj2++) {
            int jj = jj2 * 2 + grp;
            float4 k4 = *(const float4*)&Ks[jj * 68 + 4 * l4];
            float4 v4 = *(const float4*)&Vs[jj * 68 + 4 * l4];
            float sc[6];
#pragma unroll
            for (int k = 0; k < 6; k++) {
                float s = q4[k].x * k4.x;
                s = fmaf(q4[k].y, k4.y, s);
                s = fmaf(q4[k].z, k4.z, s);
                s = fmaf(q4[k].w, k4.w, s);
                sc[k] = s;
            }
#pragma unroll
            for (int o = 1; o <= 8; o <<= 1) {
#pragma unroll
                for (int k = 0; k < 6; k++)
                    sc[k] += __shfl_xor_sync(0xffffffffu, sc[k], o);
            }
#pragma unroll
            for (int k = 0; k < 6; k++) {
                float s = sc[k] * 0.125f;
                float mn = fmaxf(m[k], s);
                float ea = __expf(s - mn);
                float eb = __expf(m[k] - mn);
                ss[k] = ss[k] * eb + ea;
                a4[k].x = a4[k].x * eb + ea * v4.x;
                a4[k].y = a4[k].y * eb + ea * v4.y;
                a4[k].z = a4[k].z * eb + ea * v4.z;
                a4[k].w = a4[k].w * eb + ea * v4.w;
                m[k] = mn;
            }
        }
    }

    const int c2 = ch * 2 + grp;
#pragma unroll
    for (int k = 0; k < 6; k++) {
        if (k < nu) {
            int u = w + 8 * k;
            size_t base = ((size_t)(bh * NCH2_ + c2) * U_ + u) * PREC_;
            *(float4*)&g_part[base + 4 * l4] = a4[k];
            if (l4 == 0) { g_part[base + 64] = m[k]; g_part[base + 65] = ss[k]; }
        }
    }
}

// ---------------- combine split-L partials (bh-sliced: 32 bh per launch) ----------
__global__ __launch_bounds__(256) void attn_combine(int bhoff)
{
    int gw = (blockIdx.x * blockDim.x + threadIdx.x) >> 5;
    int lane = threadIdx.x & 31;
    if (gw >= 32 * U_) return;
    int bh = bhoff + gw / U_, u = gw % U_;

    float M = -CUDART_INF_F;
#pragma unroll
    for (int ch = 0; ch < NCH2_; ch++)
        M = fmaxf(M, g_part[((size_t)(bh * NCH2_ + ch) * U_ + u) * PREC_ + 64]);
    float S = 0.f, a0 = 0.f, a1 = 0.f;
#pragma unroll
    for (int ch = 0; ch < NCH2_; ch++) {
        size_t base = ((size_t)(bh * NCH2_ + ch) * U_ + u) * PREC_;
        float f = __expf(g_part[base + 64] - M);
        S  += g_part[base + 65] * f;
        a0 += g_part[base + 2 * lane] * f;
        a1 += g_part[base + 2 * lane + 1] * f;
    }
    float inv = 1.0f / S;
    size_t gv = (size_t)(bh * U_ + u) * 64;
    g_vals[gv + 2 * lane]     = a0 * inv;
    g_vals[gv + 2 * lane + 1] = a1 * inv;
}

// ---------------- low-rank output path ---------------------------------------------
__global__ __launch_bounds__(256) void obase_kernel(const float* __restrict__ Wfc)
{
    int b = blockIdx.x, tid = threadIdx.x;
    __shared__ float vm[512];
    vm[tid]       = g_vmean[b * 512 + tid];
    vm[tid + 256] = g_vmean[b * 512 + tid + 256];
    __syncthreads();
    float a0 = 0.f, a1 = 0.f;
    const float2* W2 = (const float2*)Wfc + tid;
#pragma unroll 8
    for (int r = 0; r < 512; r++) {
        float2 w = __ldg(W2 + (size_t)r * 256);
        float v = vm[r];
        a0 = fmaf(v, w.x, a0);
        a1 = fmaf(v, w.y, a1);
    }
    g_obase[b * 512 + 2 * tid]     = a0;
    g_obase[b * 512 + 2 * tid + 1] = a1;
}

__global__ __launch_bounds__(256) void out_assemble(const float* __restrict__ inQ,
                                                    float* __restrict__ out)
{
    int i4 = blockIdx.x * 256 + threadIdx.x;
    int b  = i4 >> 19;
    int c4 = i4 & 127;
    float4 x = ((const float4*)inQ)[i4];
    float4 o = __ldg((const float4*)g_obase + (b << 7) + c4);
    x.x += o.x; x.y += o.y; x.z += o.z; x.w += o.w;
    ((float4*)out)[i4] = x;
}

__global__ __launch_bounds__(128) void correction_kernel(float* __restrict__ out,
                                                         const float* __restrict__ Wfc,
                                                         int guoff)
{
    int gu = guoff + blockIdx.x;
    int bh = gu / U_;
    int b = bh >> 3, h = bh & 7;
    int l = g_idx[gu];
    int tid = threadIdx.x;

    __shared__ float delta[64];
    if (tid < 64)
        delta[tid] = g_vals[(size_t)gu * 64 + tid] - g_vmean[bh * 64 + tid];
    __syncthreads();

    float4 acc = make_float4(0.f, 0.f, 0.f, 0.f);
    const float4* W4 = (const float4*)Wfc + (size_t)(h * 64) * 128 + tid;
#pragma unroll 8
    for (int k = 0; k < 64; k++) {
        float d = delta[k];
        float4 w = __ldg(W4 + (size_t)k * 128);
        acc.x = fmaf(d, w.x, acc.x);
        acc.y = fmaf(d, w.y, acc.y);
        acc.z = fmaf(d, w.z, acc.z);
        acc.w = fmaf(d, w.w, acc.w);
    }
    float* o = out + ((size_t)(b * L_ + l)) * 512 + tid * 4;
    atomicAdd(o + 0, acc.x);
    atomicAdd(o + 1, acc.y);
    atomicAdd(o + 2, acc.z);
    atomicAdd(o + 3, acc.w);
}

// ---------------- LayerNorm (row-sliced) ------------------------------------------
__global__ __launch_bounds__(128) void ln_kernel(float* __restrict__ out,
                                                 const float* __restrict__ gamma,
                                                 const float* __restrict__ beta,
                                                 int rowoff)
{
    int row = rowoff + blockIdx.x, tid = threadIdx.x;
    float4 x = ((const float4*)out)[(size_t)row * 128 + tid];
    float s  = x.x + x.y + x.z + x.w;
    float sq = x.x * x.x + x.y * x.y + x.z * x.z + x.w * x.w;
#pragma unroll
    for (int o = 16; o > 0; o >>= 1) {
        s  += __shfl_xor_sync(0xffffffffu, s, o);
        sq += __shfl_xor_sync(0xffffffffu, sq, o);
    }
    __shared__ float sh[8];
    int w = tid >> 5, lane = tid & 31;
    if (lane == 0) { sh[w] = s; sh[4 + w] = sq; }
    __syncthreads();
    s  = sh[0] + sh[1] + sh[2] + sh[3];
    sq = sh[4] + sh[5] + sh[6] + sh[7];
    float mu  = s * (1.0f / 512.0f);
    float var = sq * (1.0f / 512.0f) - mu * mu;
    float r   = rsqrtf(var + EPS_);
    float4 gg = ((const float4*)gamma)[tid];
    float4 bb = ((const float4*)beta)[tid];
    float4 y;
    y.x = gg.x * (x.x - mu) * r + bb.x;
    y.y = gg.y * (x.y - mu) * r + bb.y;
    y.z = gg.z * (x.z - mu) * r + bb.z;
    y.w = gg.w * (x.w - mu) * r + bb.w;
    ((float4*)out)[(size_t)row * 128 + tid] = y;
}

// ---------------- launch ------------------------------------------------------------
extern "C" void kernel_launch(void* const* d_in, const int* in_sizes, int n_in,
                              void* d_out, int out_size)
{
    const float* inQ   = (const float*)d_in[0];
    const float* inK   = (const float*)d_in[1];
    const float* inV   = (const float*)d_in[2];
    const float* WQ    = (const float*)d_in[3];
    const float* WK    = (const float*)d_in[4];
    const float* WV    = (const float*)d_in[5];
    const float* Wfc   = (const float*)d_in[6];
    const float* gamma = (const float*)d_in[7];
    const float* beta  = (const float*)d_in[8];
    const int*   isamp = (const int*)d_in[9];
    float* out = (float*)d_out;

    static cudaStream_t s2, s3;
    static cudaEvent_t evFork, evV, evOA, evGa, evH1;
    static bool init = false;
    if (!init) {
        cudaStreamCreateWithFlags(&s2, cudaStreamNonBlocking);
        cudaStreamCreateWithFlags(&s3, cudaStreamNonBlocking);
        cudaEventCreateWithFlags(&evFork, cudaEventDisableTiming);
        cudaEventCreateWithFlags(&evV, cudaEventDisableTiming);
        cudaEventCreateWithFlags(&evOA, cudaEventDisableTiming);
        cudaEventCreateWithFlags(&evGa, cudaEventDisableTiming);
        cudaEventCreateWithFlags(&evH1, cudaEventDisableTiming);
        cudaFuncSetAttribute(gemm3_hmma, cudaFuncAttributeMaxDynamicSharedMemorySize,
                             GSMEM_BYTES);
        init = true;
    }

    const int cmbBlocks = (32 * U_ * 32 + 255) / 256;   // combine blocks per half

    // ---- main: weight transpose, then fork ----
    transW_kernel<<<dim3(16, 16, 3), 256>>>(WQ, WK, WV);
    cudaEventRecord(evFork, 0);
    cudaStreamWaitEvent(s2, evFork, 0);

    // ---- s2: V projection branch ----
    gemm3_hmma<<<dim3(4, 256, 1), 256, GSMEM_BYTES, s2>>>(inQ, inK, inV, 2, 0);
    cudaEventRecord(evV, s2);
    vmean_kernel<<<BH_, 256, 0, s2>>>();
    obase_kernel<<<B_, 256, 0, s2>>>(Wfc);
    out_assemble<<<(B_ * L_ * DM_ / 4) / 256, 256, 0, s2>>>(inQ, out);
    cudaEventRecord(evOA, s2);

    // ---- main: Q,K projections batches 0-3 -> fork first-half tail onto s3 ----
    gemm3_hmma<<<dim3(4, 128, 2), 256, GSMEM_BYTES>>>(inQ, inK, inV, 0, 0);
    cudaEventRecord(evGa, 0);
    cudaStreamWaitEvent(s3, evGa, 0);

    // ---- s3: FULL first-half tail (batches 0-3 / bh 0-31 / rows 0-16383) ----
    qkm3_kernel<<<2048, 256, 0, s3>>>(isamp, 0);
    topkA_kernel<<<dim3(8, 32), 256, 0, s3>>>(0);
    topkB_kernel<<<32, 256, 0, s3>>>(0);
    cudaStreamWaitEvent(s3, evV, 0);
    attn_partial<<<dim3(NCH_, 32), 256, 0, s3>>>(0);
    attn_combine<<<cmbBlocks, 256, 0, s3>>>(0);
    cudaStreamWaitEvent(s3, evOA, 0);
    correction_kernel<<<32 * U_, 128, 0, s3>>>(out, Wfc, 0);
    ln_kernel<<<16384, 128, 0, s3>>>(out, gamma, beta, 0);
    cudaEventRecord(evH1, s3);

    // ---- main: second half (batches 4-7 / bh 32-63 / rows 16384-32767) ----
    gemm3_hmma<<<dim3(4, 128, 2), 256, GSMEM_BYTES>>>(inQ, inK, inV, 0, 16384);
    qkm3_kernel<<<2048, 256>>>(isamp, 2048);
    topkA_kernel<<<dim3(8, 32), 256>>>(32);
    topkB_kernel<<<32, 256>>>(32);
    cudaStreamWaitEvent(0, evV, 0);
    attn_partial<<<dim3(NCH_, 32), 256>>>(32);
    attn_combine<<<cmbBlocks, 256>>>(32);
    cudaStreamWaitEvent(0, evOA, 0);
    correction_kernel<<<32 * U_, 128>>>(out, Wfc, 32 * U_);
    ln_kernel<<<16384, 128>>>(out, gamma, beta, 16384);

    // ---- join first-half tail ----
    cudaStreamWaitEvent(0, evH1, 0);
}

// round 14
// speedup vs baseline: 2.5725x; 1.0090x over previous
#include <cuda_runtime.h>
#include <math_constants.h>
#include <cstdint>

#define B_    8
#define L_    4096
#define DM_   512
#define H_    8
#define DK_   64
#define DV_   64
#define U_    41
#define BH_   (B_*H_)
#define NCH_  8
#define NCH2_ 16
#define CHUNK_ (L_/NCH_)
#define PREC_ 68
#define EPS_  1e-5f

// ---------------- scratch ----------------------------------------------------
__device__ float g_Q[B_*L_*DM_];
__device__ float g_K[B_*L_*DM_];
__device__ float g_V[B_*L_*DM_];
__device__ float g_Wt[3*DM_*DM_];
__device__ float g_M[BH_*L_];
__device__ int   g_idx[BH_*U_];
__device__ float g_cval[BH_*8*U_];
__device__ int   g_cidx[BH_*8*U_];
__device__ float g_vals[BH_*U_*DV_];
__device__ float g_vmean[BH_*DV_];
__device__ float g_obase4[4][B_*DM_];     // per-K-chunk partials (no atomics)
__device__ __align__(16) float g_part[BH_*NCH2_*U_*PREC_];

// ---------------- helpers ------------------------------------------------------
__device__ __forceinline__ uint32_t smem_u32(const void* p) {
    uint32_t a;
    asm("{ .reg .u64 t; cvta.to.shared.u64 t, %1; cvt.u32.u64 %0, t; }" : "=r"(a) : "l"(p));
    return a;
}
#define CP_ASYNC_CG(dst, src) \
    asm volatile("cp.async.cg.shared.global [%0], [%1], 16;" :: "r"(dst), "l"(src) : "memory")
#define CP_COMMIT() asm volatile("cp.async.commit_group;" ::: "memory")
#define CP_WAIT1()  asm volatile("cp.async.wait_group 1;" ::: "memory")
#define CP_WAIT0()  asm volatile("cp.async.wait_group 0;" ::: "memory")

__device__ __forceinline__ uint32_t packbf(float e0, float e1) {
    uint32_t r;
    asm("cvt.rn.bf16x2.f32 %0, %1, %2;" : "=r"(r) : "f"(e1), "f"(e0));
    return r;
}
__device__ __forceinline__ void splitbf(float2 x, uint32_t& h, uint32_t& l) {
    h = packbf(x.x, x.y);
    float r0 = x.x - __uint_as_float(h << 16);
    float r1 = x.y - __uint_as_float(h & 0xffff0000u);
    l = packbf(r0, r1);
}

#define MMA_BF16(c, a, b) \
    asm volatile("mma.sync.aligned.m16n8k16.row.col.f32.bf16.bf16.f32 " \
        "{%0,%1,%2,%3}, {%4,%5,%6,%7}, {%8,%9}, {%0,%1,%2,%3};" \
        : "+f"((c)[0]), "+f"((c)[1]), "+f"((c)[2]), "+f"((c)[3]) \
        : "r"((a)[0]), "r"((a)[1]), "r"((a)[2]), "r"((a)[3]), \
          "r"((b)[0]), "r"((b)[1]))

// ---------------- W transpose (fp32 only), all 3 weights ------------------------
__global__ __launch_bounds__(256) void transW_kernel(
    const float* __restrict__ W0, const float* __restrict__ W1,
    const float* __restrict__ W2)
{
    __shared__ float tile[32][33];
    const float* W = (blockIdx.z == 0) ? W0 : (blockIdx.z == 1) ? W1 : W2;
    float* dst = g_Wt + (size_t)blockIdx.z * DM_ * DM_;
    int bx = blockIdx.x * 32;
    int by = blockIdx.y * 32;
    int tx = threadIdx.x & 31, ty = threadIdx.x >> 5;
#pragma unroll
    for (int i = 0; i < 4; i++)
        tile[ty + 8 * i][tx] = __ldg(&W[(size_t)(by + ty + 8 * i) * 512 + bx + tx]);
    __syncthreads();
#pragma unroll
    for (int i = 0; i < 4; i++)
        dst[(size_t)(bx + ty + 8 * i) * 512 + by + tx] = tile[tx][ty + 8 * i];
}

// ---------------- HMMA bf16 GEMM, fused in-register hi/lo split ------------------
#define PADK 40
#define MATF (128 * PADK)
#define STAGEF (2 * MATF)
#define GSMEM_BYTES (2 * STAGEF * 4)

__device__ __forceinline__ void g_load_stage(
    float* sm, int stage, int c, int tid,
    const float* __restrict__ A, const float* __restrict__ Bt)
{
    float* dst = sm + stage * STAGEF;
#pragma unroll
    for (int i = 0; i < 4; i++) {
        int idx = i * 256 + tid;
        int row = idx >> 3, q = idx & 7;
        CP_ASYNC_CG(smem_u32(dst + row * PADK + q * 4),
                    A + (size_t)row * 512 + c * 32 + q * 4);
    }
#pragma unroll
    for (int i = 0; i < 4; i++) {
        int idx = i * 256 + tid;
        int row = idx >> 3, q = idx & 7;
        CP_ASYNC_CG(smem_u32(dst + MATF + row * PADK + q * 4),
                    Bt + (size_t)row * 512 + c * 32 + q * 4);
    }
    CP_COMMIT();
}

__global__ __launch_bounds__(256, 1) void gemm3_hmma(
    const float* __restrict__ inQ, const float* __restrict__ inK,
    const float* __restrict__ inV, int base, int rowbase)
{
    extern __shared__ float sm[];
    const int tid = threadIdx.x;
    const int wid = tid >> 5, lane = tid & 31;
    const int g = lane >> 2, tg = lane & 3;
    const int wm = wid & 1, wn = wid >> 1;
    const int row0 = rowbase + blockIdx.y * 128, col0 = blockIdx.x * 128;
    const int which = base + blockIdx.z;
    const bool full = (which != 2);

    const float* Asrc = (which == 0) ? inQ : (which == 1) ? inK : inV;
    const float* A  = Asrc + (size_t)row0 * 512;
    const float* Bt = g_Wt + (size_t)which * DM_ * DM_ + (size_t)col0 * 512;
    float* C = (which == 0) ? g_Q : (which == 1) ? g_K : g_V;

    float acc[4][4][4];
#pragma unroll
    for (int i = 0; i < 4; i++)
#pragma unroll
        for (int j = 0; j < 4; j++)
#pragma unroll
            for (int r = 0; r < 4; r++) acc[i][j][r] = 0.f;

    g_load_stage(sm, 0, 0, tid, A, Bt);

    for (int c = 0; c < 16; c++) {
        const int buf = c & 1;
        if (c < 15) g_load_stage(sm, buf ^ 1, c + 1, tid, A, Bt);
        if (c < 15) { CP_WAIT1(); } else { CP_WAIT0(); }
        __syncthreads();

        const float* sA = sm + buf * STAGEF;
        const float* sB = sA + MATF;

#pragma unroll
        for (int ks = 0; ks < 2; ks++) {
            const int k0 = ks * 16;
            uint32_t ah[4][4], al[4][4], bh[4][2], bl[4][2];
#pragma unroll
            for (int i = 0; i < 4; i++) {
                int r = wm * 64 + i * 16 + g;
                float2 x0 = *(const float2*)&sA[r * PADK + k0 + 2 * tg];
                float2 x1 = *(const float2*)&sA[(r + 8) * PADK + k0 + 2 * tg];
                float2 x2 = *(const float2*)&sA[r * PADK + k0 + 2 * tg + 8];
                float2 x3 = *(const float2*)&sA[(r + 8) * PADK + k0 + 2 * tg + 8];
                if (full) {
                    splitbf(x0, ah[i][0], al[i][0]);
                    splitbf(x1, ah[i][1], al[i][1]);
                    splitbf(x2, ah[i][2], al[i][2]);
                    splitbf(x3, ah[i][3], al[i][3]);
                } else {
                    ah[i][0] = packbf(x0.x, x0.y);
                    ah[i][1] = packbf(x1.x, x1.y);
                    ah[i][2] = packbf(x2.x, x2.y);
                    ah[i][3] = packbf(x3.x, x3.y);
                }
            }
#pragma unroll
            for (int j = 0; j < 4; j++) {
                int n = wn * 32 + j * 8 + g;
                float2 y0 = *(const float2*)&sB[n * PADK + k0 + 2 * tg];
                float2 y1 = *(const float2*)&sB[n * PADK + k0 + 2 * tg + 8];
                if (full) {
                    splitbf(y0, bh[j][0], bl[j][0]);
                    splitbf(y1, bh[j][1], bl[j][1]);
                } else {
                    bh[j][0] = packbf(y0.x, y0.y);
                    bh[j][1] = packbf(y1.x, y1.y);
                }
            }
#pragma unroll
            for (int i = 0; i < 4; i++)
#pragma unroll
                for (int j = 0; j < 4; j++) MMA_BF16(acc[i][j], ah[i], bh[j]);
            if (full) {
#pragma unroll
                for (int i = 0; i < 4; i++)
#pragma unroll
                    for (int j = 0; j < 4; j++) MMA_BF16(acc[i][j], ah[i], bl[j]);
#pragma unroll
                for (int i = 0; i < 4; i++)
#pragma unroll
                    for (int j = 0; j < 4; j++) MMA_BF16(acc[i][j], al[i], bh[j]);
            }
        }
        __syncthreads();
    }

#pragma unroll
    for (int i = 0; i < 4; i++) {
#pragma unroll
        for (int j = 0; j < 4; j++) {
            int row = row0 + wm * 64 + i * 16 + g;
            int col = col0 + wn * 32 + j * 8 + tg * 2;
            float2 v0 = make_float2(acc[i][j][0], acc[i][j][1]);
            float2 v1 = make_float2(acc[i][j][2], acc[i][j][3]);
            *(float2*)(C + (size_t)row * 512 + col) = v0;
            *(float2*)(C + (size_t)(row + 8) * 512 + col) = v1;
        }
    }
}

// ---------------- QK_samp -> M (batch-sliced) -------------------------------------
__global__ __launch_bounds__(256) void qkm3_kernel(const int* __restrict__ isamp,
                                                   int boff)
{
    int gw   = ((boff + blockIdx.x) * 256 + threadIdx.x) >> 5;
    int lane = threadIdx.x & 31;
    int l = gw & (L_ - 1);
    int b = gw >> 12;

    const float4* qb = (const float4*)(g_Q + ((size_t)(b * L_ + l)) * DM_);
    float4 q0 = qb[lane], q1 = qb[lane + 32], q2 = qb[lane + 64], q3 = qb[lane + 96];

    float smax0 = -CUDART_INF_F, smax1 = -CUDART_INF_F, smax2 = -CUDART_INF_F, smax3 = -CUDART_INF_F;
    float ssum0 = 0.f, ssum1 = 0.f, ssum2 = 0.f, ssum3 = 0.f;
    const int* ip = isamp + l * U_;

#pragma unroll 2
    for (int u = 0; u < U_; u++) {
        int j = __ldg(ip + u);
        const float4* kb = (const float4*)(g_K + ((size_t)(b * L_ + j)) * DM_);
        float4 k0 = kb[lane], k1 = kb[lane + 32], k2 = kb[lane + 64], k3 = kb[lane + 96];
        float s0 = q0.x * k0.x; s0 = fmaf(q0.y, k0.y, s0); s0 = fmaf(q0.z, k0.z, s0); s0 = fmaf(q0.w, k0.w, s0);
        float s1 = q1.x * k1.x; s1 = fmaf(q1.y, k1.y, s1); s1 = fmaf(q1.z, k1.z, s1); s1 = fmaf(q1.w, k1.w, s1);
        float s2 = q2.x * k2.x; s2 = fmaf(q2.y, k2.y, s2); s2 = fmaf(q2.z, k2.z, s2); s2 = fmaf(q2.w, k2.w, s2);
        float s3 = q3.x * k3.x; s3 = fmaf(q3.y, k3.y, s3); s3 = fmaf(q3.z, k3.z, s3); s3 = fmaf(q3.w, k3.w, s3);
#pragma unroll
        for (int m = 1; m <= 8; m <<= 1) {
            s0 += __shfl_xor_sync(0xffffffffu, s0, m);
            s1 += __shfl_xor_sync(0xffffffffu, s1, m);
            s2 += __shfl_xor_sync(0xffffffffu, s2, m);
            s3 += __shfl_xor_sync(0xffffffffu, s3, m);
        }
        smax0 = fmaxf(smax0, s0); ssum0 += s0;
        smax1 = fmaxf(smax1, s1); ssum1 += s1;
        smax2 = fmaxf(smax2, s2); ssum2 += s2;
        smax3 = fmaxf(smax3, s3); ssum3 += s3;
    }
    if ((lane & 15) == 0) {
        int g = lane >> 4;
        size_t base = ((size_t)b * 8) * L_ + l;
        g_M[base + (size_t)(g + 0) * L_] = smax0 - ssum0 * (1.0f / U_);
        g_M[base + (size_t)(g + 2) * L_] = smax1 - ssum1 * (1.0f / U_);
        g_M[base + (size_t)(g + 4) * L_] = smax2 - ssum2 * (1.0f / U_);
        g_M[base + (size_t)(g + 6) * L_] = smax3 - ssum3 * (1.0f / U_);
    }
}

// ---------------- top-k phase A (bh-sliced) ---------------------------------------
__global__ __launch_bounds__(256) void topkA_kernel(int bhoff)
{
    int slice = blockIdx.x, bh = bhoff + blockIdx.y;
    __shared__ float sv[512];
    __shared__ float wv[8];
    __shared__ int   wi[8];
    int tid = threadIdx.x, lane = tid & 31, w = tid >> 5;

    sv[tid]       = g_M[bh * L_ + slice * 512 + tid];
    sv[tid + 256] = g_M[bh * L_ + slice * 512 + tid + 256];
    __syncthreads();

    for (int it = 0; it < U_; it++) {
        float v0 = sv[tid], v1 = sv[tid + 256];
        float bv; int bi;
        if (v1 > v0) { bv = v1; bi = tid + 256; } else { bv = v0; bi = tid; }
#pragma unroll
        for (int o = 16; o > 0; o >>= 1) {
            float ov = __shfl_xor_sync(0xffffffffu, bv, o);
            int   oi = __shfl_xor_sync(0xffffffffu, bi, o);
            if (ov > bv || (ov == bv && oi < bi)) { bv = ov; bi = oi; }
        }
        if (lane == 0) { wv[w] = bv; wi[w] = bi; }
        __syncthreads();
        if (tid == 0) {
            float fv = wv[0]; int fi = wi[0];
#pragma unroll
            for (int k = 1; k < 8; k++) {
                if (wv[k] > fv || (wv[k] == fv && wi[k] < fi)) { fv = wv[k]; fi = wi[k]; }
            }
            sv[fi] = -CUDART_INF_F;
            g_cval[(bh * 8 + slice) * U_ + it] = fv;
            g_cidx[(bh * 8 + slice) * U_ + it] = slice * 512 + fi;
        }
        __syncthreads();
    }
}

// ---------------- top-k phase B (bh-sliced) ---------------------------------------
__global__ __launch_bounds__(256) void topkB_kernel(int bhoff)
{
    int bh = bhoff + blockIdx.x;
    __shared__ float sv[512];
    __shared__ int   si[512];
    __shared__ float wv[8];
    __shared__ int   wi[8];
    int tid = threadIdx.x, lane = tid & 31, w = tid >> 5;

    const int NC = 8 * U_;
#pragma unroll
    for (int r = 0; r < 2; r++) {
        int i = tid + 256 * r;
        if (i < NC) {
            sv[i] = g_cval[bh * NC + i];
            si[i] = g_cidx[bh * NC + i];
        } else if (i < 512) {
            sv[i] = -CUDART_INF_F;
            si[i] = 0x7fffffff;
        }
    }
    __syncthreads();

    for (int it = 0; it < U_; it++) {
        float v0 = sv[tid], v1 = sv[tid + 256];
        int   i0 = si[tid], i1 = si[tid + 256];
        float bv; int bi, bslot;
        if (v1 > v0 || (v1 == v0 && i1 < i0)) { bv = v1; bi = i1; bslot = tid + 256; }
        else                                   { bv = v0; bi = i0; bslot = tid; }
#pragma unroll
        for (int o = 16; o > 0; o >>= 1) {
            float ov = __shfl_xor_sync(0xffffffffu, bv, o);
            int   oi = __shfl_xor_sync(0xffffffffu, bi, o);
            int   os = __shfl_xor_sync(0xffffffffu, bslot, o);
            if (ov > bv || (ov == bv && oi < bi)) { bv = ov; bi = oi; bslot = os; }
        }
        if (lane == 0) { wv[w] = bv; wi[w] = bslot; }
        __syncthreads();
        if (tid == 0) {
            float fv = wv[0]; int fslot = wi[0];
#pragma unroll
            for (int k = 1; k < 8; k++) {
                int s2 = wi[k];
                if (wv[k] > fv || (wv[k] == fv && si[s2] < si[fslot])) { fv = wv[k]; fslot = s2; }
            }
            g_idx[bh * U_ + it] = si[fslot];
            sv[fslot] = -CUDART_INF_F;
            si[fslot] = 0x7fffffff;
        }
        __syncthreads();
    }
}

// ---------------- V mean per (b,h): 1024 threads, 16-way L-split ------------------
__global__ __launch_bounds__(1024) void vmean_kernel(int bhoff)
{
    int bh = bhoff + blockIdx.x;
    int b = bh >> 3, h = bh & 7;
    int tid = threadIdx.x;
    int d = tid & 63, g = tid >> 6;
    float sum = 0.f;
#pragma unroll 4
    for (int l = g; l < L_; l += 16)
        sum += g_V[((size_t)(b * L_ + l)) * DM_ + h * DK_ + d];
    __shared__ float red[16][64];
    red[g][d] = sum;
    __syncthreads();
    if (g == 0) {
        float t = 0.f;
#pragma unroll
        for (int k = 0; k < 16; k++) t += red[k][d];
        g_vmean[bh * 64 + d] = t * (1.0f / L_);
    }
}

// ---------------- obase partials: per-kc buffers, plain stores (replay-safe) ------
__global__ __launch_bounds__(256) void obase_part(const float* __restrict__ Wfc,
                                                  int boff)
{
    int b = boff + blockIdx.x;
    int kc = blockIdx.y;
    int tid = threadIdx.x;
    __shared__ float vm[128];
    if (tid < 128) vm[tid] = g_vmean[b * 512 + kc * 128 + tid];
    __syncthreads();
    float a0 = 0.f, a1 = 0.f;
    const float2* W2 = (const float2*)Wfc + tid + (size_t)(kc * 128) * 256;
#pragma unroll 8
    for (int r = 0; r < 128; r++) {
        float2 w = __ldg(W2 + (size_t)r * 256);
        float v = vm[r];
        a0 = fmaf(v, w.x, a0);
        a1 = fmaf(v, w.y, a1);
    }
    g_obase4[kc][b * 512 + 2 * tid]     = a0;
    g_obase4[kc][b * 512 + 2 * tid + 1] = a1;
}

__global__ __launch_bounds__(256) void out_assemble(const float* __restrict__ inQ,
                                                    float* __restrict__ out,
                                                    int i4off)
{
    int i4 = i4off + blockIdx.x * 256 + threadIdx.x;
    int b  = i4 >> 19;
    int c4 = i4 & 127;
    float4 x = ((const float4*)inQ)[i4];
#pragma unroll
    for (int kc = 0; kc < 4; kc++) {
        float4 o = __ldg((const float4*)g_obase4[kc] + (b << 7) + c4);
        x.x += o.x; x.y += o.y; x.z += o.z; x.w += o.w;
    }
    ((float4*)out)[i4] = x;
}

// ---------------- sparse attention: 16-lane groups (bh-sliced) --------------------
__global__ __launch_bounds__(256) void attn_partial(int bhoff)
{
    int ch = blockIdx.x, bh = bhoff + blockIdx.y;
    int b = bh >> 3, h = bh & 7;
    int tid = threadIdx.x, lane = tid & 31, w = tid >> 5;
    int grp = lane >> 4, l4 = lane & 15;

    __shared__ float qs[U_ * DK_];
    __shared__ float Ks[64 * 68];
    __shared__ float Vs[64 * 68];

    for (int i = tid; i < U_ * DK_; i += 256) {
        int u = i >> 6, d = i & 63;
        int l = g_idx[bh * U_ + u];
        qs[i] = g_Q[((size_t)(b * L_ + l)) * DM_ + h * DK_ + d];
    }
    __syncthreads();

    const int nu = (w == 0) ? 6 : 5;
    float4 q4[6], a4[6];
    float m[6], ss[6];
#pragma unroll
    for (int k = 0; k < 6; k++) {
        if (k < nu) {
            int u = w + 8 * k;
            q4[k] = *(const float4*)&qs[u * 64 + 4 * l4];
        } else {
            q4[k] = make_float4(0.f, 0.f, 0.f, 0.f);
        }
        m[k] = -CUDART_INF_F; ss[k] = 0.f;
        a4[k] = make_float4(0.f, 0.f, 0.f, 0.f);
    }

    const int jbase0 = ch * CHUNK_;
    for (int t = 0; t < CHUNK_ / 64; t++) {
        __syncthreads();
        int jb = jbase0 + t * 64;
        const float4* Kg = (const float4*)(g_K + ((size_t)(b * L_ + jb)) * DM_ + h * DK_);
        const float4* Vg = (const float4*)(g_V + ((size_t)(b * L_ + jb)) * DM_ + h * DK_);
#pragma unroll
        for (int r = 0; r < 4; r++) {
            int idx = tid + 256 * r;
            int row = idx >> 4, cq = idx & 15;
            float4 kv = Kg[(size_t)row * (DM_ / 4) + cq];
            *(float4*)&Ks[row * 68 + cq * 4] = kv;
            float4 vv = Vg[(size_t)row * (DM_ / 4) + cq];
            *(float4*)&Vs[row * 68 + cq * 4] = vv;
        }
        __syncthreads();

#pragma unroll 2
        for (int jj2 = 0; jj2 < 32; jj2++) {
            int jj = jj2 * 2 + grp;
            float4 k4 = *(const float4*)&Ks[jj * 68 + 4 * l4];
            float4 v4 = *(const float4*)&Vs[jj * 68 + 4 * l4];
            float sc[6];
#pragma unroll
            for (int k = 0; k < 6; k++) {
                float s = q4[k].x * k4.x;
                s = fmaf(q4[k].y, k4.y, s);
                s = fmaf(q4[k].z, k4.z, s);
                s = fmaf(q4[k].w, k4.w, s);
                sc[k] = s;
            }
#pragma unroll
            for (int o = 1; o <= 8; o <<= 1) {
#pragma unroll
                for (int k = 0; k < 6; k++)
                    sc[k] += __shfl_xor_sync(0xffffffffu, sc[k], o);
            }
#pragma unroll
            for (int k = 0; k < 6; k++) {
                float s = sc[k] * 0.125f;
                float mn = fmaxf(m[k], s);
                float ea = __expf(s - mn);
                float eb = __expf(m[k] - mn);
                ss[k] = ss[k] * eb + ea;
                a4[k].x = a4[k].x * eb + ea * v4.x;
                a4[k].y = a4[k].y * eb + ea * v4.y;
                a4[k].z = a4[k].z * eb + ea * v4.z;
                a4[k].w = a4[k].w * eb + ea * v4.w;
                m[k] = mn;
            }
        }
    }

    const int c2 = ch * 2 + grp;
#pragma unroll
    for (int k = 0; k < 6; k++) {
        if (k < nu) {
            int u = w + 8 * k;
            size_t base = ((size_t)(bh * NCH2_ + c2) * U_ + u) * PREC_;
            *(float4*)&g_part[base + 4 * l4] = a4[k];
            if (l4 == 0) { g_part[base + 64] = m[k]; g_part[base + 65] = ss[k]; }
        }
    }
}

// ---------------- combine split-L partials (bh-sliced) ----------------------------
__global__ __launch_bounds__(256) void attn_combine(int bhoff)
{
    int gw = (blockIdx.x * blockDim.x + threadIdx.x) >> 5;
    int lane = threadIdx.x & 31;
    if (gw >= 32 * U_) return;
    int bh = bhoff + gw / U_, u = gw % U_;

    float M = -CUDART_INF_F;
#pragma unroll
    for (int ch = 0; ch < NCH2_; ch++)
        M = fmaxf(M, g_part[((size_t)(bh * NCH2_ + ch) * U_ + u) * PREC_ + 64]);
    float S = 0.f, a0 = 0.f, a1 = 0.f;
#pragma unroll
    for (int ch = 0; ch < NCH2_; ch++) {
        size_t base = ((size_t)(bh * NCH2_ + ch) * U_ + u) * PREC_;
        float f = __expf(g_part[base + 64] - M);
        S  += g_part[base + 65] * f;
        a0 += g_part[base + 2 * lane] * f;
        a1 += g_part[base + 2 * lane + 1] * f;
    }
    float inv = 1.0f / S;
    size_t gv = (size_t)(bh * U_ + u) * 64;
    g_vals[gv + 2 * lane]     = a0 * inv;
    g_vals[gv + 2 * lane + 1] = a1 * inv;
}

__global__ __launch_bounds__(128) void correction_kernel(float* __restrict__ out,
                                                         const float* __restrict__ Wfc,
                                                         int guoff)
{
    int gu = guoff + blockIdx.x;
    int bh = gu / U_;
    int b = bh >> 3, h = bh & 7;
    int l = g_idx[gu];
    int tid = threadIdx.x;

    __shared__ float delta[64];
    if (tid < 64)
        delta[tid] = g_vals[(size_t)gu * 64 + tid] - g_vmean[bh * 64 + tid];
    __syncthreads();

    float4 acc = make_float4(0.f, 0.f, 0.f, 0.f);
    const float4* W4 = (const float4*)Wfc + (size_t)(h * 64) * 128 + tid;
#pragma unroll 8
    for (int k = 0; k < 64; k++) {
        float d = delta[k];
        float4 w = __ldg(W4 + (size_t)k * 128);
        acc.x = fmaf(d, w.x, acc.x);
        acc.y = fmaf(d, w.y, acc.y);
        acc.z = fmaf(d, w.z, acc.z);
        acc.w = fmaf(d, w.w, acc.w);
    }
    float* o = out + ((size_t)(b * L_ + l)) * 512 + tid * 4;
    atomicAdd(o + 0, acc.x);
    atomicAdd(o + 1, acc.y);
    atomicAdd(o + 2, acc.z);
    atomicAdd(o + 3, acc.w);
}

// ---------------- LayerNorm (row-sliced) ------------------------------------------
__global__ __launch_bounds__(128) void ln_kernel(float* __restrict__ out,
                                                 const float* __restrict__ gamma,
                                                 const float* __restrict__ beta,
                                                 int rowoff)
{
    int row = rowoff + blockIdx.x, tid = threadIdx.x;
    float4 x = ((const float4*)out)[(size_t)row * 128 + tid];
    float s  = x.x + x.y + x.z + x.w;
    float sq = x.x * x.x + x.y * x.y + x.z * x.z + x.w * x.w;
#pragma unroll
    for (int o = 16; o > 0; o >>= 1) {
        s  += __shfl_xor_sync(0xffffffffu, s, o);
        sq += __shfl_xor_sync(0xffffffffu, sq, o);
    }
    __shared__ float sh[8];
    int w = tid >> 5, lane = tid & 31;
    if (lane == 0) { sh[w] = s; sh[4 + w] = sq; }
    __syncthreads();
    s  = sh[0] + sh[1] + sh[2] + sh[3];
    sq = sh[4] + sh[5] + sh[6] + sh[7];
    float mu  = s * (1.0f / 512.0f);
    float var = sq * (1.0f / 512.0f) - mu * mu;
    float r   = rsqrtf(var + EPS_);
    float4 gg = ((const float4*)gamma)[tid];
    float4 bb = ((const float4*)beta)[tid];
    float4 y;
    y.x = gg.x * (x.x - mu) * r + bb.x;
    y.y = gg.y * (x.y - mu) * r + bb.y;
    y.z = gg.z * (x.z - mu) * r + bb.z;
    y.w = gg.w * (x.w - mu) * r + bb.w;
    ((float4*)out)[(size_t)row * 128 + tid] = y;
}

// ---------------- launch ------------------------------------------------------------
// Capture rules: records precede waits; every side-stream node is reachable
// from the capture-origin stream (no eager stragglers).
extern "C" void kernel_launch(void* const* d_in, const int* in_sizes, int n_in,
                              void* d_out, int out_size)
{
    const float* inQ   = (const float*)d_in[0];
    const float* inK   = (const float*)d_in[1];
    const float* inV   = (const float*)d_in[2];
    const float* WQ    = (const float*)d_in[3];
    const float* WK    = (const float*)d_in[4];
    const float* WV    = (const float*)d_in[5];
    const float* Wfc   = (const float*)d_in[6];
    const float* gamma = (const float*)d_in[7];
    const float* beta  = (const float*)d_in[8];
    const int*   isamp = (const int*)d_in[9];
    float* out = (float*)d_out;

    static cudaStream_t s2, s3, s4;
    static cudaEvent_t evGa, evVa, evGb, evVb, evQb, evOAa, evOAb, evH1;
    static bool init = false;
    if (!init) {
        cudaStreamCreateWithFlags(&s2, cudaStreamNonBlocking);
        cudaStreamCreateWithFlags(&s3, cudaStreamNonBlocking);
        cudaStreamCreateWithFlags(&s4, cudaStreamNonBlocking);
        cudaEventCreateWithFlags(&evGa, cudaEventDisableTiming);
        cudaEventCreateWithFlags(&evVa, cudaEventDisableTiming);
        cudaEventCreateWithFlags(&evGb, cudaEventDisableTiming);
        cudaEventCreateWithFlags(&evVb, cudaEventDisableTiming);
        cudaEventCreateWithFlags(&evQb, cudaEventDisableTiming);
        cudaEventCreateWithFlags(&evOAa, cudaEventDisableTiming);
        cudaEventCreateWithFlags(&evOAb, cudaEventDisableTiming);
        cudaEventCreateWithFlags(&evH1, cudaEventDisableTiming);
        cudaFuncSetAttribute(gemm3_hmma, cudaFuncAttributeMaxDynamicSharedMemorySize,
                             GSMEM_BYTES);
        init = true;
    }

    const int cmbBlocks = (32 * U_ * 32 + 255) / 256;

    // ---- main: ALL tensor work back-to-back (records first) ----
    transW_kernel<<<dim3(16, 16, 3), 256>>>(WQ, WK, WV);
    gemm3_hmma<<<dim3(4, 128, 2), 256, GSMEM_BYTES>>>(inQ, inK, inV, 0, 0);       // QK b0-3
    cudaEventRecord(evGa, 0);
    gemm3_hmma<<<dim3(4, 128, 1), 256, GSMEM_BYTES>>>(inQ, inK, inV, 2, 0);       // V  b0-3
    cudaEventRecord(evVa, 0);
    gemm3_hmma<<<dim3(4, 128, 2), 256, GSMEM_BYTES>>>(inQ, inK, inV, 0, 16384);   // QK b4-7
    cudaEventRecord(evGb, 0);
    gemm3_hmma<<<dim3(4, 128, 1), 256, GSMEM_BYTES>>>(inQ, inK, inV, 2, 16384);   // V  b4-7
    cudaEventRecord(evVb, 0);

    // ---- s2: V-branch halves ----
    cudaStreamWaitEvent(s2, evVa, 0);
    vmean_kernel<<<32, 1024, 0, s2>>>(0);
    obase_part<<<dim3(4, 4), 256, 0, s2>>>(Wfc, 0);
    out_assemble<<<8192, 256, 0, s2>>>(inQ, out, 0);
    cudaEventRecord(evOAa, s2);
    cudaStreamWaitEvent(s2, evVb, 0);
    vmean_kernel<<<32, 1024, 0, s2>>>(32);
    obase_part<<<dim3(4, 4), 256, 0, s2>>>(Wfc, 4);
    out_assemble<<<8192, 256, 0, s2>>>(inQ, out, 8192 * 256);
    cudaEventRecord(evOAb, s2);

    // ---- s4: qkm second half (overlaps gemmV b4-7 on main) ----
    cudaStreamWaitEvent(s4, evGb, 0);
    qkm3_kernel<<<2048, 256, 0, s4>>>(isamp, 2048);
    cudaEventRecord(evQb, s4);

    // ---- s3: first-half tail (bh 0-31, rows 0-16383) ----
    cudaStreamWaitEvent(s3, evGa, 0);
    qkm3_kernel<<<2048, 256, 0, s3>>>(isamp, 0);
    topkA_kernel<<<dim3(8, 32), 256, 0, s3>>>(0);
    topkB_kernel<<<32, 256, 0, s3>>>(0);
    cudaStreamWaitEvent(s3, evVa, 0);
    attn_partial<<<dim3(NCH_, 32), 256, 0, s3>>>(0);
    attn_combine<<<cmbBlocks, 256, 0, s3>>>(0);
    cudaStreamWaitEvent(s3, evOAa, 0);
    correction_kernel<<<32 * U_, 128, 0, s3>>>(out, Wfc, 0);
    ln_kernel<<<16384, 128, 0, s3>>>(out, gamma, beta, 0);
    cudaEventRecord(evH1, s3);

    // ---- main: second-half tail (bh 32-63, rows 16384-32767) ----
    cudaStreamWaitEvent(0, evQb, 0);
    topkA_kernel<<<dim3(8, 32), 256>>>(32);
    topkB_kernel<<<32, 256>>>(32);
    attn_partial<<<dim3(NCH_, 32), 256>>>(32);
    attn_combine<<<cmbBlocks, 256>>>(32);
    cudaStreamWaitEvent(0, evOAb, 0);
    correction_kernel<<<32 * U_, 128>>>(out, Wfc, 32 * U_);
    ln_kernel<<<16384, 128>>>(out, gamma, beta, 16384);

    // ---- join ----
    cudaStreamWaitEvent(0, evH1, 0);
}